// round 1
// baseline (speedup 1.0000x reference)
#include <cuda_runtime.h>

// ---------------- constants ----------------
// B=8, C=64, T=128
#define HW_   16384      // 128*128
#define CHW_  1048576    // 64*128*128  (x batch stride, floats)
#define GBS_  3145728    // 192*16384   (gate/t batch stride, floats)

// ---------------- scratch ----------------
__device__ float d_t  [25165824];  // [8,192,128,128]  conv1x1 output
__device__ float d_g  [25165824];  // [8,192,128,128]  gates (HW|CW|HC)
__device__ float d_xhw[8388608];
__device__ float d_xcw[8388608];
__device__ float d_xhc[8388608];
__device__ float d_mid[8388608];
__device__ float d_o1 [8388608];
__device__ float d_wd [16384];     // folded down weights [4][64(c)][64(o)]

__device__ __forceinline__ float lrelu(float v) { return v > 0.f ? v : 0.1f * v; }

// ---------------- prep: fold w_down into 4 x (64x64) 1x1 weights ----------------
__global__ void prep_wd_kernel(const float* __restrict__ w_down, float* __restrict__ wd)
{
    int idx = blockIdx.x * 256 + threadIdx.x;
    if (idx >= 16384) return;
    int s = idx >> 12;
    int rem = idx & 4095;
    int c = rem >> 6;
    int o = rem & 63;
    // w_down shape [64][128][2][2], index ((o*128 + i)*2 + ky)*2 + kx
    auto W = [&](int i, int ky, int kx) { return w_down[((o * 128 + i) * 2 + ky) * 2 + kx]; };
    float v = 0.f;
    if (s == 0) v = W(2 * c, 0, 0) + W(2 * c + 1, 1, 1);      // x
    else if (s == 1) v = W(2 * c, 0, 1) + W(2 * c + 1, 1, 0); // x_hw
    else if (s == 2) v = W(2 * c, 1, 0) + W(2 * c + 1, 0, 1); // x_cw
    else v = W(2 * c, 1, 1) + W(2 * c + 1, 0, 0);             // x_hc
    wd[s * 4096 + c * 64 + o] = v;
}

// ---------------- conv1x1: t = w_hwc @ x + b_hwc   (64 -> 192) ----------------
__global__ __launch_bounds__(128)
void conv1x1_kernel(const float* __restrict__ x, const float* __restrict__ w,
                    const float* __restrict__ bias, float* __restrict__ t)
{
    __shared__ float ws[64][32];
    const int tid = threadIdx.x;
    const int p4 = (blockIdx.x * 128 + tid) * 4;
    const int oc0 = blockIdx.y * 32;
    const int b = blockIdx.z;

    for (int idx = tid; idx < 2048; idx += 128) {
        int c = idx >> 5, i = idx & 31;
        ws[c][i] = w[(oc0 + i) * 64 + c];
    }
    __syncthreads();

    float4 acc[32];
#pragma unroll
    for (int i = 0; i < 32; i++) acc[i] = make_float4(0.f, 0.f, 0.f, 0.f);

    const int xb = b * CHW_ + p4;
    for (int c = 0; c < 64; c++) {
        float4 xv = *(const float4*)&x[xb + c * HW_];
#pragma unroll
        for (int i = 0; i < 32; i++) {
            float wv = ws[c][i];
            acc[i].x += wv * xv.x; acc[i].y += wv * xv.y;
            acc[i].z += wv * xv.z; acc[i].w += wv * xv.w;
        }
    }
#pragma unroll
    for (int i = 0; i < 32; i++) {
        float bv = bias[oc0 + i];
        float4 v = acc[i];
        v.x += bv; v.y += bv; v.z += bv; v.w += bv;
        *(float4*)&t[b * GBS_ + (oc0 + i) * HW_ + p4] = v;
    }
}

// ---------------- depthwise 3x3: g = dw(t) + b_dw ----------------
__global__ __launch_bounds__(128)
void dwconv_kernel(const float* __restrict__ t, const float* __restrict__ w_dw,
                   const float* __restrict__ b_dw, float* __restrict__ g)
{
    __shared__ float xs[10][68];
    const int tid = threadIdx.x;
    const int s1t = blockIdx.x & 15, s2t = blockIdx.x >> 4;
    const int s1_0 = s1t * 8, s2_0 = s2t * 64;
    const int og = blockIdx.y, b = blockIdx.z;
    const int base = b * GBS_ + og * HW_;

    for (int idx = tid; idx < 660; idx += 128) {
        int row = idx / 66, col = idx - row * 66;
        int s1g = s1_0 - 1 + row;
        int s2g = s2_0 - 1 + col;
        float v = 0.f;
        if (s1g >= 0 && s1g < 128 && s2g >= 0 && s2g < 128)
            v = t[base + s1g * 128 + s2g];
        xs[row][col] = v;
    }
    __syncthreads();

    float w[9];
#pragma unroll
    for (int k = 0; k < 9; k++) w[k] = w_dw[og * 9 + k];
    float bb = b_dw[og];

    const int r = tid >> 4, cb = (tid & 15) * 4;
    float4 v;
    float* vp = &v.x;
#pragma unroll
    for (int j = 0; j < 4; j++) {
        float s = bb;
#pragma unroll
        for (int dr = 0; dr < 3; dr++)
#pragma unroll
            for (int dc = 0; dc < 3; dc++)
                s += w[dr * 3 + dc] * xs[r + dr][cb + j + dc];
        vp[j] = s;
    }
    *(float4*)&g[base + (s1_0 + r) * 128 + s2_0 + cb] = v;
}

// ---------------- generic 3x3 conv, s2-contiguous input ----------------
// y(b, oc, s1, s2) = sum_k sum_{dr,dc} w[oc,k,dr,dc] * x[b, k*sk + (s1+dr-1)*ss1 + (s2+dc-1)]
// out addr: out + b*o_b + oc*o_oc + s1*o_s1 + s2 ; gate addr: gate + b*g_b + (same elem offset)
// mode: 1 = lrelu ; 2 = lrelu*gate ; 3 = res + lrelu
__global__ __launch_bounds__(128)
void conv3x3_A(const float* __restrict__ x, const float* __restrict__ wgt,
               const float* __restrict__ bias, float* __restrict__ out,
               const float* __restrict__ gate, const float* __restrict__ res,
               int K, int S1, int sk, int ss1,
               int o_oc, int o_s1, int o_b, int g_b, int mode)
{
    __shared__ float xs[10][68];
    __shared__ float ws[16][9];
    const int tid = threadIdx.x;
    const int n_s1t = S1 >> 3;
    const int s1t = blockIdx.x % n_s1t;
    const int s2t = blockIdx.x / n_s1t;
    const int s1_0 = s1t * 8;
    const int s2_0 = s2t * 64;
    const int oc0 = blockIdx.y * 16;
    const int b = blockIdx.z;
    const int xb = b * CHW_;

    const int r = tid >> 4;
    const int cb = (tid & 15) * 4;

    float acc[16][4];
#pragma unroll
    for (int i = 0; i < 16; i++)
#pragma unroll
        for (int j = 0; j < 4; j++) acc[i][j] = 0.f;

    for (int c = 0; c < K; c++) {
        for (int idx = tid; idx < 660; idx += 128) {
            int row = idx / 66, col = idx - row * 66;
            int s1g = s1_0 - 1 + row;
            int s2g = s2_0 - 1 + col;
            float v = 0.f;
            if (s1g >= 0 && s1g < S1 && s2g >= 0 && s2g < 128)
                v = x[xb + c * sk + s1g * ss1 + s2g];
            xs[row][col] = v;
        }
        for (int idx = tid; idx < 144; idx += 128) {
            int oi = idx / 9, kk = idx - oi * 9;
            ws[oi][kk] = wgt[(oc0 + oi) * K * 9 + c * 9 + kk];
        }
        __syncthreads();

        float nb[3][6];
#pragma unroll
        for (int dr = 0; dr < 3; dr++)
#pragma unroll
            for (int j = 0; j < 6; j++)
                nb[dr][j] = xs[r + dr][cb + j];

#pragma unroll
        for (int oi = 0; oi < 16; oi++) {
            float w[9];
#pragma unroll
            for (int k = 0; k < 9; k++) w[k] = ws[oi][k];
#pragma unroll
            for (int j = 0; j < 4; j++) {
                acc[oi][j] += w[0] * nb[0][j] + w[1] * nb[0][j + 1] + w[2] * nb[0][j + 2]
                            + w[3] * nb[1][j] + w[4] * nb[1][j + 1] + w[5] * nb[1][j + 2]
                            + w[6] * nb[2][j] + w[7] * nb[2][j + 1] + w[8] * nb[2][j + 2];
            }
        }
        __syncthreads();
    }

    const int s1 = s1_0 + r;
    const int s2b = s2_0 + cb;
#pragma unroll
    for (int oi = 0; oi < 16; oi++) {
        int oc = oc0 + oi;
        float bv = bias[oc];
        int e = oc * o_oc + s1 * o_s1 + s2b;
        float4 v;
        float* vp = &v.x;
#pragma unroll
        for (int j = 0; j < 4; j++) {
            float tv = acc[oi][j] + bv;
            tv = lrelu(tv);
            vp[j] = tv;
        }
        if (mode == 2) {
            float4 g4 = *(const float4*)&gate[b * g_b + e];
            v.x *= g4.x; v.y *= g4.y; v.z *= g4.z; v.w *= g4.w;
        } else if (mode == 3) {
            float4 r4 = *(const float4*)&res[b * o_b + e];
            v.x += r4.x; v.y += r4.y; v.z += r4.z; v.w += r4.w;
        }
        *(float4*)&out[b * o_b + e] = v;
    }
}

// ---------------- x_hc conv: channel axis contiguous (k = w) ----------------
// y(b, oc=wo, s1=h, s2=c) = sum_wi sum_{dh,dc} w_hc[wo,wi,dh,dc] * x[b, (s2+dc-1)*16384 + (s1+dh-1)*128 + wi]
// stored at x-layout [b, s2, s1, oc]; gated by HC at same elem offsets.
__global__ __launch_bounds__(128)
void conv3x3_B(const float* __restrict__ x, const float* __restrict__ wgt,
               const float* __restrict__ bias, float* __restrict__ out,
               const float* __restrict__ gate)
{
    __shared__ float xs[4][18][36];
    __shared__ float ws[16][4][9];
    const int tid = threadIdx.x;
    const int s1t = blockIdx.x & 7;   // h tiles of 16
    const int s2t = blockIdx.x >> 3;  // c tiles of 32
    const int s1_0 = s1t * 16;
    const int s2_0 = s2t * 32;
    const int oc0 = blockIdx.y * 16;
    const int b = blockIdx.z;
    const int xb = b * CHW_;

    const int sc = tid & 31;          // s2 (c) within tile
    const int sr4 = (tid >> 5) * 4;   // s1 (h) base, 4 rows per thread

    float acc[16][4];
#pragma unroll
    for (int i = 0; i < 16; i++)
#pragma unroll
        for (int j = 0; j < 4; j++) acc[i][j] = 0.f;

    for (int k0 = 0; k0 < 128; k0 += 4) {
        for (int idx = tid; idx < 612; idx += 128) {
            int row = idx / 34, col = idx - row * 34;
            int s1g = s1_0 - 1 + row;
            int s2g = s2_0 - 1 + col;
            float4 v = make_float4(0.f, 0.f, 0.f, 0.f);
            if (s1g >= 0 && s1g < 128 && s2g >= 0 && s2g < 64)
                v = *(const float4*)&x[xb + s2g * HW_ + s1g * 128 + k0];
            xs[0][row][col] = v.x; xs[1][row][col] = v.y;
            xs[2][row][col] = v.z; xs[3][row][col] = v.w;
        }
        for (int idx = tid; idx < 576; idx += 128) {
            int oi = idx / 36;
            int rem = idx - oi * 36;
            int kk = rem / 9, k9 = rem - kk * 9;
            ws[oi][kk][k9] = wgt[(oc0 + oi) * 1152 + (k0 + kk) * 9 + k9];
        }
        __syncthreads();

#pragma unroll
        for (int kk = 0; kk < 4; kk++) {
            float nb[6][3];
#pragma unroll
            for (int rr = 0; rr < 6; rr++)
#pragma unroll
                for (int cc = 0; cc < 3; cc++)
                    nb[rr][cc] = xs[kk][sr4 + rr][sc + cc];
#pragma unroll
            for (int oi = 0; oi < 16; oi++) {
                float w[9];
#pragma unroll
                for (int k = 0; k < 9; k++) w[k] = ws[oi][kk][k];
#pragma unroll
                for (int i = 0; i < 4; i++) {
                    acc[oi][i] += w[0] * nb[i][0] + w[1] * nb[i][1] + w[2] * nb[i][2]
                                + w[3] * nb[i + 1][0] + w[4] * nb[i + 1][1] + w[5] * nb[i + 1][2]
                                + w[6] * nb[i + 2][0] + w[7] * nb[i + 2][1] + w[8] * nb[i + 2][2];
                }
            }
        }
        __syncthreads();
    }

    float bv[16];
#pragma unroll
    for (int oi = 0; oi < 16; oi++) bv[oi] = bias[oc0 + oi];

#pragma unroll
    for (int i = 0; i < 4; i++) {
        int s1 = s1_0 + sr4 + i;
        int e = (s2_0 + sc) * HW_ + s1 * 128 + oc0;
        const float4* g4p = (const float4*)&gate[b * GBS_ + e];
        float4* op = (float4*)&out[b * CHW_ + e];
#pragma unroll
        for (int q = 0; q < 4; q++) {
            float4 g4 = g4p[q];
            float4 v;
            v.x = lrelu(acc[q * 4 + 0][i] + bv[q * 4 + 0]) * g4.x;
            v.y = lrelu(acc[q * 4 + 1][i] + bv[q * 4 + 1]) * g4.y;
            v.z = lrelu(acc[q * 4 + 2][i] + bv[q * 4 + 2]) * g4.z;
            v.w = lrelu(acc[q * 4 + 3][i] + bv[q * 4 + 3]) * g4.w;
            op[q] = v;
        }
    }
}

// ---------------- folded down-conv: mid = sum_src Weff[src] @ src + b_down + x ----------------
__global__ __launch_bounds__(128)
void down_kernel(const float* __restrict__ x, const float* __restrict__ xhw,
                 const float* __restrict__ xcw, const float* __restrict__ xhc,
                 const float* __restrict__ wd, const float* __restrict__ b_down,
                 float* __restrict__ mid)
{
    __shared__ float ws[4][64][32];
    const int tid = threadIdx.x;
    const int p4 = (blockIdx.x * 128 + tid) * 4;
    const int oc0 = blockIdx.y * 32;
    const int b = blockIdx.z;

    for (int idx = tid; idx < 8192; idx += 128) {
        int s = idx >> 11;
        int rem = idx & 2047;
        int c = rem >> 5, i = rem & 31;
        ws[s][c][i] = wd[s * 4096 + c * 64 + oc0 + i];
    }
    __syncthreads();

    float4 acc[32];
#pragma unroll
    for (int i = 0; i < 32; i++) acc[i] = make_float4(0.f, 0.f, 0.f, 0.f);

    const int xb = b * CHW_ + p4;
    for (int c = 0; c < 64; c++) {
        int off = xb + c * HW_;
        float4 a = *(const float4*)&x[off];
        float4 h = *(const float4*)&xhw[off];
        float4 cw = *(const float4*)&xcw[off];
        float4 hc = *(const float4*)&xhc[off];
#pragma unroll
        for (int i = 0; i < 32; i++) {
            float w0 = ws[0][c][i], w1 = ws[1][c][i], w2 = ws[2][c][i], w3 = ws[3][c][i];
            acc[i].x += w0 * a.x + w1 * h.x + w2 * cw.x + w3 * hc.x;
            acc[i].y += w0 * a.y + w1 * h.y + w2 * cw.y + w3 * hc.y;
            acc[i].z += w0 * a.z + w1 * h.z + w2 * cw.z + w3 * hc.z;
            acc[i].w += w0 * a.w + w1 * h.w + w2 * cw.w + w3 * hc.w;
        }
    }
#pragma unroll
    for (int i = 0; i < 32; i++) {
        int oc = oc0 + i;
        float bvv = b_down[oc];
        float4 xr = *(const float4*)&x[b * CHW_ + oc * HW_ + p4];
        float4 v = acc[i];
        v.x += bvv + xr.x; v.y += bvv + xr.y;
        v.z += bvv + xr.z; v.w += bvv + xr.w;
        *(float4*)&mid[b * CHW_ + oc * HW_ + p4] = v;
    }
}

// ---------------- launch ----------------
extern "C" void kernel_launch(void* const* d_in, const int* in_sizes, int n_in,
                              void* d_out, int out_size)
{
    const float* x      = (const float*)d_in[0];
    const float* w_hwc  = (const float*)d_in[1];
    const float* b_hwc  = (const float*)d_in[2];
    const float* w_dw   = (const float*)d_in[3];
    const float* b_dw   = (const float*)d_in[4];
    const float* w_hw   = (const float*)d_in[5];
    const float* b_hw   = (const float*)d_in[6];
    const float* w_cw   = (const float*)d_in[7];
    const float* b_cw   = (const float*)d_in[8];
    const float* w_hc   = (const float*)d_in[9];
    const float* b_hc   = (const float*)d_in[10];
    const float* w_down = (const float*)d_in[11];
    const float* b_down = (const float*)d_in[12];
    const float* w_l1   = (const float*)d_in[13];
    const float* b_l1   = (const float*)d_in[14];
    const float* w_l2   = (const float*)d_in[15];
    const float* b_l2   = (const float*)d_in[16];
    float* out = (float*)d_out;

    float *t, *g, *xhw, *xcw, *xhc, *mid, *o1, *wd;
    cudaGetSymbolAddress((void**)&t,   d_t);
    cudaGetSymbolAddress((void**)&g,   d_g);
    cudaGetSymbolAddress((void**)&xhw, d_xhw);
    cudaGetSymbolAddress((void**)&xcw, d_xcw);
    cudaGetSymbolAddress((void**)&xhc, d_xhc);
    cudaGetSymbolAddress((void**)&mid, d_mid);
    cudaGetSymbolAddress((void**)&o1,  d_o1);
    cudaGetSymbolAddress((void**)&wd,  d_wd);

    // fold down-conv weights
    prep_wd_kernel<<<64, 256>>>(w_down, wd);

    // gates: t = 1x1(x), g = dw3x3(t)
    conv1x1_kernel<<<dim3(32, 6, 8), 128>>>(x, w_hwc, b_hwc, t);
    dwconv_kernel<<<dim3(32, 192, 8), 128>>>(t, w_dw, b_dw, g);

    // x_hw: standard conv3x3 (64->64), gated by HW (gate group 0)
    conv3x3_A<<<dim3(32, 4, 8), 128>>>(x, w_hw, b_hw, xhw, g, nullptr,
                                       64, 128, HW_, 128,
                                       HW_, 128, CHW_, GBS_, 2);
    // x_cw: conv over (c,w) with H as channels (128->128), gated by CW (group 1)
    conv3x3_A<<<dim3(16, 8, 8), 128>>>(x, w_cw, b_cw, xcw, g + 64 * HW_, nullptr,
                                       128, 64, 128, HW_,
                                       128, HW_, CHW_, GBS_, 2);
    // x_hc: conv over (h,c) with W as channels (128->128), gated by HC (group 2)
    conv3x3_B<<<dim3(16, 8, 8), 128>>>(x, w_hc, b_hc, xhc, g + 128 * HW_);

    // folded PixelShuffle + interleave + stride-2 down + residual
    down_kernel<<<dim3(32, 2, 8), 128>>>(x, xhw, xcw, xhc, wd, b_down, mid);

    // l1: lrelu(conv3x3(mid))
    conv3x3_A<<<dim3(32, 4, 8), 128>>>(mid, w_l1, b_l1, o1, nullptr, nullptr,
                                       64, 128, HW_, 128,
                                       HW_, 128, CHW_, 0, 1);
    // l2 + final residual: out = x + lrelu(conv3x3(o1))
    conv3x3_A<<<dim3(32, 4, 8), 128>>>(o1, w_l2, b_l2, out, nullptr, x,
                                       64, 128, HW_, 128,
                                       HW_, 128, CHW_, 0, 3);
}

// round 2
// speedup vs baseline: 1.9366x; 1.9366x over previous
#include <cuda_runtime.h>
#include <cstdint>

// B=8, C=64, T=128
#define HW_   16384
#define CHW_  1048576
#define GBS_  3145728

// ---------------- scratch ----------------
__device__ float d_t  [25165824];  // [8,192,128,128] conv1x1 out
__device__ float d_g  [25165824];  // [8,192,128,128] gates
__device__ float d_xt1[8388608];   // x.transpose(0,2,1,3): [b][h][c][w]
__device__ float d_xt2[8388608];   // x.transpose(0,3,2,1): [b][w][h][c]
__device__ float d_xhw[8388608];
__device__ float d_xcw[8388608];
__device__ float d_xhc[8388608];
__device__ float d_mid[8388608];
__device__ float d_o1 [8388608];
__device__ float d_wd [16384];     // folded down weights [4][64(c)][64(o)]

__device__ __forceinline__ float lrelu(float v) { return v > 0.f ? v : 0.1f * v; }

__device__ __forceinline__ void cp_async16(uint32_t dst, const float* src, bool valid) {
    int sz = valid ? 16 : 0;
    asm volatile("cp.async.cg.shared.global [%0], [%1], 16, %2;\n"
                 :: "r"(dst), "l"(src), "r"(sz));
}
__device__ __forceinline__ void cp_commit() { asm volatile("cp.async.commit_group;\n"); }
__device__ __forceinline__ void cp_wait0()  { asm volatile("cp.async.wait_group 0;\n"); }

// ---------------- prep: fold w_down into 4 x (64x64) 1x1 weights ----------------
__global__ void prep_wd_kernel(const float* __restrict__ w_down, float* __restrict__ wd)
{
    int idx = blockIdx.x * 256 + threadIdx.x;
    if (idx >= 16384) return;
    int s = idx >> 12;
    int rem = idx & 4095;
    int c = rem >> 6;
    int o = rem & 63;
    auto W = [&](int i, int ky, int kx) { return w_down[((o * 128 + i) * 2 + ky) * 2 + kx]; };
    float v = 0.f;
    if (s == 0) v = W(2 * c, 0, 0) + W(2 * c + 1, 1, 1);
    else if (s == 1) v = W(2 * c, 0, 1) + W(2 * c + 1, 1, 0);
    else if (s == 2) v = W(2 * c, 1, 0) + W(2 * c + 1, 0, 1);
    else v = W(2 * c, 1, 1) + W(2 * c + 1, 0, 0);
    wd[s * 4096 + c * 64 + o] = v;
}

// ---------------- transposes ----------------
// xt1[b][h][c][w] = x[b][c][h][w]
__global__ __launch_bounds__(256)
void t1_kernel(const float* __restrict__ x, float* __restrict__ o)
{
    int i = blockIdx.x * 256 + threadIdx.x;       // 2097152 float4s
    int w4 = i & 31; int rest = i >> 5;
    int h = rest & 127; rest >>= 7;
    int c = rest & 63; int b = rest >> 6;
    float4 v = *(const float4*)&x[((b * 64 + c) * 128 + h) * 128 + w4 * 4];
    *(float4*)&o[((b * 128 + h) * 64 + c) * 128 + w4 * 4] = v;
}

// xt2[b][w][h][c] = x[b][c][h][w]   (transpose (c,w) plane per (b,h))
__global__ __launch_bounds__(256)
void t2_kernel(const float* __restrict__ x, float* __restrict__ o)
{
    __shared__ float tile[32][33];
    int tx = threadIdx.x, ty = threadIdx.y;
    int w0 = blockIdx.x * 32;
    int c0 = blockIdx.y * 32;
    int bh = blockIdx.z;
    int b = bh >> 7, h = bh & 127;
    int xb = b * CHW_ + h * 128;
#pragma unroll
    for (int i = 0; i < 4; i++)
        tile[ty + 8 * i][tx] = x[xb + (c0 + ty + 8 * i) * HW_ + w0 + tx];
    __syncthreads();
    int ob = b * CHW_ + h * 64;
#pragma unroll
    for (int i = 0; i < 4; i++)
        o[ob + (w0 + ty + 8 * i) * 8192 + c0 + tx] = tile[tx][ty + 8 * i];
}

// ---------------- conv1x1: t = w_hwc @ x + b_hwc (64 -> 192) ----------------
__global__ __launch_bounds__(128)
void conv1x1_kernel(const float* __restrict__ x, const float* __restrict__ w,
                    const float* __restrict__ bias, float* __restrict__ t)
{
    __shared__ float ws[64][32];
    const int tid = threadIdx.x;
    const int p4 = (blockIdx.x * 128 + tid) * 4;
    const int oc0 = blockIdx.y * 32;
    const int b = blockIdx.z;

    for (int idx = tid; idx < 2048; idx += 128) {
        int c = idx >> 5, i = idx & 31;
        ws[c][i] = w[(oc0 + i) * 64 + c];
    }
    __syncthreads();

    float4 acc[32];
#pragma unroll
    for (int i = 0; i < 32; i++) acc[i] = make_float4(0.f, 0.f, 0.f, 0.f);

    const int xb = b * CHW_ + p4;
    for (int c = 0; c < 64; c++) {
        float4 xv = *(const float4*)&x[xb + c * HW_];
#pragma unroll
        for (int i = 0; i < 32; i++) {
            float wv = ws[c][i];
            acc[i].x += wv * xv.x; acc[i].y += wv * xv.y;
            acc[i].z += wv * xv.z; acc[i].w += wv * xv.w;
        }
    }
#pragma unroll
    for (int i = 0; i < 32; i++) {
        float bv = bias[oc0 + i];
        float4 v = acc[i];
        v.x += bv; v.y += bv; v.z += bv; v.w += bv;
        *(float4*)&t[b * GBS_ + (oc0 + i) * HW_ + p4] = v;
    }
}

// ---------------- depthwise 3x3 ----------------
__global__ __launch_bounds__(128)
void dwconv_kernel(const float* __restrict__ t, const float* __restrict__ w_dw,
                   const float* __restrict__ b_dw, float* __restrict__ g)
{
    __shared__ float xs[10][68];
    const int tid = threadIdx.x;
    const int s1t = blockIdx.x & 15, s2t = blockIdx.x >> 4;
    const int s1_0 = s1t * 8, s2_0 = s2t * 64;
    const int og = blockIdx.y, b = blockIdx.z;
    const int base = b * GBS_ + og * HW_;

    for (int idx = tid; idx < 660; idx += 128) {
        int row = idx / 66, col = idx - row * 66;
        int s1g = s1_0 - 1 + row;
        int s2g = s2_0 - 1 + col;
        float v = 0.f;
        if (s1g >= 0 && s1g < 128 && s2g >= 0 && s2g < 128)
            v = t[base + s1g * 128 + s2g];
        xs[row][col] = v;
    }
    __syncthreads();

    float w[9];
#pragma unroll
    for (int k = 0; k < 9; k++) w[k] = w_dw[og * 9 + k];
    float bb = b_dw[og];

    const int r = tid >> 4, cb = (tid & 15) * 4;
    float4 v;
    float* vp = &v.x;
#pragma unroll
    for (int j = 0; j < 4; j++) {
        float s = bb;
#pragma unroll
        for (int dr = 0; dr < 3; dr++)
#pragma unroll
            for (int dc = 0; dc < 3; dc++)
                s += w[dr * 3 + dc] * xs[r + dr][cb + j + dc];
        vp[j] = s;
    }
    *(float4*)&g[base + (s1_0 + r) * 128 + s2_0 + cb] = v;
}

// ---------------- pipelined generic 3x3 conv ----------------
// input x: [b][K][S1][W] contiguous (batch stride K*S1*W)
// out addr: b*o_b + oc*o_oc + s1*o_s1 + s2*o_s2
// OUTV 0: o_s2==1 (vectorize over px). OUTV 1: o_oc==1 (vectorize over oc).
// RES 1: add res (standard layout, same offsets as out).
template<int K, int S1, int W, int PX, int OUTV, int RES>
__global__ __launch_bounds__(128)
void conv3x3_v2(const float* __restrict__ x, const float* __restrict__ wgt,
                const float* __restrict__ bias, float* __restrict__ out,
                const float* __restrict__ res,
                int o_oc, int o_s1, int o_s2, int o_b)
{
    constexpr int XROW = W + 8;
    constexpr int CH = W / 4;
    constexpr int NCP = 10 * CH;
    __shared__ float xs[2][10][XROW];
    __shared__ float wsm[K * 72];      // [c][oi 0..7][k 0..8]

    const int tid = threadIdx.x;
    const int s1_0 = blockIdx.x * 8;
    const int oc0 = blockIdx.y * 8;
    const int b = blockIdx.z;
    const int xb = b * (K * S1 * W);

    // zero halo columns (cols 3 and W+4), both buffers, once
    if (tid < 40) {
        int bufi = tid & 1;
        int row = (tid >> 1) % 10;
        int side = tid / 20;
        xs[bufi][row][side ? (W + 4) : 3] = 0.f;
    }

    // stage all weights for this oc-block
    for (int idx = tid; idx < K * 72; idx += 128) {
        int c = idx / 72;
        int rem = idx - c * 72;
        int oi = rem / 9, k = rem - oi * 9;
        wsm[idx] = wgt[((oc0 + oi) * K + c) * 9 + k];
    }

    auto load_tile = [&](int c, int bufi) {
        const float* src_base = x + xb + c * (S1 * W);
        uint32_t dst_base = (uint32_t)__cvta_generic_to_shared(&xs[bufi][0][0]);
        for (int idx = tid; idx < NCP; idx += 128) {
            int row = idx / CH;
            int jc = idx - row * CH;
            int s1g = s1_0 - 1 + row;
            bool v = (s1g >= 0) && (s1g < S1);
            int s1c = v ? s1g : 0;
            cp_async16(dst_base + (uint32_t)((row * XROW + 4 + jc * 4) * 4),
                       src_base + s1c * W + jc * 4, v);
        }
        cp_commit();
    };

    load_tile(0, 0);
    cp_wait0();
    __syncthreads();

    const int r = tid >> 4;
    const int cb = (tid & 15) * PX;

    float acc[8][PX];
#pragma unroll
    for (int oi = 0; oi < 8; oi++)
#pragma unroll
        for (int j = 0; j < PX; j++) acc[oi][j] = 0.f;

    int buf = 0;
    for (int c = 0; c < K; c++) {
        if (c + 1 < K) load_tile(c + 1, buf ^ 1);
        else cp_commit();

        float nb0[PX + 2], nb1[PX + 2], nb2[PX + 2];
#pragma unroll
        for (int m = 0; m < PX + 2; m++) {
            nb0[m] = xs[buf][r + 0][cb + 3 + m];
            nb1[m] = xs[buf][r + 1][cb + 3 + m];
            nb2[m] = xs[buf][r + 2][cb + 3 + m];
        }
        const float* wp = &wsm[c * 72];
#pragma unroll
        for (int oi = 0; oi < 8; oi++) {
            float w0 = wp[oi * 9 + 0], w1 = wp[oi * 9 + 1], w2 = wp[oi * 9 + 2];
            float w3 = wp[oi * 9 + 3], w4 = wp[oi * 9 + 4], w5 = wp[oi * 9 + 5];
            float w6 = wp[oi * 9 + 6], w7 = wp[oi * 9 + 7], w8 = wp[oi * 9 + 8];
#pragma unroll
            for (int j = 0; j < PX; j++) {
                acc[oi][j] += w0 * nb0[j] + w1 * nb0[j + 1] + w2 * nb0[j + 2]
                            + w3 * nb1[j] + w4 * nb1[j + 1] + w5 * nb1[j + 2]
                            + w6 * nb2[j] + w7 * nb2[j + 1] + w8 * nb2[j + 2];
            }
        }
        cp_wait0();
        __syncthreads();
        buf ^= 1;
    }

    const int s1 = s1_0 + r;
    if (OUTV == 0) {
        const int obase = b * o_b + s1 * o_s1 + cb;
#pragma unroll
        for (int oi = 0; oi < 8; oi++) {
            float bv = bias[oc0 + oi];
            int e = obase + (oc0 + oi) * o_oc;
#pragma unroll
            for (int j4 = 0; j4 < PX; j4 += 4) {
                float4 v;
                v.x = lrelu(acc[oi][j4 + 0] + bv);
                v.y = lrelu(acc[oi][j4 + 1] + bv);
                v.z = lrelu(acc[oi][j4 + 2] + bv);
                v.w = lrelu(acc[oi][j4 + 3] + bv);
                if (RES) {
                    float4 rr = *(const float4*)&res[e + j4];
                    v.x += rr.x; v.y += rr.y; v.z += rr.z; v.w += rr.w;
                }
                *(float4*)&out[e + j4] = v;
            }
        }
    } else {
        float bv[8];
#pragma unroll
        for (int oi = 0; oi < 8; oi++) bv[oi] = bias[oc0 + oi];
#pragma unroll
        for (int j = 0; j < PX; j++) {
            int e = b * o_b + (cb + j) * o_s2 + s1 * o_s1 + oc0;
            float4 v0, v1;
            v0.x = lrelu(acc[0][j] + bv[0]); v0.y = lrelu(acc[1][j] + bv[1]);
            v0.z = lrelu(acc[2][j] + bv[2]); v0.w = lrelu(acc[3][j] + bv[3]);
            v1.x = lrelu(acc[4][j] + bv[4]); v1.y = lrelu(acc[5][j] + bv[5]);
            v1.z = lrelu(acc[6][j] + bv[6]); v1.w = lrelu(acc[7][j] + bv[7]);
            *(float4*)&out[e] = v0;
            *(float4*)&out[e + 4] = v1;
        }
    }
}

// ---------------- fused gate + folded down-conv + residual ----------------
__global__ __launch_bounds__(128)
void down_kernel_v2(const float* __restrict__ x, const float* __restrict__ xhw,
                    const float* __restrict__ xcw, const float* __restrict__ xhc,
                    const float* __restrict__ g,
                    const float* __restrict__ wd, const float* __restrict__ b_down,
                    float* __restrict__ mid)
{
    __shared__ float ws[4][64][32];
    const int tid = threadIdx.x;
    const int p4 = (blockIdx.x * 128 + tid) * 4;
    const int oc0 = blockIdx.y * 32;
    const int b = blockIdx.z;

    for (int idx = tid; idx < 8192; idx += 128) {
        int s = idx >> 11;
        int rem = idx & 2047;
        int c = rem >> 5, i = rem & 31;
        ws[s][c][i] = wd[s * 4096 + c * 64 + oc0 + i];
    }
    __syncthreads();

    float4 acc[32];
#pragma unroll
    for (int i = 0; i < 32; i++) acc[i] = make_float4(0.f, 0.f, 0.f, 0.f);

    const int xb = b * CHW_ + p4;
    const int gb = b * GBS_ + p4;
    for (int c = 0; c < 64; c++) {
        int off = xb + c * HW_;
        float4 a  = *(const float4*)&x[off];
        float4 h  = *(const float4*)&xhw[off];
        float4 cw = *(const float4*)&xcw[off];
        float4 hc = *(const float4*)&xhc[off];
        float4 g0 = *(const float4*)&g[gb + c * HW_];
        float4 g1 = *(const float4*)&g[gb + (64 + c) * HW_];
        float4 g2 = *(const float4*)&g[gb + (128 + c) * HW_];
        h.x *= g0.x; h.y *= g0.y; h.z *= g0.z; h.w *= g0.w;
        cw.x *= g1.x; cw.y *= g1.y; cw.z *= g1.z; cw.w *= g1.w;
        hc.x *= g2.x; hc.y *= g2.y; hc.z *= g2.z; hc.w *= g2.w;
#pragma unroll
        for (int i = 0; i < 32; i++) {
            float w0 = ws[0][c][i], w1 = ws[1][c][i], w2 = ws[2][c][i], w3 = ws[3][c][i];
            acc[i].x += w0 * a.x + w1 * h.x + w2 * cw.x + w3 * hc.x;
            acc[i].y += w0 * a.y + w1 * h.y + w2 * cw.y + w3 * hc.y;
            acc[i].z += w0 * a.z + w1 * h.z + w2 * cw.z + w3 * hc.z;
            acc[i].w += w0 * a.w + w1 * h.w + w2 * cw.w + w3 * hc.w;
        }
    }
#pragma unroll
    for (int i = 0; i < 32; i++) {
        int oc = oc0 + i;
        float bvv = b_down[oc];
        float4 xr = *(const float4*)&x[b * CHW_ + oc * HW_ + p4];
        float4 v = acc[i];
        v.x += bvv + xr.x; v.y += bvv + xr.y;
        v.z += bvv + xr.z; v.w += bvv + xr.w;
        *(float4*)&mid[b * CHW_ + oc * HW_ + p4] = v;
    }
}

// ---------------- launch ----------------
extern "C" void kernel_launch(void* const* d_in, const int* in_sizes, int n_in,
                              void* d_out, int out_size)
{
    const float* x      = (const float*)d_in[0];
    const float* w_hwc  = (const float*)d_in[1];
    const float* b_hwc  = (const float*)d_in[2];
    const float* w_dw   = (const float*)d_in[3];
    const float* b_dw   = (const float*)d_in[4];
    const float* w_hw   = (const float*)d_in[5];
    const float* b_hw   = (const float*)d_in[6];
    const float* w_cw   = (const float*)d_in[7];
    const float* b_cw   = (const float*)d_in[8];
    const float* w_hc   = (const float*)d_in[9];
    const float* b_hc   = (const float*)d_in[10];
    const float* w_down = (const float*)d_in[11];
    const float* b_down = (const float*)d_in[12];
    const float* w_l1   = (const float*)d_in[13];
    const float* b_l1   = (const float*)d_in[14];
    const float* w_l2   = (const float*)d_in[15];
    const float* b_l2   = (const float*)d_in[16];
    float* out = (float*)d_out;

    float *t, *g, *xt1, *xt2, *xhw, *xcw, *xhc, *mid, *o1, *wd;
    cudaGetSymbolAddress((void**)&t,   d_t);
    cudaGetSymbolAddress((void**)&g,   d_g);
    cudaGetSymbolAddress((void**)&xt1, d_xt1);
    cudaGetSymbolAddress((void**)&xt2, d_xt2);
    cudaGetSymbolAddress((void**)&xhw, d_xhw);
    cudaGetSymbolAddress((void**)&xcw, d_xcw);
    cudaGetSymbolAddress((void**)&xhc, d_xhc);
    cudaGetSymbolAddress((void**)&mid, d_mid);
    cudaGetSymbolAddress((void**)&o1,  d_o1);
    cudaGetSymbolAddress((void**)&wd,  d_wd);

    prep_wd_kernel<<<64, 256>>>(w_down, wd);
    t1_kernel<<<8192, 256>>>(x, xt1);
    t2_kernel<<<dim3(4, 2, 1024), dim3(32, 8)>>>(x, xt2);

    conv1x1_kernel<<<dim3(32, 6, 8), 128>>>(x, w_hwc, b_hwc, t);
    dwconv_kernel<<<dim3(32, 192, 8), 128>>>(t, w_dw, b_dw, g);

    // x_hw: standard conv (64->64), lrelu only (gate applied in down)
    conv3x3_v2<64, 128, 128, 8, 0, 0><<<dim3(16, 8, 8), 128>>>(
        x, w_hw, b_hw, xhw, nullptr, HW_, 128, 1, CHW_);

    // x_cw: conv on xt1 [b][h][c][w]: K=128(h), S1=64(c), W=128(w)
    // out[b][c][h'][w] -> o_oc(h')=128, o_s1(c)=HW_, o_s2=1
    conv3x3_v2<128, 64, 128, 8, 0, 0><<<dim3(8, 16, 8), 128>>>(
        xt1, w_cw, b_cw, xcw, nullptr, 128, HW_, 1, CHW_);

    // x_hc: conv on xt2 [b][w][h][c]: K=128(w), S1=128(h), W=64(c)
    // out[b][c][h][w'] -> o_oc(w')=1, o_s1(h)=128, o_s2(c)=HW_
    conv3x3_v2<128, 128, 64, 4, 1, 0><<<dim3(16, 16, 8), 128>>>(
        xt2, w_hc, b_hc, xhc, nullptr, 1, 128, HW_, CHW_);

    // fused: gates * branches -> folded down-conv -> + x
    down_kernel_v2<<<dim3(32, 2, 8), 128>>>(x, xhw, xcw, xhc, g, wd, b_down, mid);

    // l1
    conv3x3_v2<64, 128, 128, 8, 0, 0><<<dim3(16, 8, 8), 128>>>(
        mid, w_l1, b_l1, o1, nullptr, HW_, 128, 1, CHW_);
    // l2 + residual
    conv3x3_v2<64, 128, 128, 8, 0, 1><<<dim3(16, 8, 8), 128>>>(
        o1, w_l2, b_l2, out, x, HW_, 128, 1, CHW_);
}

// round 3
// speedup vs baseline: 2.3657x; 1.2216x over previous
#include <cuda_runtime.h>
#include <cstdint>

// B=8, C=64, T=128
#define HW_   16384
#define CHW_  1048576
#define GBS_  3145728

typedef unsigned long long ull;

// ---------------- scratch ----------------
__device__ float d_t  [25165824];  // [8,192,128,128] conv1x1 out
__device__ float d_g  [25165824];  // [8,192,128,128] gates
__device__ float d_xt1[8388608];   // x.transpose(0,2,1,3): [b][h][c][w]
__device__ float d_xt2[8388608];   // x.transpose(0,3,2,1): [b][w][h][c]
__device__ float d_xhw[8388608];
__device__ float d_xcw[8388608];
__device__ float d_xhc[8388608];
__device__ float d_mid[8388608];
__device__ float d_o1 [8388608];
__device__ float d_wd [16384];     // folded down weights [4][64(c)][64(o)]

__device__ __forceinline__ float lrelu(float v) { return v > 0.f ? v : 0.1f * v; }

__device__ __forceinline__ void cp_async16(uint32_t dst, const float* src, bool valid) {
    int sz = valid ? 16 : 0;
    asm volatile("cp.async.cg.shared.global [%0], [%1], 16, %2;\n"
                 :: "r"(dst), "l"(src), "r"(sz));
}
__device__ __forceinline__ void cp_commit() { asm volatile("cp.async.commit_group;\n"); }
__device__ __forceinline__ void cp_wait0()  { asm volatile("cp.async.wait_group 0;\n"); }

// ---------------- f32x2 packed helpers ----------------
__device__ __forceinline__ ull pack2b(float v) {              // broadcast
    ull r; asm("mov.b64 %0, {%1,%1};" : "=l"(r) : "f"(v)); return r;
}
__device__ __forceinline__ float2 unpack2(ull v) {
    float2 r; asm("mov.b64 {%0,%1}, %2;" : "=f"(r.x), "=f"(r.y) : "l"(v)); return r;
}
__device__ __forceinline__ void ffma2(ull& d, ull a, ull b) { // d += a*b (2x fp32)
    asm("fma.rn.f32x2 %0, %1, %2, %0;" : "+l"(d) : "l"(a), "l"(b));
}

// ---------------- prep: fold w_down into 4 x (64x64) 1x1 weights ----------------
__global__ void prep_wd_kernel(const float* __restrict__ w_down, float* __restrict__ wd)
{
    int idx = blockIdx.x * 256 + threadIdx.x;
    if (idx >= 16384) return;
    int s = idx >> 12;
    int rem = idx & 4095;
    int c = rem >> 6;
    int o = rem & 63;
    auto W = [&](int i, int ky, int kx) { return w_down[((o * 128 + i) * 2 + ky) * 2 + kx]; };
    float v = 0.f;
    if (s == 0) v = W(2 * c, 0, 0) + W(2 * c + 1, 1, 1);
    else if (s == 1) v = W(2 * c, 0, 1) + W(2 * c + 1, 1, 0);
    else if (s == 2) v = W(2 * c, 1, 0) + W(2 * c + 1, 0, 1);
    else v = W(2 * c, 1, 1) + W(2 * c + 1, 0, 0);
    wd[s * 4096 + c * 64 + o] = v;
}

// ---------------- transposes ----------------
__global__ __launch_bounds__(256)
void t1_kernel(const float* __restrict__ x, float* __restrict__ o)
{
    int i = blockIdx.x * 256 + threadIdx.x;
    int w4 = i & 31; int rest = i >> 5;
    int h = rest & 127; rest >>= 7;
    int c = rest & 63; int b = rest >> 6;
    float4 v = *(const float4*)&x[((b * 64 + c) * 128 + h) * 128 + w4 * 4];
    *(float4*)&o[((b * 128 + h) * 64 + c) * 128 + w4 * 4] = v;
}

__global__ __launch_bounds__(256)
void t2_kernel(const float* __restrict__ x, float* __restrict__ o)
{
    __shared__ float tile[32][33];
    int tx = threadIdx.x, ty = threadIdx.y;
    int w0 = blockIdx.x * 32;
    int c0 = blockIdx.y * 32;
    int bh = blockIdx.z;
    int b = bh >> 7, h = bh & 127;
    int xb = b * CHW_ + h * 128;
#pragma unroll
    for (int i = 0; i < 4; i++)
        tile[ty + 8 * i][tx] = x[xb + (c0 + ty + 8 * i) * HW_ + w0 + tx];
    __syncthreads();
    int ob = b * CHW_ + h * 64;
#pragma unroll
    for (int i = 0; i < 4; i++)
        o[ob + (w0 + ty + 8 * i) * 8192 + c0 + tx] = tile[tx][ty + 8 * i];
}

// ---------------- conv1x1 (f32x2, 16-oc blocks) ----------------
__global__ __launch_bounds__(128)
void conv1x1_kernel(const float* __restrict__ x, const float* __restrict__ w,
                    const float* __restrict__ bias, float* __restrict__ t)
{
    __shared__ __align__(16) float ws[64][16];
    const int tid = threadIdx.x;
    const int p4 = (blockIdx.x * 128 + tid) * 4;
    const int oc0 = blockIdx.y * 16;
    const int b = blockIdx.z;

    for (int idx = tid; idx < 1024; idx += 128) {
        int c = idx >> 4, i = idx & 15;
        ws[c][i] = w[(oc0 + i) * 64 + c];
    }
    __syncthreads();

    ull acc2[8][4];
#pragma unroll
    for (int i = 0; i < 8; i++)
#pragma unroll
        for (int j = 0; j < 4; j++) acc2[i][j] = 0ull;

    const int xb = b * CHW_ + p4;
    for (int c = 0; c < 64; c++) {
        float4 xv = *(const float4*)&x[xb + c * HW_];
        ull xp[4] = { pack2b(xv.x), pack2b(xv.y), pack2b(xv.z), pack2b(xv.w) };
#pragma unroll
        for (int op = 0; op < 8; op++) {
            ull w2 = *(const ull*)&ws[c][op * 2];
            ffma2(acc2[op][0], w2, xp[0]);
            ffma2(acc2[op][1], w2, xp[1]);
            ffma2(acc2[op][2], w2, xp[2]);
            ffma2(acc2[op][3], w2, xp[3]);
        }
    }
#pragma unroll
    for (int op = 0; op < 8; op++) {
        float b0 = bias[oc0 + 2 * op], b1 = bias[oc0 + 2 * op + 1];
        float2 p0 = unpack2(acc2[op][0]), p1 = unpack2(acc2[op][1]);
        float2 p2 = unpack2(acc2[op][2]), p3 = unpack2(acc2[op][3]);
        float4 v0 = make_float4(p0.x + b0, p1.x + b0, p2.x + b0, p3.x + b0);
        float4 v1 = make_float4(p0.y + b1, p1.y + b1, p2.y + b1, p3.y + b1);
        *(float4*)&t[b * GBS_ + (oc0 + 2 * op) * HW_ + p4] = v0;
        *(float4*)&t[b * GBS_ + (oc0 + 2 * op + 1) * HW_ + p4] = v1;
    }
}

// ---------------- depthwise 3x3 ----------------
__global__ __launch_bounds__(128)
void dwconv_kernel(const float* __restrict__ t, const float* __restrict__ w_dw,
                   const float* __restrict__ b_dw, float* __restrict__ g)
{
    __shared__ float xs[10][68];
    const int tid = threadIdx.x;
    const int s1t = blockIdx.x & 15, s2t = blockIdx.x >> 4;
    const int s1_0 = s1t * 8, s2_0 = s2t * 64;
    const int og = blockIdx.y, b = blockIdx.z;
    const int base = b * GBS_ + og * HW_;

    for (int idx = tid; idx < 660; idx += 128) {
        int row = idx / 66, col = idx - row * 66;
        int s1g = s1_0 - 1 + row;
        int s2g = s2_0 - 1 + col;
        float v = 0.f;
        if (s1g >= 0 && s1g < 128 && s2g >= 0 && s2g < 128)
            v = t[base + s1g * 128 + s2g];
        xs[row][col] = v;
    }
    __syncthreads();

    float w[9];
#pragma unroll
    for (int k = 0; k < 9; k++) w[k] = w_dw[og * 9 + k];
    float bb = b_dw[og];

    const int r = tid >> 4, cb = (tid & 15) * 4;
    float4 v;
    float* vp = &v.x;
#pragma unroll
    for (int j = 0; j < 4; j++) {
        float s = bb;
#pragma unroll
        for (int dr = 0; dr < 3; dr++)
#pragma unroll
            for (int dc = 0; dc < 3; dc++)
                s += w[dr * 3 + dc] * xs[r + dr][cb + j + dc];
        vp[j] = s;
    }
    *(float4*)&g[base + (s1_0 + r) * 128 + s2_0 + cb] = v;
}

// ---------------- pipelined 3x3 conv with f32x2 (oc-pair lanes) ----------------
// input x: [b][K][S1][W]; out addr: b*o_b + oc*o_oc + s1*o_s1 + s2*o_s2
// OUTV 0: o_s2==1 (vectorize px). OUTV 1: o_oc==1 (vectorize oc). RES: add res.
template<int K, int S1, int W, int PX, int OUTV, int RES>
__global__ __launch_bounds__(128)
void conv3x3_v3(const float* __restrict__ x, const float* __restrict__ wgt,
                const float* __restrict__ bias, float* __restrict__ out,
                const float* __restrict__ res,
                int o_oc, int o_s1, int o_s2, int o_b)
{
    constexpr int XROW = W + 8;
    constexpr int CH = W / 4;
    constexpr int NCP = 10 * CH;
    __shared__ __align__(16) float xs[2][10][XROW];
    __shared__ __align__(16) float wsm[K * 72];   // [c][k 0..8][oi 0..7]

    const int tid = threadIdx.x;
    const int s1_0 = blockIdx.x * 8;
    const int oc0 = blockIdx.y * 8;
    const int b = blockIdx.z;
    const int xb = b * (K * S1 * W);

    if (tid < 40) {
        int bufi = tid & 1;
        int row = (tid >> 1) % 10;
        int side = tid / 20;
        xs[bufi][row][side ? (W + 4) : 3] = 0.f;
    }

    // weights: wsm[c*72 + k*8 + oi]  (oc pairs contiguous)
    for (int idx = tid; idx < K * 72; idx += 128) {
        int c = idx / 72;
        int rem = idx - c * 72;
        int k = rem >> 3, oi = rem & 7;
        wsm[idx] = wgt[((oc0 + oi) * K + c) * 9 + k];
    }

    auto load_tile = [&](int c, int bufi) {
        const float* src_base = x + xb + c * (S1 * W);
        uint32_t dst_base = (uint32_t)__cvta_generic_to_shared(&xs[bufi][0][0]);
        for (int idx = tid; idx < NCP; idx += 128) {
            int row = idx / CH;
            int jc = idx - row * CH;
            int s1g = s1_0 - 1 + row;
            bool v = (s1g >= 0) && (s1g < S1);
            int s1c = v ? s1g : 0;
            cp_async16(dst_base + (uint32_t)((row * XROW + 4 + jc * 4) * 4),
                       src_base + s1c * W + jc * 4, v);
        }
        cp_commit();
    };

    load_tile(0, 0);
    cp_wait0();
    __syncthreads();

    const int r = tid >> 4;
    const int cb = (tid & 15) * PX;

    ull acc2[4][PX];   // 4 oc-pairs x PX pixels
#pragma unroll
    for (int op = 0; op < 4; op++)
#pragma unroll
        for (int j = 0; j < PX; j++) acc2[op][j] = 0ull;

    int buf = 0;
    for (int c = 0; c < K; c++) {
        if (c + 1 < K) load_tile(c + 1, buf ^ 1);
        else cp_commit();

        const float* xr0 = &xs[buf][r + 0][cb + 3];
        const float* xr1 = &xs[buf][r + 1][cb + 3];
        const float* xr2 = &xs[buf][r + 2][cb + 3];
        const float* wc = &wsm[c * 72];

#pragma unroll
        for (int half = 0; half < PX / 4; half++) {
            ull nbb[3][6];
#pragma unroll
            for (int m = 0; m < 6; m++) {
                nbb[0][m] = pack2b(xr0[half * 4 + m]);
                nbb[1][m] = pack2b(xr1[half * 4 + m]);
                nbb[2][m] = pack2b(xr2[half * 4 + m]);
            }
#pragma unroll
            for (int op = 0; op < 4; op++) {
                ull w2[9];
#pragma unroll
                for (int k = 0; k < 9; k++)
                    w2[k] = *(const ull*)&wc[k * 8 + op * 2];
#pragma unroll
                for (int j = 0; j < 4; j++) {
                    ull* a = &acc2[op][half * 4 + j];
                    ffma2(*a, w2[0], nbb[0][j]);
                    ffma2(*a, w2[1], nbb[0][j + 1]);
                    ffma2(*a, w2[2], nbb[0][j + 2]);
                    ffma2(*a, w2[3], nbb[1][j]);
                    ffma2(*a, w2[4], nbb[1][j + 1]);
                    ffma2(*a, w2[5], nbb[1][j + 2]);
                    ffma2(*a, w2[6], nbb[2][j]);
                    ffma2(*a, w2[7], nbb[2][j + 1]);
                    ffma2(*a, w2[8], nbb[2][j + 2]);
                }
            }
        }
        cp_wait0();
        __syncthreads();
        buf ^= 1;
    }

    const int s1 = s1_0 + r;
    if (OUTV == 0) {
        const int obase = b * o_b + s1 * o_s1 + cb;
#pragma unroll
        for (int op = 0; op < 4; op++) {
            float b0 = bias[oc0 + 2 * op], b1 = bias[oc0 + 2 * op + 1];
            int e0 = obase + (oc0 + 2 * op) * o_oc;
            int e1 = obase + (oc0 + 2 * op + 1) * o_oc;
#pragma unroll
            for (int j4 = 0; j4 < PX; j4 += 4) {
                float2 p0 = unpack2(acc2[op][j4 + 0]);
                float2 p1 = unpack2(acc2[op][j4 + 1]);
                float2 p2 = unpack2(acc2[op][j4 + 2]);
                float2 p3 = unpack2(acc2[op][j4 + 3]);
                float4 v0 = make_float4(lrelu(p0.x + b0), lrelu(p1.x + b0),
                                        lrelu(p2.x + b0), lrelu(p3.x + b0));
                float4 v1 = make_float4(lrelu(p0.y + b1), lrelu(p1.y + b1),
                                        lrelu(p2.y + b1), lrelu(p3.y + b1));
                if (RES) {
                    float4 r0 = *(const float4*)&res[e0 + j4];
                    float4 r1 = *(const float4*)&res[e1 + j4];
                    v0.x += r0.x; v0.y += r0.y; v0.z += r0.z; v0.w += r0.w;
                    v1.x += r1.x; v1.y += r1.y; v1.z += r1.z; v1.w += r1.w;
                }
                *(float4*)&out[e0 + j4] = v0;
                *(float4*)&out[e1 + j4] = v1;
            }
        }
    } else {
        float bv[8];
#pragma unroll
        for (int oi = 0; oi < 8; oi++) bv[oi] = bias[oc0 + oi];
#pragma unroll
        for (int j = 0; j < PX; j++) {
            int e = b * o_b + (cb + j) * o_s2 + s1 * o_s1 + oc0;
            float2 p0 = unpack2(acc2[0][j]);
            float2 p1 = unpack2(acc2[1][j]);
            float2 p2 = unpack2(acc2[2][j]);
            float2 p3 = unpack2(acc2[3][j]);
            float4 v0 = make_float4(lrelu(p0.x + bv[0]), lrelu(p0.y + bv[1]),
                                    lrelu(p1.x + bv[2]), lrelu(p1.y + bv[3]));
            float4 v1 = make_float4(lrelu(p2.x + bv[4]), lrelu(p2.y + bv[5]),
                                    lrelu(p3.x + bv[6]), lrelu(p3.y + bv[7]));
            *(float4*)&out[e] = v0;
            *(float4*)&out[e + 4] = v1;
        }
    }
}

// ---------------- fused gate + folded down-conv + residual (f32x2) ----------------
__global__ __launch_bounds__(128)
void down_kernel_v3(const float* __restrict__ x, const float* __restrict__ xhw,
                    const float* __restrict__ xcw, const float* __restrict__ xhc,
                    const float* __restrict__ g,
                    const float* __restrict__ wd, const float* __restrict__ b_down,
                    float* __restrict__ mid)
{
    __shared__ __align__(16) float ws[4][64][16];
    const int tid = threadIdx.x;
    const int p4 = (blockIdx.x * 128 + tid) * 4;
    const int oc0 = blockIdx.y * 16;
    const int b = blockIdx.z;

    for (int idx = tid; idx < 4096; idx += 128) {
        int s = idx >> 10;
        int rem = idx & 1023;
        int c = rem >> 4, i = rem & 15;
        ws[s][c][i] = wd[s * 4096 + c * 64 + oc0 + i];
    }
    __syncthreads();

    ull acc2[8][4];
#pragma unroll
    for (int i = 0; i < 8; i++)
#pragma unroll
        for (int j = 0; j < 4; j++) acc2[i][j] = 0ull;

    const int xb = b * CHW_ + p4;
    const int gb = b * GBS_ + p4;
    for (int c = 0; c < 64; c++) {
        int off = xb + c * HW_;
        float4 a  = *(const float4*)&x[off];
        float4 h  = *(const float4*)&xhw[off];
        float4 cw = *(const float4*)&xcw[off];
        float4 hc = *(const float4*)&xhc[off];
        float4 g0 = *(const float4*)&g[gb + c * HW_];
        float4 g1 = *(const float4*)&g[gb + (64 + c) * HW_];
        float4 g2 = *(const float4*)&g[gb + (128 + c) * HW_];
        h.x *= g0.x; h.y *= g0.y; h.z *= g0.z; h.w *= g0.w;
        cw.x *= g1.x; cw.y *= g1.y; cw.z *= g1.z; cw.w *= g1.w;
        hc.x *= g2.x; hc.y *= g2.y; hc.z *= g2.z; hc.w *= g2.w;
        ull ap[4]  = { pack2b(a.x),  pack2b(a.y),  pack2b(a.z),  pack2b(a.w)  };
        ull hp[4]  = { pack2b(h.x),  pack2b(h.y),  pack2b(h.z),  pack2b(h.w)  };
        ull cp[4]  = { pack2b(cw.x), pack2b(cw.y), pack2b(cw.z), pack2b(cw.w) };
        ull hcp[4] = { pack2b(hc.x), pack2b(hc.y), pack2b(hc.z), pack2b(hc.w) };
#pragma unroll
        for (int op = 0; op < 8; op++) {
            ull w0 = *(const ull*)&ws[0][c][op * 2];
            ull w1 = *(const ull*)&ws[1][c][op * 2];
            ull w2 = *(const ull*)&ws[2][c][op * 2];
            ull w3 = *(const ull*)&ws[3][c][op * 2];
#pragma unroll
            for (int j = 0; j < 4; j++) {
                ffma2(acc2[op][j], w0, ap[j]);
                ffma2(acc2[op][j], w1, hp[j]);
                ffma2(acc2[op][j], w2, cp[j]);
                ffma2(acc2[op][j], w3, hcp[j]);
            }
        }
    }
#pragma unroll
    for (int op = 0; op < 8; op++) {
        int oc = oc0 + 2 * op;
        float b0 = b_down[oc], b1 = b_down[oc + 1];
        float4 x0 = *(const float4*)&x[b * CHW_ + oc * HW_ + p4];
        float4 x1 = *(const float4*)&x[b * CHW_ + (oc + 1) * HW_ + p4];
        float2 p0 = unpack2(acc2[op][0]), p1 = unpack2(acc2[op][1]);
        float2 p2 = unpack2(acc2[op][2]), p3 = unpack2(acc2[op][3]);
        float4 v0 = make_float4(p0.x + b0 + x0.x, p1.x + b0 + x0.y,
                                p2.x + b0 + x0.z, p3.x + b0 + x0.w);
        float4 v1 = make_float4(p0.y + b1 + x1.x, p1.y + b1 + x1.y,
                                p2.y + b1 + x1.z, p3.y + b1 + x1.w);
        *(float4*)&mid[b * CHW_ + oc * HW_ + p4] = v0;
        *(float4*)&mid[b * CHW_ + (oc + 1) * HW_ + p4] = v1;
    }
}

// ---------------- launch ----------------
extern "C" void kernel_launch(void* const* d_in, const int* in_sizes, int n_in,
                              void* d_out, int out_size)
{
    const float* x      = (const float*)d_in[0];
    const float* w_hwc  = (const float*)d_in[1];
    const float* b_hwc  = (const float*)d_in[2];
    const float* w_dw   = (const float*)d_in[3];
    const float* b_dw   = (const float*)d_in[4];
    const float* w_hw   = (const float*)d_in[5];
    const float* b_hw   = (const float*)d_in[6];
    const float* w_cw   = (const float*)d_in[7];
    const float* b_cw   = (const float*)d_in[8];
    const float* w_hc   = (const float*)d_in[9];
    const float* b_hc   = (const float*)d_in[10];
    const float* w_down = (const float*)d_in[11];
    const float* b_down = (const float*)d_in[12];
    const float* w_l1   = (const float*)d_in[13];
    const float* b_l1   = (const float*)d_in[14];
    const float* w_l2   = (const float*)d_in[15];
    const float* b_l2   = (const float*)d_in[16];
    float* out = (float*)d_out;

    float *t, *g, *xt1, *xt2, *xhw, *xcw, *xhc, *mid, *o1, *wd;
    cudaGetSymbolAddress((void**)&t,   d_t);
    cudaGetSymbolAddress((void**)&g,   d_g);
    cudaGetSymbolAddress((void**)&xt1, d_xt1);
    cudaGetSymbolAddress((void**)&xt2, d_xt2);
    cudaGetSymbolAddress((void**)&xhw, d_xhw);
    cudaGetSymbolAddress((void**)&xcw, d_xcw);
    cudaGetSymbolAddress((void**)&xhc, d_xhc);
    cudaGetSymbolAddress((void**)&mid, d_mid);
    cudaGetSymbolAddress((void**)&o1,  d_o1);
    cudaGetSymbolAddress((void**)&wd,  d_wd);

    prep_wd_kernel<<<64, 256>>>(w_down, wd);
    t1_kernel<<<8192, 256>>>(x, xt1);
    t2_kernel<<<dim3(4, 2, 1024), dim3(32, 8)>>>(x, xt2);

    conv1x1_kernel<<<dim3(32, 12, 8), 128>>>(x, w_hwc, b_hwc, t);
    dwconv_kernel<<<dim3(32, 192, 8), 128>>>(t, w_dw, b_dw, g);

    // x_hw: standard conv (64->64)
    conv3x3_v3<64, 128, 128, 8, 0, 0><<<dim3(16, 8, 8), 128>>>(
        x, w_hw, b_hw, xhw, nullptr, HW_, 128, 1, CHW_);

    // x_cw: conv on xt1 [b][h][c][w]
    conv3x3_v3<128, 64, 128, 8, 0, 0><<<dim3(8, 16, 8), 128>>>(
        xt1, w_cw, b_cw, xcw, nullptr, 128, HW_, 1, CHW_);

    // x_hc: conv on xt2 [b][w][h][c]
    conv3x3_v3<128, 128, 64, 4, 1, 0><<<dim3(16, 16, 8), 128>>>(
        xt2, w_hc, b_hc, xhc, nullptr, 1, 128, HW_, CHW_);

    // fused: gates * branches -> folded down-conv -> + x
    down_kernel_v3<<<dim3(32, 4, 8), 128>>>(x, xhw, xcw, xhc, g, wd, b_down, mid);

    // l1
    conv3x3_v3<64, 128, 128, 8, 0, 0><<<dim3(16, 8, 8), 128>>>(
        mid, w_l1, b_l1, o1, nullptr, HW_, 128, 1, CHW_);
    // l2 + residual
    conv3x3_v3<64, 128, 128, 8, 0, 1><<<dim3(16, 8, 8), 128>>>(
        o1, w_l2, b_l2, out, x, HW_, 128, 1, CHW_);
}

// round 4
// speedup vs baseline: 2.4503x; 1.0358x over previous
#include <cuda_runtime.h>
#include <cstdint>

// B=8, C=64, T=128
#define HW_   16384
#define CHW_  1048576
#define GBS_  3145728

typedef unsigned long long ull;

// ---------------- scratch ----------------
__device__ float d_t  [25165824];  // [8,192,128,128] conv1x1 out
__device__ float d_g  [25165824];  // [8,192,128,128] gates
__device__ float d_xt1[8388608];   // x.transpose(0,2,1,3): [b][h][c][w]
__device__ float d_xt2[8388608];   // x.transpose(0,3,2,1): [b][w][h][c]
__device__ float d_xhw[8388608];
__device__ float d_xcw[8388608];
__device__ float d_xhc[8388608];
__device__ float d_mid[8388608];
__device__ float d_o1 [8388608];
__device__ float d_wd [16384];     // folded down weights [4][64(c)][64(o)]

__device__ __forceinline__ float lrelu(float v) { return v > 0.f ? v : 0.1f * v; }

__device__ __forceinline__ void cp_async16(uint32_t dst, const float* src, bool valid) {
    int sz = valid ? 16 : 0;
    asm volatile("cp.async.cg.shared.global [%0], [%1], 16, %2;\n"
                 :: "r"(dst), "l"(src), "r"(sz));
}
__device__ __forceinline__ void cp_commit() { asm volatile("cp.async.commit_group;\n"); }
__device__ __forceinline__ void cp_wait0()  { asm volatile("cp.async.wait_group 0;\n"); }

// ---------------- f32x2 packed helpers ----------------
__device__ __forceinline__ ull pack2b(float v) {
    ull r; asm("mov.b64 %0, {%1,%1};" : "=l"(r) : "f"(v)); return r;
}
__device__ __forceinline__ float2 unpack2(ull v) {
    float2 r; asm("mov.b64 {%0,%1}, %2;" : "=f"(r.x), "=f"(r.y) : "l"(v)); return r;
}
__device__ __forceinline__ void ffma2(ull& d, ull a, ull b) {
    asm("fma.rn.f32x2 %0, %1, %2, %0;" : "+l"(d) : "l"(a), "l"(b));
}

// ---------------- prep: fold w_down ----------------
__global__ void prep_wd_kernel(const float* __restrict__ w_down, float* __restrict__ wd)
{
    int idx = blockIdx.x * 256 + threadIdx.x;
    if (idx >= 16384) return;
    int s = idx >> 12;
    int rem = idx & 4095;
    int c = rem >> 6;
    int o = rem & 63;
    auto W = [&](int i, int ky, int kx) { return w_down[((o * 128 + i) * 2 + ky) * 2 + kx]; };
    float v = 0.f;
    if (s == 0) v = W(2 * c, 0, 0) + W(2 * c + 1, 1, 1);
    else if (s == 1) v = W(2 * c, 0, 1) + W(2 * c + 1, 1, 0);
    else if (s == 2) v = W(2 * c, 1, 0) + W(2 * c + 1, 0, 1);
    else v = W(2 * c, 1, 1) + W(2 * c + 1, 0, 0);
    wd[s * 4096 + c * 64 + o] = v;
}

// ---------------- transposes ----------------
__global__ __launch_bounds__(256)
void t1_kernel(const float* __restrict__ x, float* __restrict__ o)
{
    int i = blockIdx.x * 256 + threadIdx.x;
    int w4 = i & 31; int rest = i >> 5;
    int h = rest & 127; rest >>= 7;
    int c = rest & 63; int b = rest >> 6;
    float4 v = *(const float4*)&x[((b * 64 + c) * 128 + h) * 128 + w4 * 4];
    *(float4*)&o[((b * 128 + h) * 64 + c) * 128 + w4 * 4] = v;
}

__global__ __launch_bounds__(256)
void t2_kernel(const float* __restrict__ x, float* __restrict__ o)
{
    __shared__ float tile[32][33];
    int tx = threadIdx.x, ty = threadIdx.y;
    int w0 = blockIdx.x * 32;
    int c0 = blockIdx.y * 32;
    int bh = blockIdx.z;
    int b = bh >> 7, h = bh & 127;
    int xb = b * CHW_ + h * 128;
#pragma unroll
    for (int i = 0; i < 4; i++)
        tile[ty + 8 * i][tx] = x[xb + (c0 + ty + 8 * i) * HW_ + w0 + tx];
    __syncthreads();
    int ob = b * CHW_ + h * 64;
#pragma unroll
    for (int i = 0; i < 4; i++)
        o[ob + (w0 + ty + 8 * i) * 8192 + c0 + tx] = tile[tx][ty + 8 * i];
}

// ---------------- conv1x1 (f32x2, prefetch) ----------------
__global__ __launch_bounds__(128)
void conv1x1_kernel(const float* __restrict__ x, const float* __restrict__ w,
                    const float* __restrict__ bias, float* __restrict__ t)
{
    __shared__ __align__(16) float ws[64][16];
    const int tid = threadIdx.x;
    const int p4 = (blockIdx.x * 128 + tid) * 4;
    const int oc0 = blockIdx.y * 16;
    const int b = blockIdx.z;

    for (int idx = tid; idx < 1024; idx += 128) {
        int c = idx >> 4, i = idx & 15;
        ws[c][i] = w[(oc0 + i) * 64 + c];
    }
    __syncthreads();

    ull acc2[8][4];
#pragma unroll
    for (int i = 0; i < 8; i++)
#pragma unroll
        for (int j = 0; j < 4; j++) acc2[i][j] = 0ull;

    const int xb = b * CHW_ + p4;
    float4 xv = *(const float4*)&x[xb];
    for (int c = 0; c < 64; c++) {
        float4 nxt;
        if (c + 1 < 64) nxt = *(const float4*)&x[xb + (c + 1) * HW_];
        ull xp[4] = { pack2b(xv.x), pack2b(xv.y), pack2b(xv.z), pack2b(xv.w) };
#pragma unroll
        for (int op = 0; op < 8; op++) {
            ull w2 = *(const ull*)&ws[c][op * 2];
            ffma2(acc2[op][0], w2, xp[0]);
            ffma2(acc2[op][1], w2, xp[1]);
            ffma2(acc2[op][2], w2, xp[2]);
            ffma2(acc2[op][3], w2, xp[3]);
        }
        xv = nxt;
    }
#pragma unroll
    for (int op = 0; op < 8; op++) {
        float b0 = bias[oc0 + 2 * op], b1 = bias[oc0 + 2 * op + 1];
        float2 p0 = unpack2(acc2[op][0]), p1 = unpack2(acc2[op][1]);
        float2 p2 = unpack2(acc2[op][2]), p3 = unpack2(acc2[op][3]);
        float4 v0 = make_float4(p0.x + b0, p1.x + b0, p2.x + b0, p3.x + b0);
        float4 v1 = make_float4(p0.y + b1, p1.y + b1, p2.y + b1, p3.y + b1);
        *(float4*)&t[b * GBS_ + (oc0 + 2 * op) * HW_ + p4] = v0;
        *(float4*)&t[b * GBS_ + (oc0 + 2 * op + 1) * HW_ + p4] = v1;
    }
}

// ---------------- depthwise 3x3 ----------------
__global__ __launch_bounds__(128)
void dwconv_kernel(const float* __restrict__ t, const float* __restrict__ w_dw,
                   const float* __restrict__ b_dw, float* __restrict__ g)
{
    __shared__ float xs[10][68];
    const int tid = threadIdx.x;
    const int s1t = blockIdx.x & 15, s2t = blockIdx.x >> 4;
    const int s1_0 = s1t * 8, s2_0 = s2t * 64;
    const int og = blockIdx.y, b = blockIdx.z;
    const int base = b * GBS_ + og * HW_;

    for (int idx = tid; idx < 660; idx += 128) {
        int row = idx / 66, col = idx - row * 66;
        int s1g = s1_0 - 1 + row;
        int s2g = s2_0 - 1 + col;
        float v = 0.f;
        if (s1g >= 0 && s1g < 128 && s2g >= 0 && s2g < 128)
            v = t[base + s1g * 128 + s2g];
        xs[row][col] = v;
    }
    __syncthreads();

    float w[9];
#pragma unroll
    for (int k = 0; k < 9; k++) w[k] = w_dw[og * 9 + k];
    float bb = b_dw[og];

    const int r = tid >> 4, cb = (tid & 15) * 4;
    float4 v;
    float* vp = &v.x;
#pragma unroll
    for (int j = 0; j < 4; j++) {
        float s = bb;
#pragma unroll
        for (int dr = 0; dr < 3; dr++)
#pragma unroll
            for (int dc = 0; dc < 3; dc++)
                s += w[dr * 3 + dc] * xs[r + dr][cb + j + dc];
        vp[j] = s;
    }
    *(float4*)&g[base + (s1_0 + r) * 128 + s2_0 + cb] = v;
}

// ---------------- pipelined 3x3 conv v4 (f32x2, oc-pair lanes, row-major channel body) ----------------
// input x: [b][K][S1][W]; out addr: b*o_b + oc*o_oc + s1*o_s1 + s2*o_s2
// PX pixels per thread, ROWS tile rows (threads/row = 128/ROWS must equal W/PX).
// OUTV 0: o_s2==1 (vectorize px). OUTV 1: o_oc==1 (vectorize oc). RES: add res.
template<int K, int S1, int W, int PX, int ROWS, int OUTV, int RES>
__global__ __launch_bounds__(128)
void conv3x3_v4(const float* __restrict__ x, const float* __restrict__ wgt,
                const float* __restrict__ bias, float* __restrict__ out,
                const float* __restrict__ res,
                int o_oc, int o_s1, int o_s2, int o_b)
{
    constexpr int TPR = W / PX;           // threads per row
    static_assert(TPR * ROWS == 128, "layout");
    constexpr int HR = ROWS + 2;
    constexpr int XROW = W + 8;
    constexpr int CH = W / 4;
    constexpr int NCP = HR * CH;
    __shared__ __align__(16) float xs[2][HR][XROW];
    __shared__ __align__(16) float wsm[K * 72];   // [c][k 0..8][oi 0..7]

    const int tid = threadIdx.x;
    const int s1_0 = blockIdx.x * ROWS;
    const int oc0 = blockIdx.y * 8;
    const int b = blockIdx.z;
    const int xb = b * (K * S1 * W);

    if (tid < 4 * HR) {
        int bufi = tid & 1;
        int rest = tid >> 1;
        int row = rest % HR;
        int side = rest / HR;
        xs[bufi][row][side ? (W + 4) : 3] = 0.f;
    }

    for (int idx = tid; idx < K * 72; idx += 128) {
        int c = idx / 72;
        int rem = idx - c * 72;
        int k = rem >> 3, oi = rem & 7;
        wsm[idx] = wgt[((oc0 + oi) * K + c) * 9 + k];
    }

    auto load_tile = [&](int c, int bufi) {
        const float* src_base = x + xb + c * (S1 * W);
        uint32_t dst_base = (uint32_t)__cvta_generic_to_shared(&xs[bufi][0][0]);
        for (int idx = tid; idx < NCP; idx += 128) {
            int row = idx / CH;
            int jc = idx - row * CH;
            int s1g = s1_0 - 1 + row;
            bool v = (s1g >= 0) && (s1g < S1);
            int s1c = v ? s1g : 0;
            cp_async16(dst_base + (uint32_t)((row * XROW + 4 + jc * 4) * 4),
                       src_base + s1c * W + jc * 4, v);
        }
        cp_commit();
    };

    load_tile(0, 0);
    cp_wait0();
    __syncthreads();

    const int r = tid / TPR;
    const int cb = (tid % TPR) * PX;

    ull acc2[4][PX];
#pragma unroll
    for (int op = 0; op < 4; op++)
#pragma unroll
        for (int j = 0; j < PX; j++) acc2[op][j] = 0ull;

    int buf = 0;
    for (int c = 0; c < K; c++) {
        if (c + 1 < K) load_tile(c + 1, buf ^ 1);
        else cp_commit();

        const float* wc = &wsm[c * 72];
#pragma unroll
        for (int dr = 0; dr < 3; dr++) {
            const float* xr = &xs[buf][r + dr][cb + 3];
            ull nbp[PX + 2];
#pragma unroll
            for (int m = 0; m < PX + 2; m++) nbp[m] = pack2b(xr[m]);
#pragma unroll
            for (int op = 0; op < 4; op++) {
                ull wa = *(const ull*)&wc[(dr * 3 + 0) * 8 + op * 2];
                ull wb = *(const ull*)&wc[(dr * 3 + 1) * 8 + op * 2];
                ull wq = *(const ull*)&wc[(dr * 3 + 2) * 8 + op * 2];
#pragma unroll
                for (int j = 0; j < PX; j++) {
                    ffma2(acc2[op][j], wa, nbp[j]);
                    ffma2(acc2[op][j], wb, nbp[j + 1]);
                    ffma2(acc2[op][j], wq, nbp[j + 2]);
                }
            }
        }
        cp_wait0();
        __syncthreads();
        buf ^= 1;
    }

    const int s1 = s1_0 + r;
    if (OUTV == 0) {
        const int obase = b * o_b + s1 * o_s1 + cb;
#pragma unroll
        for (int op = 0; op < 4; op++) {
            float b0 = bias[oc0 + 2 * op], b1 = bias[oc0 + 2 * op + 1];
            int e0 = obase + (oc0 + 2 * op) * o_oc;
            int e1 = obase + (oc0 + 2 * op + 1) * o_oc;
#pragma unroll
            for (int j4 = 0; j4 < PX; j4 += 4) {
                float2 p0 = unpack2(acc2[op][j4 + 0]);
                float2 p1 = unpack2(acc2[op][j4 + 1]);
                float2 p2 = unpack2(acc2[op][j4 + 2]);
                float2 p3 = unpack2(acc2[op][j4 + 3]);
                float4 v0 = make_float4(lrelu(p0.x + b0), lrelu(p1.x + b0),
                                        lrelu(p2.x + b0), lrelu(p3.x + b0));
                float4 v1 = make_float4(lrelu(p0.y + b1), lrelu(p1.y + b1),
                                        lrelu(p2.y + b1), lrelu(p3.y + b1));
                if (RES) {
                    float4 r0 = *(const float4*)&res[e0 + j4];
                    float4 r1 = *(const float4*)&res[e1 + j4];
                    v0.x += r0.x; v0.y += r0.y; v0.z += r0.z; v0.w += r0.w;
                    v1.x += r1.x; v1.y += r1.y; v1.z += r1.z; v1.w += r1.w;
                }
                *(float4*)&out[e0 + j4] = v0;
                *(float4*)&out[e1 + j4] = v1;
            }
        }
    } else {
        float bv[8];
#pragma unroll
        for (int oi = 0; oi < 8; oi++) bv[oi] = bias[oc0 + oi];
#pragma unroll
        for (int j = 0; j < PX; j++) {
            int e = b * o_b + (cb + j) * o_s2 + s1 * o_s1 + oc0;
            float2 p0 = unpack2(acc2[0][j]);
            float2 p1 = unpack2(acc2[1][j]);
            float2 p2 = unpack2(acc2[2][j]);
            float2 p3 = unpack2(acc2[3][j]);
            float4 v0 = make_float4(lrelu(p0.x + bv[0]), lrelu(p0.y + bv[1]),
                                    lrelu(p1.x + bv[2]), lrelu(p1.y + bv[3]));
            float4 v1 = make_float4(lrelu(p2.x + bv[4]), lrelu(p2.y + bv[5]),
                                    lrelu(p3.x + bv[6]), lrelu(p3.y + bv[7]));
            *(float4*)&out[e] = v0;
            *(float4*)&out[e + 4] = v1;
        }
    }
}

// ---------------- fused gate + folded down-conv + residual (f32x2) ----------------
__global__ __launch_bounds__(128)
void down_kernel_v3(const float* __restrict__ x, const float* __restrict__ xhw,
                    const float* __restrict__ xcw, const float* __restrict__ xhc,
                    const float* __restrict__ g,
                    const float* __restrict__ wd, const float* __restrict__ b_down,
                    float* __restrict__ mid)
{
    __shared__ __align__(16) float ws[4][64][16];
    const int tid = threadIdx.x;
    const int p4 = (blockIdx.x * 128 + tid) * 4;
    const int oc0 = blockIdx.y * 16;
    const int b = blockIdx.z;

    for (int idx = tid; idx < 4096; idx += 128) {
        int s = idx >> 10;
        int rem = idx & 1023;
        int c = rem >> 4, i = rem & 15;
        ws[s][c][i] = wd[s * 4096 + c * 64 + oc0 + i];
    }
    __syncthreads();

    ull acc2[8][4];
#pragma unroll
    for (int i = 0; i < 8; i++)
#pragma unroll
        for (int j = 0; j < 4; j++) acc2[i][j] = 0ull;

    const int xb = b * CHW_ + p4;
    const int gb = b * GBS_ + p4;
    for (int c = 0; c < 64; c++) {
        int off = xb + c * HW_;
        float4 a  = *(const float4*)&x[off];
        float4 h  = *(const float4*)&xhw[off];
        float4 cw = *(const float4*)&xcw[off];
        float4 hc = *(const float4*)&xhc[off];
        float4 g0 = *(const float4*)&g[gb + c * HW_];
        float4 g1 = *(const float4*)&g[gb + (64 + c) * HW_];
        float4 g2 = *(const float4*)&g[gb + (128 + c) * HW_];
        h.x *= g0.x; h.y *= g0.y; h.z *= g0.z; h.w *= g0.w;
        cw.x *= g1.x; cw.y *= g1.y; cw.z *= g1.z; cw.w *= g1.w;
        hc.x *= g2.x; hc.y *= g2.y; hc.z *= g2.z; hc.w *= g2.w;
        ull ap[4]  = { pack2b(a.x),  pack2b(a.y),  pack2b(a.z),  pack2b(a.w)  };
        ull hp[4]  = { pack2b(h.x),  pack2b(h.y),  pack2b(h.z),  pack2b(h.w)  };
        ull cp[4]  = { pack2b(cw.x), pack2b(cw.y), pack2b(cw.z), pack2b(cw.w) };
        ull hcp[4] = { pack2b(hc.x), pack2b(hc.y), pack2b(hc.z), pack2b(hc.w) };
#pragma unroll
        for (int op = 0; op < 8; op++) {
            ull w0 = *(const ull*)&ws[0][c][op * 2];
            ull w1 = *(const ull*)&ws[1][c][op * 2];
            ull w2 = *(const ull*)&ws[2][c][op * 2];
            ull w3 = *(const ull*)&ws[3][c][op * 2];
#pragma unroll
            for (int j = 0; j < 4; j++) {
                ffma2(acc2[op][j], w0, ap[j]);
                ffma2(acc2[op][j], w1, hp[j]);
                ffma2(acc2[op][j], w2, cp[j]);
                ffma2(acc2[op][j], w3, hcp[j]);
            }
        }
    }
#pragma unroll
    for (int op = 0; op < 8; op++) {
        int oc = oc0 + 2 * op;
        float b0 = b_down[oc], b1 = b_down[oc + 1];
        float4 x0 = *(const float4*)&x[b * CHW_ + oc * HW_ + p4];
        float4 x1 = *(const float4*)&x[b * CHW_ + (oc + 1) * HW_ + p4];
        float2 p0 = unpack2(acc2[op][0]), p1 = unpack2(acc2[op][1]);
        float2 p2 = unpack2(acc2[op][2]), p3 = unpack2(acc2[op][3]);
        float4 v0 = make_float4(p0.x + b0 + x0.x, p1.x + b0 + x0.y,
                                p2.x + b0 + x0.z, p3.x + b0 + x0.w);
        float4 v1 = make_float4(p0.y + b1 + x1.x, p1.y + b1 + x1.y,
                                p2.y + b1 + x1.z, p3.y + b1 + x1.w);
        *(float4*)&mid[b * CHW_ + oc * HW_ + p4] = v0;
        *(float4*)&mid[b * CHW_ + (oc + 1) * HW_ + p4] = v1;
    }
}

// ---------------- launch ----------------
extern "C" void kernel_launch(void* const* d_in, const int* in_sizes, int n_in,
                              void* d_out, int out_size)
{
    const float* x      = (const float*)d_in[0];
    const float* w_hwc  = (const float*)d_in[1];
    const float* b_hwc  = (const float*)d_in[2];
    const float* w_dw   = (const float*)d_in[3];
    const float* b_dw   = (const float*)d_in[4];
    const float* w_hw   = (const float*)d_in[5];
    const float* b_hw   = (const float*)d_in[6];
    const float* w_cw   = (const float*)d_in[7];
    const float* b_cw   = (const float*)d_in[8];
    const float* w_hc   = (const float*)d_in[9];
    const float* b_hc   = (const float*)d_in[10];
    const float* w_down = (const float*)d_in[11];
    const float* b_down = (const float*)d_in[12];
    const float* w_l1   = (const float*)d_in[13];
    const float* b_l1   = (const float*)d_in[14];
    const float* w_l2   = (const float*)d_in[15];
    const float* b_l2   = (const float*)d_in[16];
    float* out = (float*)d_out;

    float *t, *g, *xt1, *xt2, *xhw, *xcw, *xhc, *mid, *o1, *wd;
    cudaGetSymbolAddress((void**)&t,   d_t);
    cudaGetSymbolAddress((void**)&g,   d_g);
    cudaGetSymbolAddress((void**)&xt1, d_xt1);
    cudaGetSymbolAddress((void**)&xt2, d_xt2);
    cudaGetSymbolAddress((void**)&xhw, d_xhw);
    cudaGetSymbolAddress((void**)&xcw, d_xcw);
    cudaGetSymbolAddress((void**)&xhc, d_xhc);
    cudaGetSymbolAddress((void**)&mid, d_mid);
    cudaGetSymbolAddress((void**)&o1,  d_o1);
    cudaGetSymbolAddress((void**)&wd,  d_wd);

    prep_wd_kernel<<<64, 256>>>(w_down, wd);
    t1_kernel<<<8192, 256>>>(x, xt1);
    t2_kernel<<<dim3(4, 2, 1024), dim3(32, 8)>>>(x, xt2);

    conv1x1_kernel<<<dim3(32, 12, 8), 128>>>(x, w_hwc, b_hwc, t);
    dwconv_kernel<<<dim3(32, 192, 8), 128>>>(t, w_dw, b_dw, g);

    // x_hw: standard conv (64->64), tile 8x128
    conv3x3_v4<64, 128, 128, 8, 8, 0, 0><<<dim3(16, 8, 8), 128>>>(
        x, w_hw, b_hw, xhw, nullptr, HW_, 128, 1, CHW_);

    // x_cw: conv on xt1 [b][h][c][w]: tile 8x128 over (c,w)
    conv3x3_v4<128, 64, 128, 8, 8, 0, 0><<<dim3(8, 16, 8), 128>>>(
        xt1, w_cw, b_cw, xcw, nullptr, 128, HW_, 1, CHW_);

    // x_hc: conv on xt2 [b][w][h][c]: tile 16x64 over (h,c)
    conv3x3_v4<128, 128, 64, 8, 16, 1, 0><<<dim3(8, 16, 8), 128>>>(
        xt2, w_hc, b_hc, xhc, nullptr, 1, 128, HW_, CHW_);

    // fused: gates * branches -> folded down-conv -> + x
    down_kernel_v3<<<dim3(32, 4, 8), 128>>>(x, xhw, xcw, xhc, g, wd, b_down, mid);

    // l1
    conv3x3_v4<64, 128, 128, 8, 8, 0, 0><<<dim3(16, 8, 8), 128>>>(
        mid, w_l1, b_l1, o1, nullptr, HW_, 128, 1, CHW_);
    // l2 + residual
    conv3x3_v4<64, 128, 128, 8, 8, 0, 1><<<dim3(16, 8, 8), 128>>>(
        o1, w_l2, b_l2, out, x, HW_, 128, 1, CHW_);
}

// round 5
// speedup vs baseline: 2.4529x; 1.0011x over previous
#include <cuda_runtime.h>
#include <cstdint>

// B=8, C=64, T=128
#define HW_   16384
#define CHW_  1048576
#define GBS_  3145728

typedef unsigned long long ull;

// ---------------- scratch ----------------
__device__ float d_t  [25165824];  // [8,192,128,128] conv1x1 out
__device__ float d_g  [25165824];  // [8,192,128,128] gates
__device__ float d_xt1[8388608];   // x.transpose(0,2,1,3): [b][h][c][w]
__device__ float d_xt2[8388608];   // x.transpose(0,3,2,1): [b][w][h][c]
__device__ float d_xhw[8388608];
__device__ float d_xcw[8388608];
__device__ float d_xhc[8388608];
__device__ float d_mid[8388608];
__device__ float d_o1 [8388608];
__device__ float d_wd [16384];     // folded down weights [4][64(c)][64(o)]

__device__ __forceinline__ float lrelu(float v) { return v > 0.f ? v : 0.1f * v; }

__device__ __forceinline__ void cp_async16(uint32_t dst, const float* src, bool valid) {
    int sz = valid ? 16 : 0;
    asm volatile("cp.async.cg.shared.global [%0], [%1], 16, %2;\n"
                 :: "r"(dst), "l"(src), "r"(sz));
}
__device__ __forceinline__ void cp_commit() { asm volatile("cp.async.commit_group;\n"); }
__device__ __forceinline__ void cp_wait0()  { asm volatile("cp.async.wait_group 0;\n"); }

// ---------------- f32x2 packed helpers ----------------
__device__ __forceinline__ ull pack2b(float v) {
    ull r; asm("mov.b64 %0, {%1,%1};" : "=l"(r) : "f"(v)); return r;
}
__device__ __forceinline__ float2 unpack2(ull v) {
    float2 r; asm("mov.b64 {%0,%1}, %2;" : "=f"(r.x), "=f"(r.y) : "l"(v)); return r;
}
__device__ __forceinline__ void ffma2(ull& d, ull a, ull b) {
    asm("fma.rn.f32x2 %0, %1, %2, %0;" : "+l"(d) : "l"(a), "l"(b));
}

// ---------------- prep: fold w_down ----------------
__global__ void prep_wd_kernel(const float* __restrict__ w_down, float* __restrict__ wd)
{
    int idx = blockIdx.x * 256 + threadIdx.x;
    if (idx >= 16384) return;
    int s = idx >> 12;
    int rem = idx & 4095;
    int c = rem >> 6;
    int o = rem & 63;
    auto W = [&](int i, int ky, int kx) { return w_down[((o * 128 + i) * 2 + ky) * 2 + kx]; };
    float v = 0.f;
    if (s == 0) v = W(2 * c, 0, 0) + W(2 * c + 1, 1, 1);
    else if (s == 1) v = W(2 * c, 0, 1) + W(2 * c + 1, 1, 0);
    else if (s == 2) v = W(2 * c, 1, 0) + W(2 * c + 1, 0, 1);
    else v = W(2 * c, 1, 1) + W(2 * c + 1, 0, 0);
    wd[s * 4096 + c * 64 + o] = v;
}

// ---------------- transposes ----------------
__global__ __launch_bounds__(256)
void t1_kernel(const float* __restrict__ x, float* __restrict__ o)
{
    int i = blockIdx.x * 256 + threadIdx.x;
    int w4 = i & 31; int rest = i >> 5;
    int h = rest & 127; rest >>= 7;
    int c = rest & 63; int b = rest >> 6;
    float4 v = *(const float4*)&x[((b * 64 + c) * 128 + h) * 128 + w4 * 4];
    *(float4*)&o[((b * 128 + h) * 64 + c) * 128 + w4 * 4] = v;
}

__global__ __launch_bounds__(256)
void t2_kernel(const float* __restrict__ x, float* __restrict__ o)
{
    __shared__ float tile[32][33];
    int tx = threadIdx.x, ty = threadIdx.y;
    int w0 = blockIdx.x * 32;
    int c0 = blockIdx.y * 32;
    int bh = blockIdx.z;
    int b = bh >> 7, h = bh & 127;
    int xb = b * CHW_ + h * 128;
#pragma unroll
    for (int i = 0; i < 4; i++)
        tile[ty + 8 * i][tx] = x[xb + (c0 + ty + 8 * i) * HW_ + w0 + tx];
    __syncthreads();
    int ob = b * CHW_ + h * 64;
#pragma unroll
    for (int i = 0; i < 4; i++)
        o[ob + (w0 + ty + 8 * i) * 8192 + c0 + tx] = tile[tx][ty + 8 * i];
}

// ---------------- conv1x1 (f32x2, prefetch) ----------------
__global__ __launch_bounds__(128)
void conv1x1_kernel(const float* __restrict__ x, const float* __restrict__ w,
                    const float* __restrict__ bias, float* __restrict__ t)
{
    __shared__ __align__(16) float ws[64][16];
    const int tid = threadIdx.x;
    const int p4 = (blockIdx.x * 128 + tid) * 4;
    const int oc0 = blockIdx.y * 16;
    const int b = blockIdx.z;

    for (int idx = tid; idx < 1024; idx += 128) {
        int c = idx >> 4, i = idx & 15;
        ws[c][i] = w[(oc0 + i) * 64 + c];
    }
    __syncthreads();

    ull acc2[8][4];
#pragma unroll
    for (int i = 0; i < 8; i++)
#pragma unroll
        for (int j = 0; j < 4; j++) acc2[i][j] = 0ull;

    const int xb = b * CHW_ + p4;
    float4 xv = *(const float4*)&x[xb];
    for (int c = 0; c < 64; c++) {
        float4 nxt;
        if (c + 1 < 64) nxt = *(const float4*)&x[xb + (c + 1) * HW_];
        ull xp[4] = { pack2b(xv.x), pack2b(xv.y), pack2b(xv.z), pack2b(xv.w) };
#pragma unroll
        for (int op = 0; op < 8; op++) {
            ull w2 = *(const ull*)&ws[c][op * 2];
            ffma2(acc2[op][0], w2, xp[0]);
            ffma2(acc2[op][1], w2, xp[1]);
            ffma2(acc2[op][2], w2, xp[2]);
            ffma2(acc2[op][3], w2, xp[3]);
        }
        xv = nxt;
    }
#pragma unroll
    for (int op = 0; op < 8; op++) {
        float b0 = bias[oc0 + 2 * op], b1 = bias[oc0 + 2 * op + 1];
        float2 p0 = unpack2(acc2[op][0]), p1 = unpack2(acc2[op][1]);
        float2 p2 = unpack2(acc2[op][2]), p3 = unpack2(acc2[op][3]);
        float4 v0 = make_float4(p0.x + b0, p1.x + b0, p2.x + b0, p3.x + b0);
        float4 v1 = make_float4(p0.y + b1, p1.y + b1, p2.y + b1, p3.y + b1);
        *(float4*)&t[b * GBS_ + (oc0 + 2 * op) * HW_ + p4] = v0;
        *(float4*)&t[b * GBS_ + (oc0 + 2 * op + 1) * HW_ + p4] = v1;
    }
}

// ---------------- depthwise 3x3 ----------------
__global__ __launch_bounds__(128)
void dwconv_kernel(const float* __restrict__ t, const float* __restrict__ w_dw,
                   const float* __restrict__ b_dw, float* __restrict__ g)
{
    __shared__ float xs[10][68];
    const int tid = threadIdx.x;
    const int s1t = blockIdx.x & 15, s2t = blockIdx.x >> 4;
    const int s1_0 = s1t * 8, s2_0 = s2t * 64;
    const int og = blockIdx.y, b = blockIdx.z;
    const int base = b * GBS_ + og * HW_;

    for (int idx = tid; idx < 660; idx += 128) {
        int row = idx / 66, col = idx - row * 66;
        int s1g = s1_0 - 1 + row;
        int s2g = s2_0 - 1 + col;
        float v = 0.f;
        if (s1g >= 0 && s1g < 128 && s2g >= 0 && s2g < 128)
            v = t[base + s1g * 128 + s2g];
        xs[row][col] = v;
    }
    __syncthreads();

    float w[9];
#pragma unroll
    for (int k = 0; k < 9; k++) w[k] = w_dw[og * 9 + k];
    float bb = b_dw[og];

    const int r = tid >> 4, cb = (tid & 15) * 4;
    float4 v;
    float* vp = &v.x;
#pragma unroll
    for (int j = 0; j < 4; j++) {
        float s = bb;
#pragma unroll
        for (int dr = 0; dr < 3; dr++)
#pragma unroll
            for (int dc = 0; dc < 3; dc++)
                s += w[dr * 3 + dc] * xs[r + dr][cb + j + dc];
        vp[j] = s;
    }
    *(float4*)&g[base + (s1_0 + r) * 128 + s2_0 + cb] = v;
}

// ---------------- pipelined 3x3 conv v4 (f32x2, oc-pair lanes, row-major channel body) ----------------
// input x: [b][K][S1][W]; out addr: b*o_b + oc*o_oc + s1*o_s1 + s2*o_s2
// PX pixels per thread, ROWS tile rows (threads/row = 128/ROWS must equal W/PX).
// OUTV 0: o_s2==1 (vectorize px). OUTV 1: o_oc==1 (vectorize oc). RES: add res.
template<int K, int S1, int W, int PX, int ROWS, int OUTV, int RES>
__global__ __launch_bounds__(128)
void conv3x3_v4(const float* __restrict__ x, const float* __restrict__ wgt,
                const float* __restrict__ bias, float* __restrict__ out,
                const float* __restrict__ res,
                int o_oc, int o_s1, int o_s2, int o_b)
{
    constexpr int TPR = W / PX;           // threads per row
    static_assert(TPR * ROWS == 128, "layout");
    constexpr int HR = ROWS + 2;
    constexpr int XROW = W + 8;
    constexpr int CH = W / 4;
    constexpr int NCP = HR * CH;
    __shared__ __align__(16) float xs[2][HR][XROW];
    __shared__ __align__(16) float wsm[K * 72];   // [c][k 0..8][oi 0..7]

    const int tid = threadIdx.x;
    const int s1_0 = blockIdx.x * ROWS;
    const int oc0 = blockIdx.y * 8;
    const int b = blockIdx.z;
    const int xb = b * (K * S1 * W);

    if (tid < 4 * HR) {
        int bufi = tid & 1;
        int rest = tid >> 1;
        int row = rest % HR;
        int side = rest / HR;
        xs[bufi][row][side ? (W + 4) : 3] = 0.f;
    }

    for (int idx = tid; idx < K * 72; idx += 128) {
        int c = idx / 72;
        int rem = idx - c * 72;
        int k = rem >> 3, oi = rem & 7;
        wsm[idx] = wgt[((oc0 + oi) * K + c) * 9 + k];
    }

    auto load_tile = [&](int c, int bufi) {
        const float* src_base = x + xb + c * (S1 * W);
        uint32_t dst_base = (uint32_t)__cvta_generic_to_shared(&xs[bufi][0][0]);
        for (int idx = tid; idx < NCP; idx += 128) {
            int row = idx / CH;
            int jc = idx - row * CH;
            int s1g = s1_0 - 1 + row;
            bool v = (s1g >= 0) && (s1g < S1);
            int s1c = v ? s1g : 0;
            cp_async16(dst_base + (uint32_t)((row * XROW + 4 + jc * 4) * 4),
                       src_base + s1c * W + jc * 4, v);
        }
        cp_commit();
    };

    load_tile(0, 0);
    cp_wait0();
    __syncthreads();

    const int r = tid / TPR;
    const int cb = (tid % TPR) * PX;

    ull acc2[4][PX];
#pragma unroll
    for (int op = 0; op < 4; op++)
#pragma unroll
        for (int j = 0; j < PX; j++) acc2[op][j] = 0ull;

    int buf = 0;
    for (int c = 0; c < K; c++) {
        if (c + 1 < K) load_tile(c + 1, buf ^ 1);
        else cp_commit();

        const float* wc = &wsm[c * 72];
#pragma unroll
        for (int dr = 0; dr < 3; dr++) {
            const float* xr = &xs[buf][r + dr][cb + 3];
            ull nbp[PX + 2];
#pragma unroll
            for (int m = 0; m < PX + 2; m++) nbp[m] = pack2b(xr[m]);
#pragma unroll
            for (int op = 0; op < 4; op++) {
                ull wa = *(const ull*)&wc[(dr * 3 + 0) * 8 + op * 2];
                ull wb = *(const ull*)&wc[(dr * 3 + 1) * 8 + op * 2];
                ull wq = *(const ull*)&wc[(dr * 3 + 2) * 8 + op * 2];
#pragma unroll
                for (int j = 0; j < PX; j++) {
                    ffma2(acc2[op][j], wa, nbp[j]);
                    ffma2(acc2[op][j], wb, nbp[j + 1]);
                    ffma2(acc2[op][j], wq, nbp[j + 2]);
                }
            }
        }
        cp_wait0();
        __syncthreads();
        buf ^= 1;
    }

    const int s1 = s1_0 + r;
    if (OUTV == 0) {
        const int obase = b * o_b + s1 * o_s1 + cb;
#pragma unroll
        for (int op = 0; op < 4; op++) {
            float b0 = bias[oc0 + 2 * op], b1 = bias[oc0 + 2 * op + 1];
            int e0 = obase + (oc0 + 2 * op) * o_oc;
            int e1 = obase + (oc0 + 2 * op + 1) * o_oc;
#pragma unroll
            for (int j4 = 0; j4 < PX; j4 += 4) {
                float2 p0 = unpack2(acc2[op][j4 + 0]);
                float2 p1 = unpack2(acc2[op][j4 + 1]);
                float2 p2 = unpack2(acc2[op][j4 + 2]);
                float2 p3 = unpack2(acc2[op][j4 + 3]);
                float4 v0 = make_float4(lrelu(p0.x + b0), lrelu(p1.x + b0),
                                        lrelu(p2.x + b0), lrelu(p3.x + b0));
                float4 v1 = make_float4(lrelu(p0.y + b1), lrelu(p1.y + b1),
                                        lrelu(p2.y + b1), lrelu(p3.y + b1));
                if (RES) {
                    float4 r0 = *(const float4*)&res[e0 + j4];
                    float4 r1 = *(const float4*)&res[e1 + j4];
                    v0.x += r0.x; v0.y += r0.y; v0.z += r0.z; v0.w += r0.w;
                    v1.x += r1.x; v1.y += r1.y; v1.z += r1.z; v1.w += r1.w;
                }
                *(float4*)&out[e0 + j4] = v0;
                *(float4*)&out[e1 + j4] = v1;
            }
        }
    } else {
        float bv[8];
#pragma unroll
        for (int oi = 0; oi < 8; oi++) bv[oi] = bias[oc0 + oi];
#pragma unroll
        for (int j = 0; j < PX; j++) {
            int e = b * o_b + (cb + j) * o_s2 + s1 * o_s1 + oc0;
            float2 p0 = unpack2(acc2[0][j]);
            float2 p1 = unpack2(acc2[1][j]);
            float2 p2 = unpack2(acc2[2][j]);
            float2 p3 = unpack2(acc2[3][j]);
            float4 v0 = make_float4(lrelu(p0.x + bv[0]), lrelu(p0.y + bv[1]),
                                    lrelu(p1.x + bv[2]), lrelu(p1.y + bv[3]));
            float4 v1 = make_float4(lrelu(p2.x + bv[4]), lrelu(p2.y + bv[5]),
                                    lrelu(p3.x + bv[6]), lrelu(p3.y + bv[7]));
            *(float4*)&out[e] = v0;
            *(float4*)&out[e + 4] = v1;
        }
    }
}

// ---------------- fused gate + folded down-conv + residual (f32x2) ----------------
__global__ __launch_bounds__(128)
void down_kernel_v3(const float* __restrict__ x, const float* __restrict__ xhw,
                    const float* __restrict__ xcw, const float* __restrict__ xhc,
                    const float* __restrict__ g,
                    const float* __restrict__ wd, const float* __restrict__ b_down,
                    float* __restrict__ mid)
{
    __shared__ __align__(16) float ws[4][64][16];
    const int tid = threadIdx.x;
    const int p4 = (blockIdx.x * 128 + tid) * 4;
    const int oc0 = blockIdx.y * 16;
    const int b = blockIdx.z;

    for (int idx = tid; idx < 4096; idx += 128) {
        int s = idx >> 10;
        int rem = idx & 1023;
        int c = rem >> 4, i = rem & 15;
        ws[s][c][i] = wd[s * 4096 + c * 64 + oc0 + i];
    }
    __syncthreads();

    ull acc2[8][4];
#pragma unroll
    for (int i = 0; i < 8; i++)
#pragma unroll
        for (int j = 0; j < 4; j++) acc2[i][j] = 0ull;

    const int xb = b * CHW_ + p4;
    const int gb = b * GBS_ + p4;
    for (int c = 0; c < 64; c++) {
        int off = xb + c * HW_;
        float4 a  = *(const float4*)&x[off];
        float4 h  = *(const float4*)&xhw[off];
        float4 cw = *(const float4*)&xcw[off];
        float4 hc = *(const float4*)&xhc[off];
        float4 g0 = *(const float4*)&g[gb + c * HW_];
        float4 g1 = *(const float4*)&g[gb + (64 + c) * HW_];
        float4 g2 = *(const float4*)&g[gb + (128 + c) * HW_];
        h.x *= g0.x; h.y *= g0.y; h.z *= g0.z; h.w *= g0.w;
        cw.x *= g1.x; cw.y *= g1.y; cw.z *= g1.z; cw.w *= g1.w;
        hc.x *= g2.x; hc.y *= g2.y; hc.z *= g2.z; hc.w *= g2.w;
        ull ap[4]  = { pack2b(a.x),  pack2b(a.y),  pack2b(a.z),  pack2b(a.w)  };
        ull hp[4]  = { pack2b(h.x),  pack2b(h.y),  pack2b(h.z),  pack2b(h.w)  };
        ull cp[4]  = { pack2b(cw.x), pack2b(cw.y), pack2b(cw.z), pack2b(cw.w) };
        ull hcp[4] = { pack2b(hc.x), pack2b(hc.y), pack2b(hc.z), pack2b(hc.w) };
#pragma unroll
        for (int op = 0; op < 8; op++) {
            ull w0 = *(const ull*)&ws[0][c][op * 2];
            ull w1 = *(const ull*)&ws[1][c][op * 2];
            ull w2 = *(const ull*)&ws[2][c][op * 2];
            ull w3 = *(const ull*)&ws[3][c][op * 2];
#pragma unroll
            for (int j = 0; j < 4; j++) {
                ffma2(acc2[op][j], w0, ap[j]);
                ffma2(acc2[op][j], w1, hp[j]);
                ffma2(acc2[op][j], w2, cp[j]);
                ffma2(acc2[op][j], w3, hcp[j]);
            }
        }
    }
#pragma unroll
    for (int op = 0; op < 8; op++) {
        int oc = oc0 + 2 * op;
        float b0 = b_down[oc], b1 = b_down[oc + 1];
        float4 x0 = *(const float4*)&x[b * CHW_ + oc * HW_ + p4];
        float4 x1 = *(const float4*)&x[b * CHW_ + (oc + 1) * HW_ + p4];
        float2 p0 = unpack2(acc2[op][0]), p1 = unpack2(acc2[op][1]);
        float2 p2 = unpack2(acc2[op][2]), p3 = unpack2(acc2[op][3]);
        float4 v0 = make_float4(p0.x + b0 + x0.x, p1.x + b0 + x0.y,
                                p2.x + b0 + x0.z, p3.x + b0 + x0.w);
        float4 v1 = make_float4(p0.y + b1 + x1.x, p1.y + b1 + x1.y,
                                p2.y + b1 + x1.z, p3.y + b1 + x1.w);
        *(float4*)&mid[b * CHW_ + oc * HW_ + p4] = v0;
        *(float4*)&mid[b * CHW_ + (oc + 1) * HW_ + p4] = v1;
    }
}

// ---------------- launch ----------------
extern "C" void kernel_launch(void* const* d_in, const int* in_sizes, int n_in,
                              void* d_out, int out_size)
{
    const float* x      = (const float*)d_in[0];
    const float* w_hwc  = (const float*)d_in[1];
    const float* b_hwc  = (const float*)d_in[2];
    const float* w_dw   = (const float*)d_in[3];
    const float* b_dw   = (const float*)d_in[4];
    const float* w_hw   = (const float*)d_in[5];
    const float* b_hw   = (const float*)d_in[6];
    const float* w_cw   = (const float*)d_in[7];
    const float* b_cw   = (const float*)d_in[8];
    const float* w_hc   = (const float*)d_in[9];
    const float* b_hc   = (const float*)d_in[10];
    const float* w_down = (const float*)d_in[11];
    const float* b_down = (const float*)d_in[12];
    const float* w_l1   = (const float*)d_in[13];
    const float* b_l1   = (const float*)d_in[14];
    const float* w_l2   = (const float*)d_in[15];
    const float* b_l2   = (const float*)d_in[16];
    float* out = (float*)d_out;

    float *t, *g, *xt1, *xt2, *xhw, *xcw, *xhc, *mid, *o1, *wd;
    cudaGetSymbolAddress((void**)&t,   d_t);
    cudaGetSymbolAddress((void**)&g,   d_g);
    cudaGetSymbolAddress((void**)&xt1, d_xt1);
    cudaGetSymbolAddress((void**)&xt2, d_xt2);
    cudaGetSymbolAddress((void**)&xhw, d_xhw);
    cudaGetSymbolAddress((void**)&xcw, d_xcw);
    cudaGetSymbolAddress((void**)&xhc, d_xhc);
    cudaGetSymbolAddress((void**)&mid, d_mid);
    cudaGetSymbolAddress((void**)&o1,  d_o1);
    cudaGetSymbolAddress((void**)&wd,  d_wd);

    prep_wd_kernel<<<64, 256>>>(w_down, wd);
    t1_kernel<<<8192, 256>>>(x, xt1);
    t2_kernel<<<dim3(4, 2, 1024), dim3(32, 8)>>>(x, xt2);

    conv1x1_kernel<<<dim3(32, 12, 8), 128>>>(x, w_hwc, b_hwc, t);
    dwconv_kernel<<<dim3(32, 192, 8), 128>>>(t, w_dw, b_dw, g);

    // x_hw: standard conv (64->64), tile 8x128
    conv3x3_v4<64, 128, 128, 8, 8, 0, 0><<<dim3(16, 8, 8), 128>>>(
        x, w_hw, b_hw, xhw, nullptr, HW_, 128, 1, CHW_);

    // x_cw: conv on xt1 [b][h][c][w]: tile 8x128 over (c,w)
    conv3x3_v4<128, 64, 128, 8, 8, 0, 0><<<dim3(8, 16, 8), 128>>>(
        xt1, w_cw, b_cw, xcw, nullptr, 128, HW_, 1, CHW_);

    // x_hc: conv on xt2 [b][w][h][c]: tile 16x64 over (h,c)
    conv3x3_v4<128, 128, 64, 8, 16, 1, 0><<<dim3(8, 16, 8), 128>>>(
        xt2, w_hc, b_hc, xhc, nullptr, 1, 128, HW_, CHW_);

    // fused: gates * branches -> folded down-conv -> + x
    down_kernel_v3<<<dim3(32, 4, 8), 128>>>(x, xhw, xcw, xhc, g, wd, b_down, mid);

    // l1
    conv3x3_v4<64, 128, 128, 8, 8, 0, 0><<<dim3(16, 8, 8), 128>>>(
        mid, w_l1, b_l1, o1, nullptr, HW_, 128, 1, CHW_);
    // l2 + residual
    conv3x3_v4<64, 128, 128, 8, 8, 0, 1><<<dim3(16, 8, 8), 128>>>(
        o1, w_l2, b_l2, out, x, HW_, 128, 1, CHW_);
}

// round 6
// speedup vs baseline: 5.4252x; 2.2118x over previous
#include <cuda_runtime.h>
#include <cstdint>

// B=8, C=64, T=128
#define HW_   16384
#define CHW_  1048576
#define GBS_  3145728

typedef unsigned long long ull;

// ---------------- scratch ----------------
__device__ float d_t  [25165824];  // [8,192,128,128] conv1x1 out
__device__ float d_g  [25165824];  // [8,192,128,128] gates
__device__ float d_xt1[8388608];   // x.transpose(0,2,1,3): [b][h][c][w]  (tf32-rounded)
__device__ float d_xt2[8388608];   // x.transpose(0,3,2,1): [b][w][h][c]  (tf32-rounded)
__device__ float d_xr [8388608];   // tf32-rounded copy of x
__device__ float d_xhw[8388608];
__device__ float d_xcw[8388608];
__device__ float d_xhc[8388608];
__device__ float d_mid[8388608];
__device__ float d_o1 [8388608];
__device__ float d_wd [16384];     // folded down weights [4][64(c)][64(o)]
__device__ float d_wr [405504];    // prepped tf32 conv weights

__device__ __forceinline__ float lrelu(float v) { return v > 0.f ? v : 0.1f * v; }
__device__ __forceinline__ float to_tf32(float v) {
    float o; asm("cvt.rna.tf32.f32 %0, %1;" : "=f"(o) : "f"(v)); return o;
}

__device__ __forceinline__ void cp_async16(uint32_t dst, const float* src, bool valid) {
    int sz = valid ? 16 : 0;
    asm volatile("cp.async.cg.shared.global [%0], [%1], 16, %2;\n"
                 :: "r"(dst), "l"(src), "r"(sz));
}
__device__ __forceinline__ void cp_commit() { asm volatile("cp.async.commit_group;\n"); }
__device__ __forceinline__ void cp_wait0()  { asm volatile("cp.async.wait_group 0;\n"); }

// ---------------- f32x2 packed helpers (for FFMA2 kernels) ----------------
__device__ __forceinline__ ull pack2b(float v) {
    ull r; asm("mov.b64 %0, {%1,%1};" : "=l"(r) : "f"(v)); return r;
}
__device__ __forceinline__ float2 unpack2(ull v) {
    float2 r; asm("mov.b64 {%0,%1}, %2;" : "=f"(r.x), "=f"(r.y) : "l"(v)); return r;
}
__device__ __forceinline__ void ffma2(ull& d, ull a, ull b) {
    asm("fma.rn.f32x2 %0, %1, %2, %0;" : "+l"(d) : "l"(a), "l"(b));
}

// ---------------- tf32 mma ----------------
__device__ __forceinline__ void mma_tf32(float* d, const uint32_t* a,
                                         uint32_t b0, uint32_t b1) {
    asm volatile("mma.sync.aligned.m16n8k8.row.col.f32.tf32.tf32.f32 "
                 "{%0,%1,%2,%3}, {%4,%5,%6,%7}, {%8,%9}, {%0,%1,%2,%3};"
                 : "+f"(d[0]), "+f"(d[1]), "+f"(d[2]), "+f"(d[3])
                 : "r"(a[0]), "r"(a[1]), "r"(a[2]), "r"(a[3]), "r"(b0), "r"(b1));
}

// ---------------- prep: fold w_down ----------------
__global__ void prep_wd_kernel(const float* __restrict__ w_down, float* __restrict__ wd)
{
    int idx = blockIdx.x * 256 + threadIdx.x;
    if (idx >= 16384) return;
    int s = idx >> 12;
    int rem = idx & 4095;
    int c = rem >> 6;
    int o = rem & 63;
    auto W = [&](int i, int ky, int kx) { return w_down[((o * 128 + i) * 2 + ky) * 2 + kx]; };
    float v = 0.f;
    if (s == 0) v = W(2 * c, 0, 0) + W(2 * c + 1, 1, 1);
    else if (s == 1) v = W(2 * c, 0, 1) + W(2 * c + 1, 1, 0);
    else if (s == 2) v = W(2 * c, 1, 0) + W(2 * c + 1, 0, 1);
    else v = W(2 * c, 1, 1) + W(2 * c + 1, 0, 0);
    wd[s * 4096 + c * 64 + o] = v;
}

// ---------------- prep: transpose + tf32-round conv weights ----------------
// dst layout: [ocb][slab][s=dr*3+dc][k(8)][ocl(64)]
__global__ void prep_w_kernel(const float* __restrict__ src, float* __restrict__ dst,
                              int OC, int C)
{
    int idx = blockIdx.x * 256 + threadIdx.x;
    int total = OC * C * 9;
    if (idx >= total) return;
    int ocl = idx & 63;
    int k = (idx >> 6) & 7;
    int sk = (idx >> 9) % 9;
    int rest = idx / (512 * 9);
    int NS = C >> 3;
    int slab = rest % NS;
    int ocb = rest / NS;
    float v = src[((ocb * 64 + ocl) * C + slab * 8 + k) * 9 + sk];
    dst[idx] = to_tf32(v);
}

// ---------------- tf32-round copy ----------------
__global__ __launch_bounds__(256)
void round4_kernel(const float* __restrict__ src, float* __restrict__ dst)
{
    int i = blockIdx.x * 256 + threadIdx.x;
    float4 v = *(const float4*)&src[i * 4];
    v.x = to_tf32(v.x); v.y = to_tf32(v.y); v.z = to_tf32(v.z); v.w = to_tf32(v.w);
    *(float4*)&dst[i * 4] = v;
}

// ---------------- transposes (tf32-rounded outputs) ----------------
__global__ __launch_bounds__(256)
void t1_kernel(const float* __restrict__ x, float* __restrict__ o)
{
    int i = blockIdx.x * 256 + threadIdx.x;
    int w4 = i & 31; int rest = i >> 5;
    int h = rest & 127; rest >>= 7;
    int c = rest & 63; int b = rest >> 6;
    float4 v = *(const float4*)&x[((b * 64 + c) * 128 + h) * 128 + w4 * 4];
    v.x = to_tf32(v.x); v.y = to_tf32(v.y); v.z = to_tf32(v.z); v.w = to_tf32(v.w);
    *(float4*)&o[((b * 128 + h) * 64 + c) * 128 + w4 * 4] = v;
}

__global__ __launch_bounds__(256)
void t2_kernel(const float* __restrict__ x, float* __restrict__ o)
{
    __shared__ float tile[32][33];
    int tx = threadIdx.x, ty = threadIdx.y;
    int w0 = blockIdx.x * 32;
    int c0 = blockIdx.y * 32;
    int bh = blockIdx.z;
    int b = bh >> 7, h = bh & 127;
    int xb = b * CHW_ + h * 128;
#pragma unroll
    for (int i = 0; i < 4; i++)
        tile[ty + 8 * i][tx] = x[xb + (c0 + ty + 8 * i) * HW_ + w0 + tx];
    __syncthreads();
    int ob = b * CHW_ + h * 64;
#pragma unroll
    for (int i = 0; i < 4; i++)
        o[ob + (w0 + ty + 8 * i) * 8192 + c0 + tx] = to_tf32(tile[tx][ty + 8 * i]);
}

// ---------------- conv1x1 (f32x2, prefetch) ----------------
__global__ __launch_bounds__(128)
void conv1x1_kernel(const float* __restrict__ x, const float* __restrict__ w,
                    const float* __restrict__ bias, float* __restrict__ t)
{
    __shared__ __align__(16) float ws[64][16];
    const int tid = threadIdx.x;
    const int p4 = (blockIdx.x * 128 + tid) * 4;
    const int oc0 = blockIdx.y * 16;
    const int b = blockIdx.z;

    for (int idx = tid; idx < 1024; idx += 128) {
        int c = idx >> 4, i = idx & 15;
        ws[c][i] = w[(oc0 + i) * 64 + c];
    }
    __syncthreads();

    ull acc2[8][4];
#pragma unroll
    for (int i = 0; i < 8; i++)
#pragma unroll
        for (int j = 0; j < 4; j++) acc2[i][j] = 0ull;

    const int xb = b * CHW_ + p4;
    float4 xv = *(const float4*)&x[xb];
    for (int c = 0; c < 64; c++) {
        float4 nxt;
        if (c + 1 < 64) nxt = *(const float4*)&x[xb + (c + 1) * HW_];
        ull xp[4] = { pack2b(xv.x), pack2b(xv.y), pack2b(xv.z), pack2b(xv.w) };
#pragma unroll
        for (int op = 0; op < 8; op++) {
            ull w2 = *(const ull*)&ws[c][op * 2];
            ffma2(acc2[op][0], w2, xp[0]);
            ffma2(acc2[op][1], w2, xp[1]);
            ffma2(acc2[op][2], w2, xp[2]);
            ffma2(acc2[op][3], w2, xp[3]);
        }
        xv = nxt;
    }
#pragma unroll
    for (int op = 0; op < 8; op++) {
        float b0 = bias[oc0 + 2 * op], b1 = bias[oc0 + 2 * op + 1];
        float2 p0 = unpack2(acc2[op][0]), p1 = unpack2(acc2[op][1]);
        float2 p2 = unpack2(acc2[op][2]), p3 = unpack2(acc2[op][3]);
        float4 v0 = make_float4(p0.x + b0, p1.x + b0, p2.x + b0, p3.x + b0);
        float4 v1 = make_float4(p0.y + b1, p1.y + b1, p2.y + b1, p3.y + b1);
        *(float4*)&t[b * GBS_ + (oc0 + 2 * op) * HW_ + p4] = v0;
        *(float4*)&t[b * GBS_ + (oc0 + 2 * op + 1) * HW_ + p4] = v1;
    }
}

// ---------------- depthwise 3x3 ----------------
__global__ __launch_bounds__(128)
void dwconv_kernel(const float* __restrict__ t, const float* __restrict__ w_dw,
                   const float* __restrict__ b_dw, float* __restrict__ g)
{
    __shared__ float xs[10][68];
    const int tid = threadIdx.x;
    const int s1t = blockIdx.x & 15, s2t = blockIdx.x >> 4;
    const int s1_0 = s1t * 8, s2_0 = s2t * 64;
    const int og = blockIdx.y, b = blockIdx.z;
    const int base = b * GBS_ + og * HW_;

    for (int idx = tid; idx < 660; idx += 128) {
        int row = idx / 66, col = idx - row * 66;
        int s1g = s1_0 - 1 + row;
        int s2g = s2_0 - 1 + col;
        float v = 0.f;
        if (s1g >= 0 && s1g < 128 && s2g >= 0 && s2g < 128)
            v = t[base + s1g * 128 + s2g];
        xs[row][col] = v;
    }
    __syncthreads();

    float w[9];
#pragma unroll
    for (int k = 0; k < 9; k++) w[k] = w_dw[og * 9 + k];
    float bb = b_dw[og];

    const int r = tid >> 4, cb = (tid & 15) * 4;
    float4 v;
    float* vp = &v.x;
#pragma unroll
    for (int j = 0; j < 4; j++) {
        float s = bb;
#pragma unroll
        for (int dr = 0; dr < 3; dr++)
#pragma unroll
            for (int dc = 0; dc < 3; dc++)
                s += w[dr * 3 + dc] * xs[r + dr][cb + j + dc];
        vp[j] = s;
    }
    *(float4*)&g[base + (s1_0 + r) * 128 + s2_0 + cb] = v;
}

// ---------------- tf32 tensor-core implicit-GEMM 3x3 conv ----------------
// input x: [b][C][S1][W] (tf32-pre-rounded); wprep: prep_w layout (tf32-rounded).
// out addr: b*o_b + oc*o_oc + s1*o_s1 + s2*o_s2
// OUTV 0: o_s2==1. OUTV 1: o_oc==1. RES: add res after lrelu. RND: round output to tf32.
template<int C, int S1, int W, int OC, int OUTV, int RES, int RND>
__global__ __launch_bounds__(256, 2)
void conv3x3_mma(const float* __restrict__ x, const float* __restrict__ wprep,
                 const float* __restrict__ bias, float* __restrict__ out,
                 const float* __restrict__ res,
                 int o_oc, int o_s1, int o_s2, int o_b)
{
    constexpr int TR = 256 / W;             // output rows per block (2 or 4)
    constexpr int NS = C / 8;               // channel slabs
    constexpr int RW = W + 8;               // B row stride (floats)
    constexpr int SK = (TR + 2) * RW + 8;   // B channel stride (pad for banks)
    constexpr int ASLAB = 9 * 8 * 72;       // 5184 floats
    constexpr int BSLAB = 8 * SK;
    constexpr int CH = W / 4;

    extern __shared__ float sm[];
    float* wsm = sm;                 // [2][ASLAB]
    float* bsm = sm + 2 * ASLAB;     // [2][BSLAB]

    const int tid = threadIdx.x;
    const int s1_0 = blockIdx.x * TR;
    const int oc0 = blockIdx.y * 64;
    const int b = blockIdx.z;
    const int xb = b * (C * S1 * W);
    const float* wsrc = wprep + blockIdx.y * (NS * 4608);

    // zero always-zero halo columns (xcol=-1 -> col 3; xcol=W -> col W+4), both buffers
    for (int i = tid; i < 2 * 8 * (TR + 2) * 2; i += 256) {
        int side = i & 1; int rest = i >> 1;
        int row = rest % (TR + 2); rest /= (TR + 2);
        int k = rest & 7; int bufi = rest >> 3;
        bsm[bufi * BSLAB + k * SK + row * RW + (side ? (W + 4) : 3)] = 0.f;
    }

    auto stageA = [&](int slab, int bufi) {
        uint32_t dst0 = (uint32_t)__cvta_generic_to_shared(wsm + bufi * ASLAB);
        const float* src = wsrc + slab * 4608;
        for (int i = tid; i < 1152; i += 256) {
            int j = i & 15; int k = (i >> 4) & 7; int s = i >> 7;
            cp_async16(dst0 + (uint32_t)((s * 576 + k * 72 + 4 * j) * 4), src + i * 4, true);
        }
    };
    auto stageB = [&](int slab, int bufi) {
        uint32_t dst0 = (uint32_t)__cvta_generic_to_shared(bsm + bufi * BSLAB);
        const float* src = x + xb + slab * 8 * (S1 * W);
        for (int i = tid; i < 8 * (TR + 2) * CH; i += 256) {
            int j = i % CH; int rest = i / CH;
            int row = rest % (TR + 2); int k = rest / (TR + 2);
            int s1g = s1_0 - 1 + row;
            bool v = (s1g >= 0) && (s1g < S1);
            int s1c = v ? s1g : 0;
            cp_async16(dst0 + (uint32_t)((k * SK + row * RW + 4 + 4 * j) * 4),
                       src + k * (S1 * W) + s1c * W + 4 * j, v);
        }
    };

    stageA(0, 0); stageB(0, 0); cp_commit();

    const int lane = tid & 31, warp = tid >> 5;
    const int g = lane >> 2, tq = lane & 3;
    const int rbase = (warp * 32) / W;
    const int cb0 = (warp * 32) % W;

    float acc[4][4][4];
#pragma unroll
    for (int mt = 0; mt < 4; mt++)
#pragma unroll
        for (int nt = 0; nt < 4; nt++)
#pragma unroll
            for (int q = 0; q < 4; q++) acc[mt][nt][q] = 0.f;

    const uint32_t* wsu = (const uint32_t*)wsm;
    const uint32_t* bsu = (const uint32_t*)bsm;

    int buf = 0;
    for (int slab = 0; slab < NS; slab++) {
        cp_wait0();
        __syncthreads();
        if (slab + 1 < NS) { stageA(slab + 1, buf ^ 1); stageB(slab + 1, buf ^ 1); cp_commit(); }

        const uint32_t* wa = wsu + buf * ASLAB;
        const uint32_t* bb = bsu + buf * BSLAB;
#pragma unroll
        for (int dr = 0; dr < 3; dr++) {
#pragma unroll
            for (int dc = 0; dc < 3; dc++) {
                const int s = dr * 3 + dc;
                uint32_t au[4][4];
#pragma unroll
                for (int mt = 0; mt < 4; mt++) {
                    int base = s * 576 + tq * 72 + 16 * mt + g;
                    au[mt][0] = wa[base];
                    au[mt][1] = wa[base + 8];
                    au[mt][2] = wa[base + 288];
                    au[mt][3] = wa[base + 296];
                }
                int bbase = tq * SK + (rbase + dr) * RW + cb0 + g + dc + 3;
#pragma unroll
                for (int nt = 0; nt < 4; nt++) {
                    uint32_t b0 = bb[bbase + 8 * nt];
                    uint32_t b1 = bb[bbase + 4 * SK + 8 * nt];
#pragma unroll
                    for (int mt = 0; mt < 4; mt++)
                        mma_tf32(acc[mt][nt], au[mt], b0, b1);
                }
            }
        }
        buf ^= 1;
    }

    // epilogue
    const int s1 = s1_0 + rbase;
#pragma unroll
    for (int mt = 0; mt < 4; mt++) {
        const int oc = oc0 + 16 * mt + g;
        const float bv0 = bias[oc], bv1 = bias[oc + 8];
#pragma unroll
        for (int nt = 0; nt < 4; nt++) {
            const int pc = cb0 + 8 * nt + 2 * tq;
            float v0 = lrelu(acc[mt][nt][0] + bv0);
            float v1 = lrelu(acc[mt][nt][1] + bv0);
            float v2 = lrelu(acc[mt][nt][2] + bv1);
            float v3 = lrelu(acc[mt][nt][3] + bv1);
            if (OUTV == 0) {
                int e0 = b * o_b + oc * o_oc + s1 * o_s1 + pc;
                int e1 = e0 + 8 * o_oc;
                if (RES) {
                    v0 += res[e0]; v1 += res[e0 + 1];
                    v2 += res[e1]; v3 += res[e1 + 1];
                }
                if (RND) {
                    v0 = to_tf32(v0); v1 = to_tf32(v1);
                    v2 = to_tf32(v2); v3 = to_tf32(v3);
                }
                *(float2*)&out[e0] = make_float2(v0, v1);
                *(float2*)&out[e1] = make_float2(v2, v3);
            } else {
                int e = b * o_b + s1 * o_s1 + oc;
                out[e + pc * o_s2] = v0;
                out[e + (pc + 1) * o_s2] = v1;
                out[e + 8 + pc * o_s2] = v2;
                out[e + 8 + (pc + 1) * o_s2] = v3;
            }
        }
    }
}

// ---------------- fused gate + folded down-conv + residual (f32x2) ----------------
__global__ __launch_bounds__(128)
void down_kernel_v3(const float* __restrict__ x, const float* __restrict__ xhw,
                    const float* __restrict__ xcw, const float* __restrict__ xhc,
                    const float* __restrict__ g,
                    const float* __restrict__ wd, const float* __restrict__ b_down,
                    float* __restrict__ mid)
{
    __shared__ __align__(16) float ws[4][64][16];
    const int tid = threadIdx.x;
    const int p4 = (blockIdx.x * 128 + tid) * 4;
    const int oc0 = blockIdx.y * 16;
    const int b = blockIdx.z;

    for (int idx = tid; idx < 4096; idx += 128) {
        int s = idx >> 10;
        int rem = idx & 1023;
        int c = rem >> 4, i = rem & 15;
        ws[s][c][i] = wd[s * 4096 + c * 64 + oc0 + i];
    }
    __syncthreads();

    ull acc2[8][4];
#pragma unroll
    for (int i = 0; i < 8; i++)
#pragma unroll
        for (int j = 0; j < 4; j++) acc2[i][j] = 0ull;

    const int xb = b * CHW_ + p4;
    const int gb = b * GBS_ + p4;
    for (int c = 0; c < 64; c++) {
        int off = xb + c * HW_;
        float4 a  = *(const float4*)&x[off];
        float4 h  = *(const float4*)&xhw[off];
        float4 cw = *(const float4*)&xcw[off];
        float4 hc = *(const float4*)&xhc[off];
        float4 g0 = *(const float4*)&g[gb + c * HW_];
        float4 g1 = *(const float4*)&g[gb + (64 + c) * HW_];
        float4 g2 = *(const float4*)&g[gb + (128 + c) * HW_];
        h.x *= g0.x; h.y *= g0.y; h.z *= g0.z; h.w *= g0.w;
        cw.x *= g1.x; cw.y *= g1.y; cw.z *= g1.z; cw.w *= g1.w;
        hc.x *= g2.x; hc.y *= g2.y; hc.z *= g2.z; hc.w *= g2.w;
        ull ap[4]  = { pack2b(a.x),  pack2b(a.y),  pack2b(a.z),  pack2b(a.w)  };
        ull hp[4]  = { pack2b(h.x),  pack2b(h.y),  pack2b(h.z),  pack2b(h.w)  };
        ull cp[4]  = { pack2b(cw.x), pack2b(cw.y), pack2b(cw.z), pack2b(cw.w) };
        ull hcp[4] = { pack2b(hc.x), pack2b(hc.y), pack2b(hc.z), pack2b(hc.w) };
#pragma unroll
        for (int op = 0; op < 8; op++) {
            ull w0 = *(const ull*)&ws[0][c][op * 2];
            ull w1 = *(const ull*)&ws[1][c][op * 2];
            ull w2 = *(const ull*)&ws[2][c][op * 2];
            ull w3 = *(const ull*)&ws[3][c][op * 2];
#pragma unroll
            for (int j = 0; j < 4; j++) {
                ffma2(acc2[op][j], w0, ap[j]);
                ffma2(acc2[op][j], w1, hp[j]);
                ffma2(acc2[op][j], w2, cp[j]);
                ffma2(acc2[op][j], w3, hcp[j]);
            }
        }
    }
#pragma unroll
    for (int op = 0; op < 8; op++) {
        int oc = oc0 + 2 * op;
        float b0 = b_down[oc], b1 = b_down[oc + 1];
        float4 x0 = *(const float4*)&x[b * CHW_ + oc * HW_ + p4];
        float4 x1 = *(const float4*)&x[b * CHW_ + (oc + 1) * HW_ + p4];
        float2 p0 = unpack2(acc2[op][0]), p1 = unpack2(acc2[op][1]);
        float2 p2 = unpack2(acc2[op][2]), p3 = unpack2(acc2[op][3]);
        // mid feeds only the l1 tf32 conv -> store tf32-rounded
        float4 v0 = make_float4(to_tf32(p0.x + b0 + x0.x), to_tf32(p1.x + b0 + x0.y),
                                to_tf32(p2.x + b0 + x0.z), to_tf32(p3.x + b0 + x0.w));
        float4 v1 = make_float4(to_tf32(p0.y + b1 + x1.x), to_tf32(p1.y + b1 + x1.y),
                                to_tf32(p2.y + b1 + x1.z), to_tf32(p3.y + b1 + x1.w));
        *(float4*)&mid[b * CHW_ + oc * HW_ + p4] = v0;
        *(float4*)&mid[b * CHW_ + (oc + 1) * HW_ + p4] = v1;
    }
}

// ---------------- launch ----------------
extern "C" void kernel_launch(void* const* d_in, const int* in_sizes, int n_in,
                              void* d_out, int out_size)
{
    const float* x      = (const float*)d_in[0];
    const float* w_hwc  = (const float*)d_in[1];
    const float* b_hwc  = (const float*)d_in[2];
    const float* w_dw   = (const float*)d_in[3];
    const float* b_dw   = (const float*)d_in[4];
    const float* w_hw   = (const float*)d_in[5];
    const float* b_hw   = (const float*)d_in[6];
    const float* w_cw   = (const float*)d_in[7];
    const float* b_cw   = (const float*)d_in[8];
    const float* w_hc   = (const float*)d_in[9];
    const float* b_hc   = (const float*)d_in[10];
    const float* w_down = (const float*)d_in[11];
    const float* b_down = (const float*)d_in[12];
    const float* w_l1   = (const float*)d_in[13];
    const float* b_l1   = (const float*)d_in[14];
    const float* w_l2   = (const float*)d_in[15];
    const float* b_l2   = (const float*)d_in[16];
    float* out = (float*)d_out;

    float *t, *g, *xt1, *xt2, *xr, *xhw, *xcw, *xhc, *mid, *o1, *wd, *wr;
    cudaGetSymbolAddress((void**)&t,   d_t);
    cudaGetSymbolAddress((void**)&g,   d_g);
    cudaGetSymbolAddress((void**)&xt1, d_xt1);
    cudaGetSymbolAddress((void**)&xt2, d_xt2);
    cudaGetSymbolAddress((void**)&xr,  d_xr);
    cudaGetSymbolAddress((void**)&xhw, d_xhw);
    cudaGetSymbolAddress((void**)&xcw, d_xcw);
    cudaGetSymbolAddress((void**)&xhc, d_xhc);
    cudaGetSymbolAddress((void**)&mid, d_mid);
    cudaGetSymbolAddress((void**)&o1,  d_o1);
    cudaGetSymbolAddress((void**)&wd,  d_wd);
    cudaGetSymbolAddress((void**)&wr,  d_wr);

    // weight offsets in wr
    float* wr_hw = wr;
    float* wr_cw = wr + 36864;
    float* wr_hc = wr + 184320;
    float* wr_l1 = wr + 331776;
    float* wr_l2 = wr + 368640;

    // dynamic smem sizes
    const int SMEM_W128 = (2 * 5184 + 2 * (8 * ((2 + 2) * 136 + 8))) * 4;  // 76800
    const int SMEM_W64  = (2 * 5184 + 2 * (8 * ((4 + 2) * 72 + 8))) * 4;   // 69632

    cudaFuncSetAttribute((const void*)conv3x3_mma<64, 128, 128, 64, 0, 0, 0>,
                         cudaFuncAttributeMaxDynamicSharedMemorySize, SMEM_W128);
    cudaFuncSetAttribute((const void*)conv3x3_mma<128, 64, 128, 128, 0, 0, 0>,
                         cudaFuncAttributeMaxDynamicSharedMemorySize, SMEM_W128);
    cudaFuncSetAttribute((const void*)conv3x3_mma<128, 128, 64, 128, 1, 0, 0>,
                         cudaFuncAttributeMaxDynamicSharedMemorySize, SMEM_W64);
    cudaFuncSetAttribute((const void*)conv3x3_mma<64, 128, 128, 64, 0, 0, 1>,
                         cudaFuncAttributeMaxDynamicSharedMemorySize, SMEM_W128);
    cudaFuncSetAttribute((const void*)conv3x3_mma<64, 128, 128, 64, 0, 1, 0>,
                         cudaFuncAttributeMaxDynamicSharedMemorySize, SMEM_W128);

    // prep
    prep_wd_kernel<<<64, 256>>>(w_down, wd);
    prep_w_kernel<<<144, 256>>>(w_hw, wr_hw, 64, 64);
    prep_w_kernel<<<576, 256>>>(w_cw, wr_cw, 128, 128);
    prep_w_kernel<<<576, 256>>>(w_hc, wr_hc, 128, 128);
    prep_w_kernel<<<144, 256>>>(w_l1, wr_l1, 64, 64);
    prep_w_kernel<<<144, 256>>>(w_l2, wr_l2, 64, 64);
    round4_kernel<<<8192, 256>>>(x, xr);
    t1_kernel<<<8192, 256>>>(x, xt1);
    t2_kernel<<<dim3(4, 2, 1024), dim3(32, 8)>>>(x, xt2);

    // gate path
    conv1x1_kernel<<<dim3(32, 12, 8), 128>>>(x, w_hwc, b_hwc, t);
    dwconv_kernel<<<dim3(32, 192, 8), 128>>>(t, w_dw, b_dw, g);

    // tensor-core convs
    conv3x3_mma<64, 128, 128, 64, 0, 0, 0><<<dim3(64, 1, 8), 256, SMEM_W128>>>(
        xr, wr_hw, b_hw, xhw, nullptr, HW_, 128, 1, CHW_);
    conv3x3_mma<128, 64, 128, 128, 0, 0, 0><<<dim3(32, 2, 8), 256, SMEM_W128>>>(
        xt1, wr_cw, b_cw, xcw, nullptr, 128, HW_, 1, CHW_);
    conv3x3_mma<128, 128, 64, 128, 1, 0, 0><<<dim3(32, 2, 8), 256, SMEM_W64>>>(
        xt2, wr_hc, b_hc, xhc, nullptr, 1, 128, HW_, CHW_);

    // fused gate * branches -> folded down-conv -> + x (rounds mid to tf32)
    down_kernel_v3<<<dim3(32, 4, 8), 128>>>(x, xhw, xcw, xhc, g, wd, b_down, mid);

    // l1 (rounds o1 to tf32), l2 + residual
    conv3x3_mma<64, 128, 128, 64, 0, 0, 1><<<dim3(64, 1, 8), 256, SMEM_W128>>>(
        mid, wr_l1, b_l1, o1, nullptr, HW_, 128, 1, CHW_);
    conv3x3_mma<64, 128, 128, 64, 0, 1, 0><<<dim3(64, 1, 8), 256, SMEM_W128>>>(
        o1, wr_l2, b_l2, out, x, HW_, 128, 1, CHW_);
}

// round 7
// speedup vs baseline: 6.1671x; 1.1367x over previous
#include <cuda_runtime.h>
#include <cstdint>

// B=8, C=64, T=128
#define HW_   16384
#define CHW_  1048576
#define GBS_  3145728

typedef unsigned long long ull;

// ---------------- scratch ----------------
__device__ float d_t  [25165824];  // [8,192,128,128] conv1x1 out
__device__ float d_g  [25165824];  // [8,192,128,128] gates
__device__ float d_xt1[8388608];   // x.transpose(0,2,1,3): [b][h][c][w]  (tf32-rounded)
__device__ float d_xt2[8388608];   // x.transpose(0,3,2,1): [b][w][h][c]  (tf32-rounded)
__device__ float d_xr [8388608];   // tf32-rounded copy of x
__device__ float d_xhw[8388608];
__device__ float d_xcw[8388608];
__device__ float d_xhc[8388608];
__device__ float d_mid[8388608];
__device__ float d_o1 [8388608];
__device__ float d_wd [16384];     // folded down weights [4][64(c)][64(o)]
__device__ float d_wr [405504];    // prepped tf32 conv weights
__device__ float d_w1 [12288];     // prepped tf32 1x1 weights

__device__ __forceinline__ float lrelu(float v) { return v > 0.f ? v : 0.1f * v; }
__device__ __forceinline__ float to_tf32(float v) {
    float o; asm("cvt.rna.tf32.f32 %0, %1;" : "=f"(o) : "f"(v)); return o;
}

__device__ __forceinline__ void cp_async16(uint32_t dst, const float* src, bool valid) {
    int sz = valid ? 16 : 0;
    asm volatile("cp.async.cg.shared.global [%0], [%1], 16, %2;\n"
                 :: "r"(dst), "l"(src), "r"(sz));
}
__device__ __forceinline__ void cp_commit() { asm volatile("cp.async.commit_group;\n"); }
__device__ __forceinline__ void cp_wait0()  { asm volatile("cp.async.wait_group 0;\n"); }

// ---------------- f32x2 packed helpers ----------------
__device__ __forceinline__ ull pack2b(float v) {
    ull r; asm("mov.b64 %0, {%1,%1};" : "=l"(r) : "f"(v)); return r;
}
__device__ __forceinline__ float2 unpack2(ull v) {
    float2 r; asm("mov.b64 {%0,%1}, %2;" : "=f"(r.x), "=f"(r.y) : "l"(v)); return r;
}
__device__ __forceinline__ void ffma2(ull& d, ull a, ull b) {
    asm("fma.rn.f32x2 %0, %1, %2, %0;" : "+l"(d) : "l"(a), "l"(b));
}

// ---------------- tf32 mma ----------------
__device__ __forceinline__ void mma_tf32(float* d, const uint32_t* a,
                                         uint32_t b0, uint32_t b1) {
    asm volatile("mma.sync.aligned.m16n8k8.row.col.f32.tf32.tf32.f32 "
                 "{%0,%1,%2,%3}, {%4,%5,%6,%7}, {%8,%9}, {%0,%1,%2,%3};"
                 : "+f"(d[0]), "+f"(d[1]), "+f"(d[2]), "+f"(d[3])
                 : "r"(a[0]), "r"(a[1]), "r"(a[2]), "r"(a[3]), "r"(b0), "r"(b1));
}

// ---------------- prep: fold w_down ----------------
__global__ void prep_wd_kernel(const float* __restrict__ w_down, float* __restrict__ wd)
{
    int idx = blockIdx.x * 256 + threadIdx.x;
    if (idx >= 16384) return;
    int s = idx >> 12;
    int rem = idx & 4095;
    int c = rem >> 6;
    int o = rem & 63;
    auto W = [&](int i, int ky, int kx) { return w_down[((o * 128 + i) * 2 + ky) * 2 + kx]; };
    float v = 0.f;
    if (s == 0) v = W(2 * c, 0, 0) + W(2 * c + 1, 1, 1);
    else if (s == 1) v = W(2 * c, 0, 1) + W(2 * c + 1, 1, 0);
    else if (s == 2) v = W(2 * c, 1, 0) + W(2 * c + 1, 0, 1);
    else v = W(2 * c, 1, 1) + W(2 * c + 1, 0, 0);
    wd[s * 4096 + c * 64 + o] = v;
}

// ---------------- prep: transpose + tf32-round conv weights ----------------
// dst layout: [ocb][slab][s=dr*3+dc][k(8)][ocl(64)]
__global__ void prep_w_kernel(const float* __restrict__ src, float* __restrict__ dst,
                              int OC, int C)
{
    int idx = blockIdx.x * 256 + threadIdx.x;
    int total = OC * C * 9;
    if (idx >= total) return;
    int ocl = idx & 63;
    int k = (idx >> 6) & 7;
    int sk = (idx >> 9) % 9;
    int rest = idx / (512 * 9);
    int NS = C >> 3;
    int slab = rest % NS;
    int ocb = rest / NS;
    float v = src[((ocb * 64 + ocl) * C + slab * 8 + k) * 9 + sk];
    dst[idx] = to_tf32(v);
}

// ---------------- prep: 1x1 weights (192x64) -> [ocb(3)][slab(8)][k(8)][ocl(64)] ----------------
__global__ void prep_w1_kernel(const float* __restrict__ src, float* __restrict__ dst)
{
    int idx = blockIdx.x * 256 + threadIdx.x;
    if (idx >= 12288) return;
    int ocl = idx & 63;
    int k = (idx >> 6) & 7;
    int slab = (idx >> 9) & 7;
    int ocb = idx >> 12;
    dst[idx] = to_tf32(src[(ocb * 64 + ocl) * 64 + slab * 8 + k]);
}

// ---------------- tf32-round copy ----------------
__global__ __launch_bounds__(256)
void round4_kernel(const float* __restrict__ src, float* __restrict__ dst)
{
    int i = blockIdx.x * 256 + threadIdx.x;
    float4 v = *(const float4*)&src[i * 4];
    v.x = to_tf32(v.x); v.y = to_tf32(v.y); v.z = to_tf32(v.z); v.w = to_tf32(v.w);
    *(float4*)&dst[i * 4] = v;
}

// ---------------- transposes (tf32-rounded outputs) ----------------
__global__ __launch_bounds__(256)
void t1_kernel(const float* __restrict__ x, float* __restrict__ o)
{
    int i = blockIdx.x * 256 + threadIdx.x;
    int w4 = i & 31; int rest = i >> 5;
    int h = rest & 127; rest >>= 7;
    int c = rest & 63; int b = rest >> 6;
    float4 v = *(const float4*)&x[((b * 64 + c) * 128 + h) * 128 + w4 * 4];
    v.x = to_tf32(v.x); v.y = to_tf32(v.y); v.z = to_tf32(v.z); v.w = to_tf32(v.w);
    *(float4*)&o[((b * 128 + h) * 64 + c) * 128 + w4 * 4] = v;
}

__global__ __launch_bounds__(256)
void t2_kernel(const float* __restrict__ x, float* __restrict__ o)
{
    __shared__ float tile[32][33];
    int tx = threadIdx.x, ty = threadIdx.y;
    int w0 = blockIdx.x * 32;
    int c0 = blockIdx.y * 32;
    int bh = blockIdx.z;
    int b = bh >> 7, h = bh & 127;
    int xb = b * CHW_ + h * 128;
#pragma unroll
    for (int i = 0; i < 4; i++)
        tile[ty + 8 * i][tx] = x[xb + (c0 + ty + 8 * i) * HW_ + w0 + tx];
    __syncthreads();
    int ob = b * CHW_ + h * 64;
#pragma unroll
    for (int i = 0; i < 4; i++)
        o[ob + (w0 + ty + 8 * i) * 8192 + c0 + tx] = to_tf32(tile[tx][ty + 8 * i]);
}

// ---------------- conv1x1 via tf32 MMA: t = w_hwc @ xr + b ----------------
// grid: (64 px-tiles of 256, 3 ocb, 8 b)
__global__ __launch_bounds__(256)
void gemm1x1_mma(const float* __restrict__ xr, const float* __restrict__ wprep,
                 const float* __restrict__ bias, float* __restrict__ t)
{
    constexpr int SKB = 264;
    constexpr int ASLAB = 576;       // 8k x 72
    constexpr int BSLAB = 8 * SKB;   // 2112
    __shared__ __align__(16) float sm[2 * (ASLAB + BSLAB)];
    float* wsm = sm;
    float* bsm = sm + 2 * ASLAB;

    const int tid = threadIdx.x;
    const int p0 = blockIdx.x * 256;
    const int oc0 = blockIdx.y * 64;
    const int b = blockIdx.z;
    const float* wsrc = wprep + blockIdx.y * 4096;
    const float* xsrc = xr + b * CHW_ + p0;

    auto stage = [&](int slab, int bufi) {
        uint32_t dA = (uint32_t)__cvta_generic_to_shared(wsm + bufi * ASLAB);
        uint32_t dB = (uint32_t)__cvta_generic_to_shared(bsm + bufi * BSLAB);
        const float* sA = wsrc + slab * 512;
        for (int i = tid; i < 128; i += 256) {
            int k = i >> 4, j = i & 15;
            cp_async16(dA + (uint32_t)((k * 72 + 4 * j) * 4), sA + i * 4, true);
        }
        const float* sB = xsrc + slab * 8 * HW_;
        for (int i = tid; i < 512; i += 256) {
            int k = i >> 6, j = i & 63;
            cp_async16(dB + (uint32_t)((k * SKB + 4 * j) * 4), sB + k * HW_ + 4 * j, true);
        }
        cp_commit();
    };

    stage(0, 0);

    const int lane = tid & 31, warp = tid >> 5;
    const int g = lane >> 2, tq = lane & 3;
    const int cb0 = warp * 32;

    float acc[4][4][4];
#pragma unroll
    for (int mt = 0; mt < 4; mt++)
#pragma unroll
        for (int nt = 0; nt < 4; nt++)
#pragma unroll
            for (int q = 0; q < 4; q++) acc[mt][nt][q] = 0.f;

    const uint32_t* wsu = (const uint32_t*)wsm;
    const uint32_t* bsu = (const uint32_t*)bsm;

    int buf = 0;
    for (int slab = 0; slab < 8; slab++) {
        cp_wait0();
        __syncthreads();
        if (slab + 1 < 8) stage(slab + 1, buf ^ 1);

        const uint32_t* wa = wsu + buf * ASLAB;
        const uint32_t* bb = bsu + buf * BSLAB;
        uint32_t au[4][4];
#pragma unroll
        for (int mt = 0; mt < 4; mt++) {
            int base = tq * 72 + 16 * mt + g;
            au[mt][0] = wa[base];
            au[mt][1] = wa[base + 8];
            au[mt][2] = wa[base + 288];
            au[mt][3] = wa[base + 296];
        }
        int bbase = tq * SKB + cb0 + g;
#pragma unroll
        for (int nt = 0; nt < 4; nt++) {
            uint32_t b0 = bb[bbase + 8 * nt];
            uint32_t b1 = bb[bbase + 4 * SKB + 8 * nt];
#pragma unroll
            for (int mt = 0; mt < 4; mt++)
                mma_tf32(acc[mt][nt], au[mt], b0, b1);
        }
        buf ^= 1;
    }

#pragma unroll
    for (int mt = 0; mt < 4; mt++) {
        const int oc = oc0 + 16 * mt + g;
        const float bv0 = bias[oc], bv1 = bias[oc + 8];
#pragma unroll
        for (int nt = 0; nt < 4; nt++) {
            const int pc = p0 + cb0 + 8 * nt + 2 * tq;
            int e0 = b * GBS_ + oc * HW_ + pc;
            int e1 = e0 + 8 * HW_;
            *(float2*)&t[e0] = make_float2(acc[mt][nt][0] + bv0, acc[mt][nt][1] + bv0);
            *(float2*)&t[e1] = make_float2(acc[mt][nt][2] + bv1, acc[mt][nt][3] + bv1);
        }
    }
}

// ---------------- depthwise 3x3 v2 (16x128 tile, 256 thr, float4) ----------------
__global__ __launch_bounds__(256)
void dwconv_v2_kernel(const float* __restrict__ t, const float* __restrict__ w_dw,
                      const float* __restrict__ b_dw, float* __restrict__ g)
{
    __shared__ float xs[18][136];
    const int tid = threadIdx.x;
    const int s1_0 = blockIdx.x * 16;
    const int og = blockIdx.y, b = blockIdx.z;
    const int base = b * GBS_ + og * HW_;

    if (tid < 36) {
        int row = tid >> 1, side = tid & 1;
        xs[row][side ? 132 : 3] = 0.f;
    }
    for (int idx = tid; idx < 576; idx += 256) {
        int row = idx >> 5, q = idx & 31;
        int s1g = s1_0 - 1 + row;
        float4 v = make_float4(0.f, 0.f, 0.f, 0.f);
        if (s1g >= 0 && s1g < 128)
            v = *(const float4*)&t[base + s1g * 128 + q * 4];
        xs[row][4 + q * 4 + 0] = v.x;
        xs[row][4 + q * 4 + 1] = v.y;
        xs[row][4 + q * 4 + 2] = v.z;
        xs[row][4 + q * 4 + 3] = v.w;
    }
    __syncthreads();

    float w[9];
#pragma unroll
    for (int k = 0; k < 9; k++) w[k] = w_dw[og * 9 + k];
    float bb = b_dw[og];

    const int r = tid >> 4, cb = (tid & 15) * 8;
    float o[8];
#pragma unroll
    for (int j = 0; j < 8; j++) {
        float s = bb;
#pragma unroll
        for (int dr = 0; dr < 3; dr++)
#pragma unroll
            for (int dc = 0; dc < 3; dc++)
                s += w[dr * 3 + dc] * xs[r + dr][cb + j + 3 + dc];
        o[j] = s;
    }
    float* op = &g[base + (s1_0 + r) * 128 + cb];
    *(float4*)op = make_float4(o[0], o[1], o[2], o[3]);
    *(float4*)(op + 4) = make_float4(o[4], o[5], o[6], o[7]);
}

// ---------------- tf32 tensor-core implicit-GEMM 3x3 conv ----------------
template<int C, int S1, int W, int OC, int OUTV, int RES, int RND>
__global__ __launch_bounds__(256, 2)
void conv3x3_mma(const float* __restrict__ x, const float* __restrict__ wprep,
                 const float* __restrict__ bias, float* __restrict__ out,
                 const float* __restrict__ res,
                 int o_oc, int o_s1, int o_s2, int o_b)
{
    constexpr int TR = 256 / W;
    constexpr int NS = C / 8;
    constexpr int RW = W + 8;
    constexpr int SK = (TR + 2) * RW + 8;
    constexpr int ASLAB = 9 * 8 * 72;
    constexpr int BSLAB = 8 * SK;
    constexpr int CH = W / 4;

    extern __shared__ float sm[];
    float* wsm = sm;
    float* bsm = sm + 2 * ASLAB;

    const int tid = threadIdx.x;
    const int s1_0 = blockIdx.x * TR;
    const int oc0 = blockIdx.y * 64;
    const int b = blockIdx.z;
    const int xb = b * (C * S1 * W);
    const float* wsrc = wprep + blockIdx.y * (NS * 4608);

    for (int i = tid; i < 2 * 8 * (TR + 2) * 2; i += 256) {
        int side = i & 1; int rest = i >> 1;
        int row = rest % (TR + 2); rest /= (TR + 2);
        int k = rest & 7; int bufi = rest >> 3;
        bsm[bufi * BSLAB + k * SK + row * RW + (side ? (W + 4) : 3)] = 0.f;
    }

    auto stageA = [&](int slab, int bufi) {
        uint32_t dst0 = (uint32_t)__cvta_generic_to_shared(wsm + bufi * ASLAB);
        const float* src = wsrc + slab * 4608;
        for (int i = tid; i < 1152; i += 256) {
            int j = i & 15; int k = (i >> 4) & 7; int s = i >> 7;
            cp_async16(dst0 + (uint32_t)((s * 576 + k * 72 + 4 * j) * 4), src + i * 4, true);
        }
    };
    auto stageB = [&](int slab, int bufi) {
        uint32_t dst0 = (uint32_t)__cvta_generic_to_shared(bsm + bufi * BSLAB);
        const float* src = x + xb + slab * 8 * (S1 * W);
        for (int i = tid; i < 8 * (TR + 2) * CH; i += 256) {
            int j = i % CH; int rest = i / CH;
            int row = rest % (TR + 2); int k = rest / (TR + 2);
            int s1g = s1_0 - 1 + row;
            bool v = (s1g >= 0) && (s1g < S1);
            int s1c = v ? s1g : 0;
            cp_async16(dst0 + (uint32_t)((k * SK + row * RW + 4 + 4 * j) * 4),
                       src + k * (S1 * W) + s1c * W + 4 * j, v);
        }
    };

    stageA(0, 0); stageB(0, 0); cp_commit();

    const int lane = tid & 31, warp = tid >> 5;
    const int g = lane >> 2, tq = lane & 3;
    const int rbase = (warp * 32) / W;
    const int cb0 = (warp * 32) % W;

    float acc[4][4][4];
#pragma unroll
    for (int mt = 0; mt < 4; mt++)
#pragma unroll
        for (int nt = 0; nt < 4; nt++)
#pragma unroll
            for (int q = 0; q < 4; q++) acc[mt][nt][q] = 0.f;

    const uint32_t* wsu = (const uint32_t*)wsm;
    const uint32_t* bsu = (const uint32_t*)bsm;

    int buf = 0;
    for (int slab = 0; slab < NS; slab++) {
        cp_wait0();
        __syncthreads();
        if (slab + 1 < NS) { stageA(slab + 1, buf ^ 1); stageB(slab + 1, buf ^ 1); cp_commit(); }

        const uint32_t* wa = wsu + buf * ASLAB;
        const uint32_t* bb = bsu + buf * BSLAB;
#pragma unroll
        for (int dr = 0; dr < 3; dr++) {
#pragma unroll
            for (int dc = 0; dc < 3; dc++) {
                const int s = dr * 3 + dc;
                uint32_t au[4][4];
#pragma unroll
                for (int mt = 0; mt < 4; mt++) {
                    int base = s * 576 + tq * 72 + 16 * mt + g;
                    au[mt][0] = wa[base];
                    au[mt][1] = wa[base + 8];
                    au[mt][2] = wa[base + 288];
                    au[mt][3] = wa[base + 296];
                }
                int bbase = tq * SK + (rbase + dr) * RW + cb0 + g + dc + 3;
#pragma unroll
                for (int nt = 0; nt < 4; nt++) {
                    uint32_t b0 = bb[bbase + 8 * nt];
                    uint32_t b1 = bb[bbase + 4 * SK + 8 * nt];
#pragma unroll
                    for (int mt = 0; mt < 4; mt++)
                        mma_tf32(acc[mt][nt], au[mt], b0, b1);
                }
            }
        }
        buf ^= 1;
    }

    const int s1 = s1_0 + rbase;
#pragma unroll
    for (int mt = 0; mt < 4; mt++) {
        const int oc = oc0 + 16 * mt + g;
        const float bv0 = bias[oc], bv1 = bias[oc + 8];
#pragma unroll
        for (int nt = 0; nt < 4; nt++) {
            const int pc = cb0 + 8 * nt + 2 * tq;
            float v0 = lrelu(acc[mt][nt][0] + bv0);
            float v1 = lrelu(acc[mt][nt][1] + bv0);
            float v2 = lrelu(acc[mt][nt][2] + bv1);
            float v3 = lrelu(acc[mt][nt][3] + bv1);
            if (OUTV == 0) {
                int e0 = b * o_b + oc * o_oc + s1 * o_s1 + pc;
                int e1 = e0 + 8 * o_oc;
                if (RES) {
                    v0 += res[e0]; v1 += res[e0 + 1];
                    v2 += res[e1]; v3 += res[e1 + 1];
                }
                if (RND) {
                    v0 = to_tf32(v0); v1 = to_tf32(v1);
                    v2 = to_tf32(v2); v3 = to_tf32(v3);
                }
                *(float2*)&out[e0] = make_float2(v0, v1);
                *(float2*)&out[e1] = make_float2(v2, v3);
            } else {
                int e = b * o_b + s1 * o_s1 + oc;
                out[e + pc * o_s2] = v0;
                out[e + (pc + 1) * o_s2] = v1;
                out[e + 8 + pc * o_s2] = v2;
                out[e + 8 + (pc + 1) * o_s2] = v3;
            }
        }
    }
}

// ---------------- fused gate + folded down-conv + residual (f32x2) ----------------
__global__ __launch_bounds__(128)
void down_kernel_v3(const float* __restrict__ x, const float* __restrict__ xhw,
                    const float* __restrict__ xcw, const float* __restrict__ xhc,
                    const float* __restrict__ g,
                    const float* __restrict__ wd, const float* __restrict__ b_down,
                    float* __restrict__ mid)
{
    __shared__ __align__(16) float ws[4][64][16];
    const int tid = threadIdx.x;
    const int p4 = (blockIdx.x * 128 + tid) * 4;
    const int oc0 = blockIdx.y * 16;
    const int b = blockIdx.z;

    for (int idx = tid; idx < 4096; idx += 128) {
        int s = idx >> 10;
        int rem = idx & 1023;
        int c = rem >> 4, i = rem & 15;
        ws[s][c][i] = wd[s * 4096 + c * 64 + oc0 + i];
    }
    __syncthreads();

    ull acc2[8][4];
#pragma unroll
    for (int i = 0; i < 8; i++)
#pragma unroll
        for (int j = 0; j < 4; j++) acc2[i][j] = 0ull;

    const int xb = b * CHW_ + p4;
    const int gb = b * GBS_ + p4;
    for (int c = 0; c < 64; c++) {
        int off = xb + c * HW_;
        float4 a  = *(const float4*)&x[off];
        float4 h  = *(const float4*)&xhw[off];
        float4 cw = *(const float4*)&xcw[off];
        float4 hc = *(const float4*)&xhc[off];
        float4 g0 = *(const float4*)&g[gb + c * HW_];
        float4 g1 = *(const float4*)&g[gb + (64 + c) * HW_];
        float4 g2 = *(const float4*)&g[gb + (128 + c) * HW_];
        h.x *= g0.x; h.y *= g0.y; h.z *= g0.z; h.w *= g0.w;
        cw.x *= g1.x; cw.y *= g1.y; cw.z *= g1.z; cw.w *= g1.w;
        hc.x *= g2.x; hc.y *= g2.y; hc.z *= g2.z; hc.w *= g2.w;
        ull ap[4]  = { pack2b(a.x),  pack2b(a.y),  pack2b(a.z),  pack2b(a.w)  };
        ull hp[4]  = { pack2b(h.x),  pack2b(h.y),  pack2b(h.z),  pack2b(h.w)  };
        ull cp[4]  = { pack2b(cw.x), pack2b(cw.y), pack2b(cw.z), pack2b(cw.w) };
        ull hcp[4] = { pack2b(hc.x), pack2b(hc.y), pack2b(hc.z), pack2b(hc.w) };
#pragma unroll
        for (int op = 0; op < 8; op++) {
            ull w0 = *(const ull*)&ws[0][c][op * 2];
            ull w1 = *(const ull*)&ws[1][c][op * 2];
            ull w2 = *(const ull*)&ws[2][c][op * 2];
            ull w3 = *(const ull*)&ws[3][c][op * 2];
#pragma unroll
            for (int j = 0; j < 4; j++) {
                ffma2(acc2[op][j], w0, ap[j]);
                ffma2(acc2[op][j], w1, hp[j]);
                ffma2(acc2[op][j], w2, cp[j]);
                ffma2(acc2[op][j], w3, hcp[j]);
            }
        }
    }
#pragma unroll
    for (int op = 0; op < 8; op++) {
        int oc = oc0 + 2 * op;
        float b0 = b_down[oc], b1 = b_down[oc + 1];
        float4 x0 = *(const float4*)&x[b * CHW_ + oc * HW_ + p4];
        float4 x1 = *(const float4*)&x[b * CHW_ + (oc + 1) * HW_ + p4];
        float2 p0 = unpack2(acc2[op][0]), p1 = unpack2(acc2[op][1]);
        float2 p2 = unpack2(acc2[op][2]), p3 = unpack2(acc2[op][3]);
        float4 v0 = make_float4(to_tf32(p0.x + b0 + x0.x), to_tf32(p1.x + b0 + x0.y),
                                to_tf32(p2.x + b0 + x0.z), to_tf32(p3.x + b0 + x0.w));
        float4 v1 = make_float4(to_tf32(p0.y + b1 + x1.x), to_tf32(p1.y + b1 + x1.y),
                                to_tf32(p2.y + b1 + x1.z), to_tf32(p3.y + b1 + x1.w));
        *(float4*)&mid[b * CHW_ + oc * HW_ + p4] = v0;
        *(float4*)&mid[b * CHW_ + (oc + 1) * HW_ + p4] = v1;
    }
}

// ---------------- stream/event pool (created once, on the uncaptured correctness call) ----------------
struct AsyncCtx {
    cudaStream_t s1, s2, s3;
    cudaEvent_t eRoot, eR4, eCw, eHc, eHw;
    bool ok;
    AsyncCtx() {
        ok = true;
        ok &= (cudaStreamCreateWithFlags(&s1, cudaStreamNonBlocking) == cudaSuccess);
        ok &= (cudaStreamCreateWithFlags(&s2, cudaStreamNonBlocking) == cudaSuccess);
        ok &= (cudaStreamCreateWithFlags(&s3, cudaStreamNonBlocking) == cudaSuccess);
        ok &= (cudaEventCreateWithFlags(&eRoot, cudaEventDisableTiming) == cudaSuccess);
        ok &= (cudaEventCreateWithFlags(&eR4, cudaEventDisableTiming) == cudaSuccess);
        ok &= (cudaEventCreateWithFlags(&eCw, cudaEventDisableTiming) == cudaSuccess);
        ok &= (cudaEventCreateWithFlags(&eHc, cudaEventDisableTiming) == cudaSuccess);
        ok &= (cudaEventCreateWithFlags(&eHw, cudaEventDisableTiming) == cudaSuccess);
    }
};

// ---------------- launch ----------------
extern "C" void kernel_launch(void* const* d_in, const int* in_sizes, int n_in,
                              void* d_out, int out_size)
{
    const float* x      = (const float*)d_in[0];
    const float* w_hwc  = (const float*)d_in[1];
    const float* b_hwc  = (const float*)d_in[2];
    const float* w_dw   = (const float*)d_in[3];
    const float* b_dw   = (const float*)d_in[4];
    const float* w_hw   = (const float*)d_in[5];
    const float* b_hw   = (const float*)d_in[6];
    const float* w_cw   = (const float*)d_in[7];
    const float* b_cw   = (const float*)d_in[8];
    const float* w_hc   = (const float*)d_in[9];
    const float* b_hc   = (const float*)d_in[10];
    const float* w_down = (const float*)d_in[11];
    const float* b_down = (const float*)d_in[12];
    const float* w_l1   = (const float*)d_in[13];
    const float* b_l1   = (const float*)d_in[14];
    const float* w_l2   = (const float*)d_in[15];
    const float* b_l2   = (const float*)d_in[16];
    float* out = (float*)d_out;

    float *t, *g, *xt1, *xt2, *xr, *xhw, *xcw, *xhc, *mid, *o1, *wd, *wr, *w1;
    cudaGetSymbolAddress((void**)&t,   d_t);
    cudaGetSymbolAddress((void**)&g,   d_g);
    cudaGetSymbolAddress((void**)&xt1, d_xt1);
    cudaGetSymbolAddress((void**)&xt2, d_xt2);
    cudaGetSymbolAddress((void**)&xr,  d_xr);
    cudaGetSymbolAddress((void**)&xhw, d_xhw);
    cudaGetSymbolAddress((void**)&xcw, d_xcw);
    cudaGetSymbolAddress((void**)&xhc, d_xhc);
    cudaGetSymbolAddress((void**)&mid, d_mid);
    cudaGetSymbolAddress((void**)&o1,  d_o1);
    cudaGetSymbolAddress((void**)&wd,  d_wd);
    cudaGetSymbolAddress((void**)&wr,  d_wr);
    cudaGetSymbolAddress((void**)&w1,  d_w1);

    float* wr_hw = wr;
    float* wr_cw = wr + 36864;
    float* wr_hc = wr + 184320;
    float* wr_l1 = wr + 331776;
    float* wr_l2 = wr + 368640;

    const int SMEM_W128 = (2 * 5184 + 2 * (8 * ((2 + 2) * 136 + 8))) * 4;
    const int SMEM_W64  = (2 * 5184 + 2 * (8 * ((4 + 2) * 72 + 8))) * 4;

    cudaFuncSetAttribute((const void*)conv3x3_mma<64, 128, 128, 64, 0, 0, 0>,
                         cudaFuncAttributeMaxDynamicSharedMemorySize, SMEM_W128);
    cudaFuncSetAttribute((const void*)conv3x3_mma<128, 64, 128, 128, 0, 0, 0>,
                         cudaFuncAttributeMaxDynamicSharedMemorySize, SMEM_W128);
    cudaFuncSetAttribute((const void*)conv3x3_mma<128, 128, 64, 128, 1, 0, 0>,
                         cudaFuncAttributeMaxDynamicSharedMemorySize, SMEM_W64);
    cudaFuncSetAttribute((const void*)conv3x3_mma<64, 128, 128, 64, 0, 0, 1>,
                         cudaFuncAttributeMaxDynamicSharedMemorySize, SMEM_W128);
    cudaFuncSetAttribute((const void*)conv3x3_mma<64, 128, 128, 64, 0, 1, 0>,
                         cudaFuncAttributeMaxDynamicSharedMemorySize, SMEM_W128);

    static AsyncCtx ctx;   // created on the (uncaptured) correctness call; same graph every call

    if (ctx.ok) {
        cudaStream_t m = 0;
        cudaEventRecord(ctx.eRoot, m);
        cudaStreamWaitEvent(ctx.s1, ctx.eRoot, 0);
        cudaStreamWaitEvent(ctx.s2, ctx.eRoot, 0);
        cudaStreamWaitEvent(ctx.s3, ctx.eRoot, 0);

        // s1: cw branch
        prep_w_kernel<<<576, 256, 0, ctx.s1>>>(w_cw, wr_cw, 128, 128);
        t1_kernel<<<8192, 256, 0, ctx.s1>>>(x, xt1);
        conv3x3_mma<128, 64, 128, 128, 0, 0, 0><<<dim3(32, 2, 8), 256, SMEM_W128, ctx.s1>>>(
            xt1, wr_cw, b_cw, xcw, nullptr, 128, HW_, 1, CHW_);
        cudaEventRecord(ctx.eCw, ctx.s1);

        // s2: hc branch
        prep_w_kernel<<<576, 256, 0, ctx.s2>>>(w_hc, wr_hc, 128, 128);
        t2_kernel<<<dim3(4, 2, 1024), dim3(32, 8), 0, ctx.s2>>>(x, xt2);
        conv3x3_mma<128, 128, 64, 128, 1, 0, 0><<<dim3(32, 2, 8), 256, SMEM_W64, ctx.s2>>>(
            xt2, wr_hc, b_hc, xhc, nullptr, 1, 128, HW_, CHW_);
        cudaEventRecord(ctx.eHc, ctx.s2);

        // s3: hw branch + misc preps
        prep_w_kernel<<<144, 256, 0, ctx.s3>>>(w_hw, wr_hw, 64, 64);
        prep_wd_kernel<<<64, 256, 0, ctx.s3>>>(w_down, wd);
        prep_w_kernel<<<144, 256, 0, ctx.s3>>>(w_l1, wr_l1, 64, 64);
        prep_w_kernel<<<144, 256, 0, ctx.s3>>>(w_l2, wr_l2, 64, 64);

        // main: gate path
        prep_w1_kernel<<<48, 256, 0, m>>>(w_hwc, w1);
        round4_kernel<<<8192, 256, 0, m>>>(x, xr);
        cudaEventRecord(ctx.eR4, m);
        cudaStreamWaitEvent(ctx.s3, ctx.eR4, 0);
        conv3x3_mma<64, 128, 128, 64, 0, 0, 0><<<dim3(64, 1, 8), 256, SMEM_W128, ctx.s3>>>(
            xr, wr_hw, b_hw, xhw, nullptr, HW_, 128, 1, CHW_);
        cudaEventRecord(ctx.eHw, ctx.s3);

        gemm1x1_mma<<<dim3(64, 3, 8), 256, 0, m>>>(xr, w1, b_hwc, t);
        dwconv_v2_kernel<<<dim3(8, 192, 8), 256, 0, m>>>(t, w_dw, b_dw, g);

        // join
        cudaStreamWaitEvent(m, ctx.eCw, 0);
        cudaStreamWaitEvent(m, ctx.eHc, 0);
        cudaStreamWaitEvent(m, ctx.eHw, 0);

        down_kernel_v3<<<dim3(32, 4, 8), 128, 0, m>>>(x, xhw, xcw, xhc, g, wd, b_down, mid);
        conv3x3_mma<64, 128, 128, 64, 0, 0, 1><<<dim3(64, 1, 8), 256, SMEM_W128, m>>>(
            mid, wr_l1, b_l1, o1, nullptr, HW_, 128, 1, CHW_);
        conv3x3_mma<64, 128, 128, 64, 0, 1, 0><<<dim3(64, 1, 8), 256, SMEM_W128, m>>>(
            o1, wr_l2, b_l2, out, x, HW_, 128, 1, CHW_);
    } else {
        // serial fallback
        prep_wd_kernel<<<64, 256>>>(w_down, wd);
        prep_w_kernel<<<144, 256>>>(w_hw, wr_hw, 64, 64);
        prep_w_kernel<<<576, 256>>>(w_cw, wr_cw, 128, 128);
        prep_w_kernel<<<576, 256>>>(w_hc, wr_hc, 128, 128);
        prep_w_kernel<<<144, 256>>>(w_l1, wr_l1, 64, 64);
        prep_w_kernel<<<144, 256>>>(w_l2, wr_l2, 64, 64);
        prep_w1_kernel<<<48, 256>>>(w_hwc, w1);
        round4_kernel<<<8192, 256>>>(x, xr);
        t1_kernel<<<8192, 256>>>(x, xt1);
        t2_kernel<<<dim3(4, 2, 1024), dim3(32, 8)>>>(x, xt2);
        gemm1x1_mma<<<dim3(64, 3, 8), 256>>>(xr, w1, b_hwc, t);
        dwconv_v2_kernel<<<dim3(8, 192, 8), 256>>>(t, w_dw, b_dw, g);
        conv3x3_mma<64, 128, 128, 64, 0, 0, 0><<<dim3(64, 1, 8), 256, SMEM_W128>>>(
            xr, wr_hw, b_hw, xhw, nullptr, HW_, 128, 1, CHW_);
        conv3x3_mma<128, 64, 128, 128, 0, 0, 0><<<dim3(32, 2, 8), 256, SMEM_W128>>>(
            xt1, wr_cw, b_cw, xcw, nullptr, 128, HW_, 1, CHW_);
        conv3x3_mma<128, 128, 64, 128, 1, 0, 0><<<dim3(32, 2, 8), 256, SMEM_W64>>>(
            xt2, wr_hc, b_hc, xhc, nullptr, 1, 128, HW_, CHW_);
        down_kernel_v3<<<dim3(32, 4, 8), 128>>>(x, xhw, xcw, xhc, g, wd, b_down, mid);
        conv3x3_mma<64, 128, 128, 64, 0, 0, 1><<<dim3(64, 1, 8), 256, SMEM_W128>>>(
            mid, wr_l1, b_l1, o1, nullptr, HW_, 128, 1, CHW_);
        conv3x3_mma<64, 128, 128, 64, 0, 1, 0><<<dim3(64, 1, 8), 256, SMEM_W128>>>(
            o1, wr_l2, b_l2, out, x, HW_, 128, 1, CHW_);
    }
}

// round 8
// speedup vs baseline: 8.4728x; 1.3739x over previous
#include <cuda_runtime.h>
#include <cuda_fp16.h>
#include <cstdint>

// B=8, C=64, T=128
#define HW_   16384
#define CHW_  1048576
#define GBS_  3145728

typedef unsigned long long ull;

// ---------------- scratch ----------------
__device__ float d_t  [25165824];  // [8,192,128,128] conv1x1 out (fp32)
__device__ float d_g  [25165824];  // [8,192,128,128] gates (fp32)
__device__ float d_xt1[8388608];   // half2 [b][h/2][c][w]
__device__ float d_xt2[8388608];   // half2 [b][w/2][h][c]
__device__ float d_xr [8388608];   // half2 [b][c/2][h][w]
__device__ float d_xhw[8388608];   // fp32 planar
__device__ float d_xcw[8388608];
__device__ float d_xhc[8388608];
__device__ float d_mid[8388608];   // half2 [b][c/2][h][w]
__device__ float d_o1 [8388608];   // half2 [b][c/2][h][w]
__device__ float d_wd [16384];     // folded down weights [4][64(c)][64(o)] fp32
__device__ float d_wr [405504];    // fp16 conv weights (as halves)
__device__ float d_w1 [12288];     // fp16 1x1 weights

__device__ __forceinline__ float lrelu(float v) { return v > 0.f ? v : 0.1f * v; }

__device__ __forceinline__ void cp_async16(uint32_t dst, const void* src, bool valid) {
    int sz = valid ? 16 : 0;
    asm volatile("cp.async.cg.shared.global [%0], [%1], 16, %2;\n"
                 :: "r"(dst), "l"(src), "r"(sz));
}
__device__ __forceinline__ void cp_commit() { asm volatile("cp.async.commit_group;\n"); }
__device__ __forceinline__ void cp_wait0()  { asm volatile("cp.async.wait_group 0;\n"); }

// ---------------- f32x2 packed helpers ----------------
__device__ __forceinline__ ull pack2b(float v) {
    ull r; asm("mov.b64 %0, {%1,%1};" : "=l"(r) : "f"(v)); return r;
}
__device__ __forceinline__ float2 unpack2(ull v) {
    float2 r; asm("mov.b64 {%0,%1}, %2;" : "=f"(r.x), "=f"(r.y) : "l"(v)); return r;
}
__device__ __forceinline__ void ffma2(ull& d, ull a, ull b) {
    asm("fma.rn.f32x2 %0, %1, %2, %0;" : "+l"(d) : "l"(a), "l"(b));
}

// ---------------- fp16 mma (m16n8k16, fp32 accum) ----------------
__device__ __forceinline__ void mma_f16(float* d, const uint32_t* a,
                                        uint32_t b0, uint32_t b1) {
    asm volatile("mma.sync.aligned.m16n8k16.row.col.f32.f16.f16.f32 "
                 "{%0,%1,%2,%3}, {%4,%5,%6,%7}, {%8,%9}, {%0,%1,%2,%3};"
                 : "+f"(d[0]), "+f"(d[1]), "+f"(d[2]), "+f"(d[3])
                 : "r"(a[0]), "r"(a[1]), "r"(a[2]), "r"(a[3]), "r"(b0), "r"(b1));
}

// ---------------- prep: fold w_down ----------------
__global__ void prep_wd_kernel(const float* __restrict__ w_down, float* __restrict__ wd)
{
    int idx = blockIdx.x * 256 + threadIdx.x;
    if (idx >= 16384) return;
    int s = idx >> 12;
    int rem = idx & 4095;
    int c = rem >> 6;
    int o = rem & 63;
    auto W = [&](int i, int ky, int kx) { return w_down[((o * 128 + i) * 2 + ky) * 2 + kx]; };
    float v = 0.f;
    if (s == 0) v = W(2 * c, 0, 0) + W(2 * c + 1, 1, 1);
    else if (s == 1) v = W(2 * c, 0, 1) + W(2 * c + 1, 1, 0);
    else if (s == 2) v = W(2 * c, 1, 0) + W(2 * c + 1, 0, 1);
    else v = W(2 * c, 1, 1) + W(2 * c + 1, 0, 0);
    wd[s * 4096 + c * 64 + o] = v;
}

// ---------------- prep: fp16 conv weights ----------------
// dst halves: [ocb][slab(C/16)][s(9)][kp(8)][ocl(64)][klo(2)]
// PERM: tile row r holds logical oc 2r (r<8) / 2(r-8)+1 (r>=8) within each 16-group
__global__ void prep_wf_kernel(const float* __restrict__ src, __half* __restrict__ dst,
                               int OC, int C, int PERM)
{
    int idx = blockIdx.x * 256 + threadIdx.x;
    int total = OC * C * 9;
    if (idx >= total) return;
    int klo = idx & 1;
    int ocl = (idx >> 1) & 63;
    int kp  = (idx >> 7) & 7;
    int s   = (idx >> 10) % 9;
    int rest = idx / 9216;
    int NS = C >> 4;
    int slab = rest % NS;
    int ocb = rest / NS;
    int l = ocl;
    if (PERM) {
        int grp = ocl >> 4, r = ocl & 15;
        l = grp * 16 + ((r < 8) ? 2 * r : 2 * (r - 8) + 1);
    }
    int k = slab * 16 + 2 * kp + klo;
    dst[idx] = __float2half_rn(src[((ocb * 64 + l) * C + k) * 9 + s]);
}

// ---------------- prep: fp16 1x1 weights [ocb(3)][slab(4)][kp(8)][ocl(64)][klo(2)] ----------------
__global__ void prep_w1f_kernel(const float* __restrict__ src, __half* __restrict__ dst)
{
    int idx = blockIdx.x * 256 + threadIdx.x;
    if (idx >= 12288) return;
    int klo = idx & 1;
    int ocl = (idx >> 1) & 63;
    int kp  = (idx >> 7) & 7;
    int slab = (idx >> 10) & 3;
    int ocb = idx >> 12;
    dst[idx] = __float2half_rn(src[(ocb * 64 + ocl) * 64 + slab * 16 + 2 * kp + klo]);
}

// ---------------- x -> half2 channel-pair interleave ----------------
__global__ __launch_bounds__(256)
void pairf_kernel(const float* __restrict__ x, uint32_t* __restrict__ o)
{
    int i = blockIdx.x * 256 + threadIdx.x;   // 1048576 threads
    int p4 = (i & 4095) * 4;
    int cp = (i >> 12) & 31;
    int b = i >> 17;
    float4 a = *(const float4*)&x[(b * 64 + 2 * cp) * HW_ + p4];
    float4 c = *(const float4*)&x[(b * 64 + 2 * cp + 1) * HW_ + p4];
    __half2 h0 = __floats2half2_rn(a.x, c.x);
    __half2 h1 = __floats2half2_rn(a.y, c.y);
    __half2 h2 = __floats2half2_rn(a.z, c.z);
    __half2 h3 = __floats2half2_rn(a.w, c.w);
    uint4 u = make_uint4(*(uint32_t*)&h0, *(uint32_t*)&h1, *(uint32_t*)&h2, *(uint32_t*)&h3);
    *(uint4*)&o[(b * 32 + cp) * HW_ + p4] = u;
}

// ---------------- t1: half2 [b][h/2][c][w], pairs over h ----------------
__global__ __launch_bounds__(256)
void t1f_kernel(const float* __restrict__ x, uint32_t* __restrict__ o)
{
    int i = blockIdx.x * 256 + threadIdx.x;   // 1048576
    int w4 = i & 31;
    int c = (i >> 5) & 63;
    int hp = (i >> 11) & 63;
    int b = i >> 17;
    const float* plane = x + (b * 64 + c) * HW_;
    float4 a = *(const float4*)&plane[(2 * hp) * 128 + 4 * w4];
    float4 d = *(const float4*)&plane[(2 * hp + 1) * 128 + 4 * w4];
    __half2 h0 = __floats2half2_rn(a.x, d.x);
    __half2 h1 = __floats2half2_rn(a.y, d.y);
    __half2 h2 = __floats2half2_rn(a.z, d.z);
    __half2 h3 = __floats2half2_rn(a.w, d.w);
    uint4 u = make_uint4(*(uint32_t*)&h0, *(uint32_t*)&h1, *(uint32_t*)&h2, *(uint32_t*)&h3);
    *(uint4*)&o[((b * 64 + hp) * 64 + c) * 128 + 4 * w4] = u;
}

// ---------------- t2: half2 [b][w/2][h][c], pairs over w ----------------
__global__ __launch_bounds__(256)
void t2f_kernel(const float* __restrict__ x, uint32_t* __restrict__ o)
{
    __shared__ float tile[32][33];
    int tx = threadIdx.x, ty = threadIdx.y;
    int w0 = blockIdx.x * 32;
    int c0 = blockIdx.y * 32;
    int bh = blockIdx.z;
    int b = bh >> 7, hrow = bh & 127;
    int xb = b * CHW_ + hrow * 128;
#pragma unroll
    for (int i = 0; i < 4; i++)
        tile[ty + 8 * i][tx] = x[xb + (c0 + ty + 8 * i) * HW_ + w0 + tx];
    __syncthreads();
#pragma unroll
    for (int j = 0; j < 2; j++) {
        int wl = ty + 8 * j;   // 0..15
        __half2 hv = __floats2half2_rn(tile[tx][2 * wl], tile[tx][2 * wl + 1]);
        o[((b * 64 + (w0 >> 1) + wl) * 128 + hrow) * 64 + c0 + tx] = *(uint32_t*)&hv;
    }
}

// ---------------- conv1x1 via fp16 MMA: t = w_hwc @ x + b (fp32 out) ----------------
__global__ __launch_bounds__(256)
void gemm1x1_f16(const uint32_t* __restrict__ xh2, const __half* __restrict__ wprep,
                 const float* __restrict__ bias, float* __restrict__ t)
{
    constexpr int SKB = 264;
    constexpr int ASLAB = 576;       // half2 units: 8kp x 72
    constexpr int BSLAB = 8 * SKB;
    __shared__ __align__(16) uint32_t sm[2 * (ASLAB + BSLAB)];
    uint32_t* wsm = sm;
    uint32_t* bsm = sm + 2 * ASLAB;

    const int tid = threadIdx.x;
    const int p0 = blockIdx.x * 256;
    const int oc0 = blockIdx.y * 64;
    const int b = blockIdx.z;
    const __half* wsrc = wprep + blockIdx.y * 4096;
    const uint32_t* xsrc = xh2 + b * (32 * HW_) + p0;

    auto stage = [&](int slab, int bufi) {
        uint32_t dA = (uint32_t)__cvta_generic_to_shared(wsm + bufi * ASLAB);
        uint32_t dB = (uint32_t)__cvta_generic_to_shared(bsm + bufi * BSLAB);
        const __half* sA = wsrc + slab * 1024;
        for (int i = tid; i < 128; i += 256) {
            int kp = i >> 4, j = i & 15;
            cp_async16(dA + (uint32_t)((kp * 72 + 4 * j) * 4), sA + kp * 128 + 8 * j, true);
        }
        for (int i = tid; i < 512; i += 256) {
            int kp = i >> 6, j = i & 63;
            cp_async16(dB + (uint32_t)((kp * SKB + 4 * j) * 4),
                       xsrc + (slab * 8 + kp) * HW_ + 4 * j, true);
        }
        cp_commit();
    };

    stage(0, 0);

    const int lane = tid & 31, warp = tid >> 5;
    const int g = lane >> 2, tq = lane & 3;
    const int cb0 = warp * 32;

    float acc[4][4][4];
#pragma unroll
    for (int mt = 0; mt < 4; mt++)
#pragma unroll
        for (int nt = 0; nt < 4; nt++)
#pragma unroll
            for (int q = 0; q < 4; q++) acc[mt][nt][q] = 0.f;

    int buf = 0;
    for (int slab = 0; slab < 4; slab++) {
        cp_wait0();
        __syncthreads();
        if (slab + 1 < 4) stage(slab + 1, buf ^ 1);

        const uint32_t* wa = wsm + buf * ASLAB;
        const uint32_t* bb = bsm + buf * BSLAB;
        uint32_t au[4][4];
#pragma unroll
        for (int mt = 0; mt < 4; mt++) {
            int base = tq * 72 + 16 * mt + g;
            au[mt][0] = wa[base];
            au[mt][1] = wa[base + 8];
            au[mt][2] = wa[base + 288];
            au[mt][3] = wa[base + 296];
        }
        int bbase = tq * SKB + cb0 + g;
#pragma unroll
        for (int nt = 0; nt < 4; nt++) {
            uint32_t b0 = bb[bbase + 8 * nt];
            uint32_t b1 = bb[bbase + 4 * SKB + 8 * nt];
#pragma unroll
            for (int mt = 0; mt < 4; mt++)
                mma_f16(acc[mt][nt], au[mt], b0, b1);
        }
        buf ^= 1;
    }

#pragma unroll
    for (int mt = 0; mt < 4; mt++) {
        const int oc = oc0 + 16 * mt + g;
        const float bv0 = bias[oc], bv1 = bias[oc + 8];
#pragma unroll
        for (int nt = 0; nt < 4; nt++) {
            const int pc = p0 + cb0 + 8 * nt + 2 * tq;
            int e0 = b * GBS_ + oc * HW_ + pc;
            int e1 = e0 + 8 * HW_;
            *(float2*)&t[e0] = make_float2(acc[mt][nt][0] + bv0, acc[mt][nt][1] + bv0);
            *(float2*)&t[e1] = make_float2(acc[mt][nt][2] + bv1, acc[mt][nt][3] + bv1);
        }
    }
}

// ---------------- depthwise 3x3 (fp32) ----------------
__global__ __launch_bounds__(256)
void dwconv_v2_kernel(const float* __restrict__ t, const float* __restrict__ w_dw,
                      const float* __restrict__ b_dw, float* __restrict__ g)
{
    __shared__ float xs[18][136];
    const int tid = threadIdx.x;
    const int s1_0 = blockIdx.x * 16;
    const int og = blockIdx.y, b = blockIdx.z;
    const int base = b * GBS_ + og * HW_;

    if (tid < 36) {
        int row = tid >> 1, side = tid & 1;
        xs[row][side ? 132 : 3] = 0.f;
    }
    for (int idx = tid; idx < 576; idx += 256) {
        int row = idx >> 5, q = idx & 31;
        int s1g = s1_0 - 1 + row;
        float4 v = make_float4(0.f, 0.f, 0.f, 0.f);
        if (s1g >= 0 && s1g < 128)
            v = *(const float4*)&t[base + s1g * 128 + q * 4];
        xs[row][4 + q * 4 + 0] = v.x;
        xs[row][4 + q * 4 + 1] = v.y;
        xs[row][4 + q * 4 + 2] = v.z;
        xs[row][4 + q * 4 + 3] = v.w;
    }
    __syncthreads();

    float w[9];
#pragma unroll
    for (int k = 0; k < 9; k++) w[k] = w_dw[og * 9 + k];
    float bb = b_dw[og];

    const int r = tid >> 4, cb = (tid & 15) * 8;
    float o[8];
#pragma unroll
    for (int j = 0; j < 8; j++) {
        float s = bb;
#pragma unroll
        for (int dr = 0; dr < 3; dr++)
#pragma unroll
            for (int dc = 0; dc < 3; dc++)
                s += w[dr * 3 + dc] * xs[r + dr][cb + j + 3 + dc];
        o[j] = s;
    }
    float* op = &g[base + (s1_0 + r) * 128 + cb];
    *(float4*)op = make_float4(o[0], o[1], o[2], o[3]);
    *(float4*)(op + 4) = make_float4(o[4], o[5], o[6], o[7]);
}

// ---------------- fp16 tensor-core implicit-GEMM 3x3 conv ----------------
// xh2: [b][C/2][S1][W] half2. OUTF16=1: out is half2 pair-interleaved (PERM weights).
template<int C, int S1, int W, int OUTV, int RES, int OUTF16>
__global__ __launch_bounds__(256, 2)
void conv3x3_f16(const uint32_t* __restrict__ xh2, const __half* __restrict__ wprep,
                 const float* __restrict__ bias, void* __restrict__ outv,
                 const float* __restrict__ res,
                 int o_oc, int o_s1, int o_s2, int o_b)
{
    constexpr int TR = 256 / W;
    constexpr int NS = C / 16;
    constexpr int RW = W + 8;
    constexpr int SK = (TR + 2) * RW + 8;
    constexpr int ASLAB = 9 * 8 * 72;    // half2 units
    constexpr int BSLAB = 8 * SK;
    constexpr int BCH = W / 4;

    extern __shared__ uint32_t smu[];
    uint32_t* wsm = smu;
    uint32_t* bsm = smu + 2 * ASLAB;

    const int tid = threadIdx.x;
    const int s1_0 = blockIdx.x * TR;
    const int oc0 = blockIdx.y * 64;
    const int b = blockIdx.z;
    const uint32_t* xb = xh2 + b * ((C / 2) * S1 * W);
    const __half* wsrc = wprep + blockIdx.y * (NS * 9216);

    for (int i = tid; i < 2 * 8 * (TR + 2) * 2; i += 256) {
        int side = i & 1; int rest = i >> 1;
        int row = rest % (TR + 2); rest /= (TR + 2);
        int kp = rest & 7; int bufi = rest >> 3;
        bsm[bufi * BSLAB + kp * SK + row * RW + (side ? (W + 4) : 3)] = 0u;
    }

    auto stageA = [&](int slab, int bufi) {
        uint32_t d0 = (uint32_t)__cvta_generic_to_shared(wsm + bufi * ASLAB);
        const __half* src = wsrc + slab * 9216;
        for (int i = tid; i < 1152; i += 256) {
            int j = i & 15; int kp = (i >> 4) & 7; int s = i >> 7;
            cp_async16(d0 + (uint32_t)((s * 576 + kp * 72 + 4 * j) * 4),
                       src + (s * 8 + kp) * 128 + 8 * j, true);
        }
    };
    auto stageB = [&](int slab, int bufi) {
        uint32_t d0 = (uint32_t)__cvta_generic_to_shared(bsm + bufi * BSLAB);
        const uint32_t* src = xb + slab * 8 * (S1 * W);
        for (int i = tid; i < 8 * (TR + 2) * BCH; i += 256) {
            int j = i % BCH; int rest = i / BCH;
            int row = rest % (TR + 2); int kp = rest / (TR + 2);
            int s1g = s1_0 - 1 + row;
            bool v = (s1g >= 0) && (s1g < S1);
            int s1c = v ? s1g : 0;
            cp_async16(d0 + (uint32_t)((kp * SK + row * RW + 4 + 4 * j) * 4),
                       src + kp * (S1 * W) + s1c * W + 4 * j, v);
        }
    };

    stageA(0, 0); stageB(0, 0); cp_commit();

    const int lane = tid & 31, warp = tid >> 5;
    const int g = lane >> 2, tq = lane & 3;
    const int rbase = (warp * 32) / W;
    const int cb0 = (warp * 32) % W;

    float acc[4][4][4];
#pragma unroll
    for (int mt = 0; mt < 4; mt++)
#pragma unroll
        for (int nt = 0; nt < 4; nt++)
#pragma unroll
            for (int q = 0; q < 4; q++) acc[mt][nt][q] = 0.f;

    int buf = 0;
    for (int slab = 0; slab < NS; slab++) {
        cp_wait0();
        __syncthreads();
        if (slab + 1 < NS) { stageA(slab + 1, buf ^ 1); stageB(slab + 1, buf ^ 1); cp_commit(); }

        const uint32_t* wa = wsm + buf * ASLAB;
        const uint32_t* bb = bsm + buf * BSLAB;
#pragma unroll
        for (int dr = 0; dr < 3; dr++) {
#pragma unroll
            for (int dc = 0; dc < 3; dc++) {
                const int s = dr * 3 + dc;
                uint32_t au[4][4];
#pragma unroll
                for (int mt = 0; mt < 4; mt++) {
                    int base = s * 576 + tq * 72 + 16 * mt + g;
                    au[mt][0] = wa[base];
                    au[mt][1] = wa[base + 8];
                    au[mt][2] = wa[base + 288];
                    au[mt][3] = wa[base + 296];
                }
                int bbase = tq * SK + (rbase + dr) * RW + cb0 + g + dc + 3;
#pragma unroll
                for (int nt = 0; nt < 4; nt++) {
                    uint32_t b0 = bb[bbase + 8 * nt];
                    uint32_t b1 = bb[bbase + 4 * SK + 8 * nt];
#pragma unroll
                    for (int mt = 0; mt < 4; mt++)
                        mma_f16(acc[mt][nt], au[mt], b0, b1);
                }
            }
        }
        buf ^= 1;
    }

    const int s1 = s1_0 + rbase;
    if (OUTF16) {
        // PERM weights: thread g holds adjacent oc pair (2g, 2g+1) within 16-group
        uint32_t* outp = (uint32_t*)outv;
#pragma unroll
        for (int mt = 0; mt < 4; mt++) {
            const int ocb16 = oc0 + 16 * mt;
            const float bve = bias[ocb16 + 2 * g];
            const float bvo = bias[ocb16 + 2 * g + 1];
            const int ocp = (ocb16 >> 1) + g;
#pragma unroll
            for (int nt = 0; nt < 4; nt++) {
                const int px = cb0 + 8 * nt + 2 * tq;
                float v0 = lrelu(acc[mt][nt][0] + bve);
                float v1 = lrelu(acc[mt][nt][1] + bve);
                float v2 = lrelu(acc[mt][nt][2] + bvo);
                float v3 = lrelu(acc[mt][nt][3] + bvo);
                __half2 h0 = __floats2half2_rn(v0, v2);
                __half2 h1 = __floats2half2_rn(v1, v3);
                int e = b * o_b + ocp * o_oc + s1 * o_s1 + px;
                uint2 u = make_uint2(*(uint32_t*)&h0, *(uint32_t*)&h1);
                *(uint2*)&outp[e] = u;
            }
        }
    } else {
        float* out = (float*)outv;
#pragma unroll
        for (int mt = 0; mt < 4; mt++) {
            const int oc = oc0 + 16 * mt + g;
            const float bv0 = bias[oc], bv1 = bias[oc + 8];
#pragma unroll
            for (int nt = 0; nt < 4; nt++) {
                const int pc = cb0 + 8 * nt + 2 * tq;
                float v0 = lrelu(acc[mt][nt][0] + bv0);
                float v1 = lrelu(acc[mt][nt][1] + bv0);
                float v2 = lrelu(acc[mt][nt][2] + bv1);
                float v3 = lrelu(acc[mt][nt][3] + bv1);
                if (OUTV == 0) {
                    int e0 = b * o_b + oc * o_oc + s1 * o_s1 + pc;
                    int e1 = e0 + 8 * o_oc;
                    if (RES) {
                        v0 += res[e0]; v1 += res[e0 + 1];
                        v2 += res[e1]; v3 += res[e1 + 1];
                    }
                    *(float2*)&out[e0] = make_float2(v0, v1);
                    *(float2*)&out[e1] = make_float2(v2, v3);
                } else {
                    int e = b * o_b + s1 * o_s1 + oc;
                    out[e + pc * o_s2] = v0;
                    out[e + (pc + 1) * o_s2] = v1;
                    out[e + 8 + pc * o_s2] = v2;
                    out[e + 8 + (pc + 1) * o_s2] = v3;
                }
            }
        }
    }
}

// ---------------- fused gate + folded down-conv + residual (f32x2, half2 out) ----------------
__global__ __launch_bounds__(128)
void down_kernel_v4(const float* __restrict__ x, const float* __restrict__ xhw,
                    const float* __restrict__ xcw, const float* __restrict__ xhc,
                    const float* __restrict__ g,
                    const float* __restrict__ wd, const float* __restrict__ b_down,
                    uint32_t* __restrict__ midh2)
{
    __shared__ __align__(16) float ws[4][64][16];
    const int tid = threadIdx.x;
    const int p4 = (blockIdx.x * 128 + tid) * 4;
    const int oc0 = blockIdx.y * 16;
    const int b = blockIdx.z;

    for (int idx = tid; idx < 4096; idx += 128) {
        int s = idx >> 10;
        int rem = idx & 1023;
        int c = rem >> 4, i = rem & 15;
        ws[s][c][i] = wd[s * 4096 + c * 64 + oc0 + i];
    }
    __syncthreads();

    ull acc2[8][4];
#pragma unroll
    for (int i = 0; i < 8; i++)
#pragma unroll
        for (int j = 0; j < 4; j++) acc2[i][j] = 0ull;

    const int xb = b * CHW_ + p4;
    const int gb = b * GBS_ + p4;
    for (int c = 0; c < 64; c++) {
        int off = xb + c * HW_;
        float4 a  = *(const float4*)&x[off];
        float4 h  = *(const float4*)&xhw[off];
        float4 cw = *(const float4*)&xcw[off];
        float4 hc = *(const float4*)&xhc[off];
        float4 g0 = *(const float4*)&g[gb + c * HW_];
        float4 g1 = *(const float4*)&g[gb + (64 + c) * HW_];
        float4 g2 = *(const float4*)&g[gb + (128 + c) * HW_];
        h.x *= g0.x; h.y *= g0.y; h.z *= g0.z; h.w *= g0.w;
        cw.x *= g1.x; cw.y *= g1.y; cw.z *= g1.z; cw.w *= g1.w;
        hc.x *= g2.x; hc.y *= g2.y; hc.z *= g2.z; hc.w *= g2.w;
        ull ap[4]  = { pack2b(a.x),  pack2b(a.y),  pack2b(a.z),  pack2b(a.w)  };
        ull hp[4]  = { pack2b(h.x),  pack2b(h.y),  pack2b(h.z),  pack2b(h.w)  };
        ull cp[4]  = { pack2b(cw.x), pack2b(cw.y), pack2b(cw.z), pack2b(cw.w) };
        ull hcp[4] = { pack2b(hc.x), pack2b(hc.y), pack2b(hc.z), pack2b(hc.w) };
#pragma unroll
        for (int op = 0; op < 8; op++) {
            ull w0 = *(const ull*)&ws[0][c][op * 2];
            ull w1 = *(const ull*)&ws[1][c][op * 2];
            ull w2 = *(const ull*)&ws[2][c][op * 2];
            ull w3 = *(const ull*)&ws[3][c][op * 2];
#pragma unroll
            for (int j = 0; j < 4; j++) {
                ffma2(acc2[op][j], w0, ap[j]);
                ffma2(acc2[op][j], w1, hp[j]);
                ffma2(acc2[op][j], w2, cp[j]);
                ffma2(acc2[op][j], w3, hcp[j]);
            }
        }
    }
#pragma unroll
    for (int op = 0; op < 8; op++) {
        int oc = oc0 + 2 * op;
        float b0 = b_down[oc], b1 = b_down[oc + 1];
        float4 x0 = *(const float4*)&x[b * CHW_ + oc * HW_ + p4];
        float4 x1 = *(const float4*)&x[b * CHW_ + (oc + 1) * HW_ + p4];
        float2 p0 = unpack2(acc2[op][0]), p1 = unpack2(acc2[op][1]);
        float2 p2 = unpack2(acc2[op][2]), p3 = unpack2(acc2[op][3]);
        __half2 m0 = __floats2half2_rn(p0.x + b0 + x0.x, p0.y + b1 + x1.x);
        __half2 m1 = __floats2half2_rn(p1.x + b0 + x0.y, p1.y + b1 + x1.y);
        __half2 m2 = __floats2half2_rn(p2.x + b0 + x0.z, p2.y + b1 + x1.z);
        __half2 m3 = __floats2half2_rn(p3.x + b0 + x0.w, p3.y + b1 + x1.w);
        uint4 u = make_uint4(*(uint32_t*)&m0, *(uint32_t*)&m1, *(uint32_t*)&m2, *(uint32_t*)&m3);
        *(uint4*)&midh2[(b * 32 + (oc >> 1)) * HW_ + p4] = u;
    }
}

// ---------------- stream/event pool ----------------
struct AsyncCtx {
    cudaStream_t s1, s2, s3;
    cudaEvent_t eRoot, eR4, eCw, eHc, eHw;
    bool ok;
    AsyncCtx() {
        ok = true;
        ok &= (cudaStreamCreateWithFlags(&s1, cudaStreamNonBlocking) == cudaSuccess);
        ok &= (cudaStreamCreateWithFlags(&s2, cudaStreamNonBlocking) == cudaSuccess);
        ok &= (cudaStreamCreateWithFlags(&s3, cudaStreamNonBlocking) == cudaSuccess);
        ok &= (cudaEventCreateWithFlags(&eRoot, cudaEventDisableTiming) == cudaSuccess);
        ok &= (cudaEventCreateWithFlags(&eR4, cudaEventDisableTiming) == cudaSuccess);
        ok &= (cudaEventCreateWithFlags(&eCw, cudaEventDisableTiming) == cudaSuccess);
        ok &= (cudaEventCreateWithFlags(&eHc, cudaEventDisableTiming) == cudaSuccess);
        ok &= (cudaEventCreateWithFlags(&eHw, cudaEventDisableTiming) == cudaSuccess);
    }
};

// ---------------- launch ----------------
extern "C" void kernel_launch(void* const* d_in, const int* in_sizes, int n_in,
                              void* d_out, int out_size)
{
    const float* x      = (const float*)d_in[0];
    const float* w_hwc  = (const float*)d_in[1];
    const float* b_hwc  = (const float*)d_in[2];
    const float* w_dw   = (const float*)d_in[3];
    const float* b_dw   = (const float*)d_in[4];
    const float* w_hw   = (const float*)d_in[5];
    const float* b_hw   = (const float*)d_in[6];
    const float* w_cw   = (const float*)d_in[7];
    const float* b_cw   = (const float*)d_in[8];
    const float* w_hc   = (const float*)d_in[9];
    const float* b_hc   = (const float*)d_in[10];
    const float* w_down = (const float*)d_in[11];
    const float* b_down = (const float*)d_in[12];
    const float* w_l1   = (const float*)d_in[13];
    const float* b_l1   = (const float*)d_in[14];
    const float* w_l2   = (const float*)d_in[15];
    const float* b_l2   = (const float*)d_in[16];
    float* out = (float*)d_out;

    float *t, *g, *xhw, *xcw, *xhc, *wd;
    uint32_t *xt1, *xt2, *xr, *mid, *o1;
    __half *wrh, *w1h;
    { void* p;
      cudaGetSymbolAddress(&p, d_t);   t   = (float*)p;
      cudaGetSymbolAddress(&p, d_g);   g   = (float*)p;
      cudaGetSymbolAddress(&p, d_xt1); xt1 = (uint32_t*)p;
      cudaGetSymbolAddress(&p, d_xt2); xt2 = (uint32_t*)p;
      cudaGetSymbolAddress(&p, d_xr);  xr  = (uint32_t*)p;
      cudaGetSymbolAddress(&p, d_xhw); xhw = (float*)p;
      cudaGetSymbolAddress(&p, d_xcw); xcw = (float*)p;
      cudaGetSymbolAddress(&p, d_xhc); xhc = (float*)p;
      cudaGetSymbolAddress(&p, d_mid); mid = (uint32_t*)p;
      cudaGetSymbolAddress(&p, d_o1);  o1  = (uint32_t*)p;
      cudaGetSymbolAddress(&p, d_wd);  wd  = (float*)p;
      cudaGetSymbolAddress(&p, d_wr);  wrh = (__half*)p;
      cudaGetSymbolAddress(&p, d_w1);  w1h = (__half*)p;
    }

    __half* wf_hw = wrh;
    __half* wf_cw = wrh + 36864;
    __half* wf_hc = wrh + 184320;
    __half* wf_l1 = wrh + 331776;
    __half* wf_l2 = wrh + 368640;

    // smem: half2 units * 4B
    const int SM128 = (2 * 5184 + 2 * (8 * ((2 + 2) * 136 + 8))) * 4;  // 76800
    const int SM64  = (2 * 5184 + 2 * (8 * ((4 + 2) * 72 + 8))) * 4;   // 69632

    cudaFuncSetAttribute((const void*)conv3x3_f16<64, 128, 128, 0, 0, 0>,
                         cudaFuncAttributeMaxDynamicSharedMemorySize, SM128);
    cudaFuncSetAttribute((const void*)conv3x3_f16<128, 64, 128, 0, 0, 0>,
                         cudaFuncAttributeMaxDynamicSharedMemorySize, SM128);
    cudaFuncSetAttribute((const void*)conv3x3_f16<128, 128, 64, 1, 0, 0>,
                         cudaFuncAttributeMaxDynamicSharedMemorySize, SM64);
    cudaFuncSetAttribute((const void*)conv3x3_f16<64, 128, 128, 0, 0, 1>,
                         cudaFuncAttributeMaxDynamicSharedMemorySize, SM128);
    cudaFuncSetAttribute((const void*)conv3x3_f16<64, 128, 128, 0, 1, 0>,
                         cudaFuncAttributeMaxDynamicSharedMemorySize, SM128);

    static AsyncCtx ctx;

    if (ctx.ok) {
        cudaStream_t m = 0;
        cudaEventRecord(ctx.eRoot, m);
        cudaStreamWaitEvent(ctx.s1, ctx.eRoot, 0);
        cudaStreamWaitEvent(ctx.s2, ctx.eRoot, 0);
        cudaStreamWaitEvent(ctx.s3, ctx.eRoot, 0);

        // s1: cw branch
        prep_wf_kernel<<<576, 256, 0, ctx.s1>>>(w_cw, wf_cw, 128, 128, 0);
        t1f_kernel<<<4096, 256, 0, ctx.s1>>>(x, xt1);
        conv3x3_f16<128, 64, 128, 0, 0, 0><<<dim3(32, 2, 8), 256, SM128, ctx.s1>>>(
            xt1, wf_cw, b_cw, xcw, nullptr, 128, HW_, 1, CHW_);
        cudaEventRecord(ctx.eCw, ctx.s1);

        // s2: hc branch
        prep_wf_kernel<<<576, 256, 0, ctx.s2>>>(w_hc, wf_hc, 128, 128, 0);
        t2f_kernel<<<dim3(4, 2, 1024), dim3(32, 8), 0, ctx.s2>>>(x, xt2);
        conv3x3_f16<128, 128, 64, 1, 0, 0><<<dim3(32, 2, 8), 256, SM64, ctx.s2>>>(
            xt2, wf_hc, b_hc, xhc, nullptr, 1, 128, HW_, CHW_);
        cudaEventRecord(ctx.eHc, ctx.s2);

        // s3: hw branch + misc preps
        prep_wf_kernel<<<144, 256, 0, ctx.s3>>>(w_hw, wf_hw, 64, 64, 0);
        prep_wd_kernel<<<64, 256, 0, ctx.s3>>>(w_down, wd);
        prep_wf_kernel<<<144, 256, 0, ctx.s3>>>(w_l1, wf_l1, 64, 64, 1);
        prep_wf_kernel<<<144, 256, 0, ctx.s3>>>(w_l2, wf_l2, 64, 64, 0);

        // main: gate path
        prep_w1f_kernel<<<48, 256, 0, m>>>(w_hwc, w1h);
        pairf_kernel<<<4096, 256, 0, m>>>(x, xr);
        cudaEventRecord(ctx.eR4, m);
        cudaStreamWaitEvent(ctx.s3, ctx.eR4, 0);
        conv3x3_f16<64, 128, 128, 0, 0, 0><<<dim3(64, 1, 8), 256, SM128, ctx.s3>>>(
            xr, wf_hw, b_hw, xhw, nullptr, HW_, 128, 1, CHW_);
        cudaEventRecord(ctx.eHw, ctx.s3);

        gemm1x1_f16<<<dim3(64, 3, 8), 256, 0, m>>>(xr, w1h, b_hwc, t);
        dwconv_v2_kernel<<<dim3(8, 192, 8), 256, 0, m>>>(t, w_dw, b_dw, g);

        // join
        cudaStreamWaitEvent(m, ctx.eCw, 0);
        cudaStreamWaitEvent(m, ctx.eHc, 0);
        cudaStreamWaitEvent(m, ctx.eHw, 0);

        down_kernel_v4<<<dim3(32, 4, 8), 128, 0, m>>>(x, xhw, xcw, xhc, g, wd, b_down, mid);
        conv3x3_f16<64, 128, 128, 0, 0, 1><<<dim3(64, 1, 8), 256, SM128, m>>>(
            mid, wf_l1, b_l1, o1, nullptr, HW_, 128, 1, 32 * HW_);
        conv3x3_f16<64, 128, 128, 0, 1, 0><<<dim3(64, 1, 8), 256, SM128, m>>>(
            o1, wf_l2, b_l2, out, x, HW_, 128, 1, CHW_);
    } else {
        // serial fallback
        prep_wd_kernel<<<64, 256>>>(w_down, wd);
        prep_wf_kernel<<<144, 256>>>(w_hw, wf_hw, 64, 64, 0);
        prep_wf_kernel<<<576, 256>>>(w_cw, wf_cw, 128, 128, 0);
        prep_wf_kernel<<<576, 256>>>(w_hc, wf_hc, 128, 128, 0);
        prep_wf_kernel<<<144, 256>>>(w_l1, wf_l1, 64, 64, 1);
        prep_wf_kernel<<<144, 256>>>(w_l2, wf_l2, 64, 64, 0);
        prep_w1f_kernel<<<48, 256>>>(w_hwc, w1h);
        pairf_kernel<<<4096, 256>>>(x, xr);
        t1f_kernel<<<4096, 256>>>(x, xt1);
        t2f_kernel<<<dim3(4, 2, 1024), dim3(32, 8)>>>(x, xt2);
        gemm1x1_f16<<<dim3(64, 3, 8), 256>>>(xr, w1h, b_hwc, t);
        dwconv_v2_kernel<<<dim3(8, 192, 8), 256>>>(t, w_dw, b_dw, g);
        conv3x3_f16<64, 128, 128, 0, 0, 0><<<dim3(64, 1, 8), 256, SM128>>>(
            xr, wf_hw, b_hw, xhw, nullptr, HW_, 128, 1, CHW_);
        conv3x3_f16<128, 64, 128, 0, 0, 0><<<dim3(32, 2, 8), 256, SM128>>>(
            xt1, wf_cw, b_cw, xcw, nullptr, 128, HW_, 1, CHW_);
        conv3x3_f16<128, 128, 64, 1, 0, 0><<<dim3(32, 2, 8), 256, SM64>>>(
            xt2, wf_hc, b_hc, xhc, nullptr, 1, 128, HW_, CHW_);
        down_kernel_v4<<<dim3(32, 4, 8), 128>>>(x, xhw, xcw, xhc, g, wd, b_down, mid);
        conv3x3_f16<64, 128, 128, 0, 0, 1><<<dim3(64, 1, 8), 256, SM128>>>(
            mid, wf_l1, b_l1, o1, nullptr, HW_, 128, 1, 32 * HW_);
        conv3x3_f16<64, 128, 128, 0, 1, 0><<<dim3(64, 1, 8), 256, SM128>>>(
            o1, wf_l2, b_l2, out, x, HW_, 128, 1, CHW_);
    }
}

// round 9
// speedup vs baseline: 9.7111x; 1.1461x over previous
#include <cuda_runtime.h>
#include <cuda_fp16.h>
#include <cstdint>

// B=8, C=64, T=128
#define HW_   16384
#define CHW_  1048576
#define GBS_  3145728

typedef unsigned long long ull;

// ---------------- scratch ----------------
__device__ float d_t  [12582912];  // half [8,192,128,128] conv1x1 out
__device__ float d_g  [12582912];  // half [8,192,128,128] gates
__device__ float d_xt1[8388608];   // half2 [b][h/2][c][w]
__device__ float d_xt2[8388608];   // half2 [b][w/2][h][c]
__device__ float d_xr [8388608];   // half2 [b][c/2][h][w]
__device__ float d_xhw[4194304];   // half planar [b][c][h][w]
__device__ float d_xcw[4194304];
__device__ float d_xhc[4194304];
__device__ float d_mid[8388608];   // half2 [b][c/2][h][w]
__device__ float d_o1 [8388608];   // half2 [b][c/2][h][w]
__device__ float d_wd [16384];     // folded down weights [4][64(c)][64(o)] fp32
__device__ float d_wr [405504];    // fp16 conv weights
__device__ float d_w1 [12288];     // fp16 1x1 weights

__device__ __forceinline__ float lrelu(float v) { return v > 0.f ? v : 0.1f * v; }

__device__ __forceinline__ void cp_async16(uint32_t dst, const void* src, bool valid) {
    int sz = valid ? 16 : 0;
    asm volatile("cp.async.cg.shared.global [%0], [%1], 16, %2;\n"
                 :: "r"(dst), "l"(src), "r"(sz));
}
__device__ __forceinline__ void cp_commit() { asm volatile("cp.async.commit_group;\n"); }
__device__ __forceinline__ void cp_wait0()  { asm volatile("cp.async.wait_group 0;\n"); }

// ---------------- f32x2 packed helpers ----------------
__device__ __forceinline__ ull pack2b(float v) {
    ull r; asm("mov.b64 %0, {%1,%1};" : "=l"(r) : "f"(v)); return r;
}
__device__ __forceinline__ float2 unpack2(ull v) {
    float2 r; asm("mov.b64 {%0,%1}, %2;" : "=f"(r.x), "=f"(r.y) : "l"(v)); return r;
}
__device__ __forceinline__ void ffma2(ull& d, ull a, ull b) {
    asm("fma.rn.f32x2 %0, %1, %2, %0;" : "+l"(d) : "l"(a), "l"(b));
}
__device__ __forceinline__ float4 h4_to_f4(uint2 u) {
    float2 a = __half22float2(*(__half2*)&u.x);
    float2 b = __half22float2(*(__half2*)&u.y);
    return make_float4(a.x, a.y, b.x, b.y);
}

// ---------------- fp16 mma (m16n8k16, fp32 accum) ----------------
__device__ __forceinline__ void mma_f16(float* d, const uint32_t* a,
                                        uint32_t b0, uint32_t b1) {
    asm volatile("mma.sync.aligned.m16n8k16.row.col.f32.f16.f16.f32 "
                 "{%0,%1,%2,%3}, {%4,%5,%6,%7}, {%8,%9}, {%0,%1,%2,%3};"
                 : "+f"(d[0]), "+f"(d[1]), "+f"(d[2]), "+f"(d[3])
                 : "r"(a[0]), "r"(a[1]), "r"(a[2]), "r"(a[3]), "r"(b0), "r"(b1));
}

// ---------------- prep: fold w_down ----------------
__global__ void prep_wd_kernel(const float* __restrict__ w_down, float* __restrict__ wd)
{
    int idx = blockIdx.x * 256 + threadIdx.x;
    if (idx >= 16384) return;
    int s = idx >> 12;
    int rem = idx & 4095;
    int c = rem >> 6;
    int o = rem & 63;
    auto W = [&](int i, int ky, int kx) { return w_down[((o * 128 + i) * 2 + ky) * 2 + kx]; };
    float v = 0.f;
    if (s == 0) v = W(2 * c, 0, 0) + W(2 * c + 1, 1, 1);
    else if (s == 1) v = W(2 * c, 0, 1) + W(2 * c + 1, 1, 0);
    else if (s == 2) v = W(2 * c, 1, 0) + W(2 * c + 1, 0, 1);
    else v = W(2 * c, 1, 1) + W(2 * c + 1, 0, 0);
    wd[s * 4096 + c * 64 + o] = v;
}

// ---------------- prep: fp16 conv weights ----------------
__global__ void prep_wf_kernel(const float* __restrict__ src, __half* __restrict__ dst,
                               int OC, int C, int PERM)
{
    int idx = blockIdx.x * 256 + threadIdx.x;
    int total = OC * C * 9;
    if (idx >= total) return;
    int klo = idx & 1;
    int ocl = (idx >> 1) & 63;
    int kp  = (idx >> 7) & 7;
    int s   = (idx >> 10) % 9;
    int rest = idx / 9216;
    int NS = C >> 4;
    int slab = rest % NS;
    int ocb = rest / NS;
    int l = ocl;
    if (PERM) {
        int grp = ocl >> 4, r = ocl & 15;
        l = grp * 16 + ((r < 8) ? 2 * r : 2 * (r - 8) + 1);
    }
    int k = slab * 16 + 2 * kp + klo;
    dst[idx] = __float2half_rn(src[((ocb * 64 + l) * C + k) * 9 + s]);
}

__global__ void prep_w1f_kernel(const float* __restrict__ src, __half* __restrict__ dst)
{
    int idx = blockIdx.x * 256 + threadIdx.x;
    if (idx >= 12288) return;
    int klo = idx & 1;
    int ocl = (idx >> 1) & 63;
    int kp  = (idx >> 7) & 7;
    int slab = (idx >> 10) & 3;
    int ocb = idx >> 12;
    dst[idx] = __float2half_rn(src[(ocb * 64 + ocl) * 64 + slab * 16 + 2 * kp + klo]);
}

// ---------------- x -> half2 channel-pair interleave ----------------
__global__ __launch_bounds__(256)
void pairf_kernel(const float* __restrict__ x, uint32_t* __restrict__ o)
{
    int i = blockIdx.x * 256 + threadIdx.x;
    int p4 = (i & 4095) * 4;
    int cp = (i >> 12) & 31;
    int b = i >> 17;
    float4 a = *(const float4*)&x[(b * 64 + 2 * cp) * HW_ + p4];
    float4 c = *(const float4*)&x[(b * 64 + 2 * cp + 1) * HW_ + p4];
    __half2 h0 = __floats2half2_rn(a.x, c.x);
    __half2 h1 = __floats2half2_rn(a.y, c.y);
    __half2 h2 = __floats2half2_rn(a.z, c.z);
    __half2 h3 = __floats2half2_rn(a.w, c.w);
    uint4 u = make_uint4(*(uint32_t*)&h0, *(uint32_t*)&h1, *(uint32_t*)&h2, *(uint32_t*)&h3);
    *(uint4*)&o[(b * 32 + cp) * HW_ + p4] = u;
}

// ---------------- t1: half2 [b][h/2][c][w] ----------------
__global__ __launch_bounds__(256)
void t1f_kernel(const float* __restrict__ x, uint32_t* __restrict__ o)
{
    int i = blockIdx.x * 256 + threadIdx.x;
    int w4 = i & 31;
    int c = (i >> 5) & 63;
    int hp = (i >> 11) & 63;
    int b = i >> 17;
    const float* plane = x + (b * 64 + c) * HW_;
    float4 a = *(const float4*)&plane[(2 * hp) * 128 + 4 * w4];
    float4 d = *(const float4*)&plane[(2 * hp + 1) * 128 + 4 * w4];
    __half2 h0 = __floats2half2_rn(a.x, d.x);
    __half2 h1 = __floats2half2_rn(a.y, d.y);
    __half2 h2 = __floats2half2_rn(a.z, d.z);
    __half2 h3 = __floats2half2_rn(a.w, d.w);
    uint4 u = make_uint4(*(uint32_t*)&h0, *(uint32_t*)&h1, *(uint32_t*)&h2, *(uint32_t*)&h3);
    *(uint4*)&o[((b * 64 + hp) * 64 + c) * 128 + 4 * w4] = u;
}

// ---------------- t2: half2 [b][w/2][h][c] ----------------
__global__ __launch_bounds__(256)
void t2f_kernel(const float* __restrict__ x, uint32_t* __restrict__ o)
{
    __shared__ float tile[32][33];
    int tx = threadIdx.x, ty = threadIdx.y;
    int w0 = blockIdx.x * 32;
    int c0 = blockIdx.y * 32;
    int bh = blockIdx.z;
    int b = bh >> 7, hrow = bh & 127;
    int xb = b * CHW_ + hrow * 128;
#pragma unroll
    for (int i = 0; i < 4; i++)
        tile[ty + 8 * i][tx] = x[xb + (c0 + ty + 8 * i) * HW_ + w0 + tx];
    __syncthreads();
#pragma unroll
    for (int j = 0; j < 2; j++) {
        int wl = ty + 8 * j;
        __half2 hv = __floats2half2_rn(tile[tx][2 * wl], tile[tx][2 * wl + 1]);
        o[((b * 64 + (w0 >> 1) + wl) * 128 + hrow) * 64 + c0 + tx] = *(uint32_t*)&hv;
    }
}

// ---------------- conv1x1 via fp16 MMA: t(half) = w_hwc @ x + b ----------------
__global__ __launch_bounds__(256)
void gemm1x1_f16(const uint32_t* __restrict__ xh2, const __half* __restrict__ wprep,
                 const float* __restrict__ bias, __half* __restrict__ t)
{
    constexpr int SKB = 264;
    constexpr int ASLAB = 576;
    constexpr int BSLAB = 8 * SKB;
    __shared__ __align__(16) uint32_t sm[2 * (ASLAB + BSLAB)];
    uint32_t* wsm = sm;
    uint32_t* bsm = sm + 2 * ASLAB;

    const int tid = threadIdx.x;
    const int p0 = blockIdx.x * 256;
    const int oc0 = blockIdx.y * 64;
    const int b = blockIdx.z;
    const __half* wsrc = wprep + blockIdx.y * 4096;
    const uint32_t* xsrc = xh2 + b * (32 * HW_) + p0;

    auto stage = [&](int slab, int bufi) {
        uint32_t dA = (uint32_t)__cvta_generic_to_shared(wsm + bufi * ASLAB);
        uint32_t dB = (uint32_t)__cvta_generic_to_shared(bsm + bufi * BSLAB);
        const __half* sA = wsrc + slab * 1024;
        for (int i = tid; i < 128; i += 256) {
            int kp = i >> 4, j = i & 15;
            cp_async16(dA + (uint32_t)((kp * 72 + 4 * j) * 4), sA + kp * 128 + 8 * j, true);
        }
        for (int i = tid; i < 512; i += 256) {
            int kp = i >> 6, j = i & 63;
            cp_async16(dB + (uint32_t)((kp * SKB + 4 * j) * 4),
                       xsrc + (slab * 8 + kp) * HW_ + 4 * j, true);
        }
        cp_commit();
    };

    stage(0, 0);

    const int lane = tid & 31, warp = tid >> 5;
    const int g = lane >> 2, tq = lane & 3;
    const int cb0 = warp * 32;

    float acc[4][4][4];
#pragma unroll
    for (int mt = 0; mt < 4; mt++)
#pragma unroll
        for (int nt = 0; nt < 4; nt++)
#pragma unroll
            for (int q = 0; q < 4; q++) acc[mt][nt][q] = 0.f;

    int buf = 0;
    for (int slab = 0; slab < 4; slab++) {
        cp_wait0();
        __syncthreads();
        if (slab + 1 < 4) stage(slab + 1, buf ^ 1);

        const uint32_t* wa = wsm + buf * ASLAB;
        const uint32_t* bb = bsm + buf * BSLAB;
        uint32_t au[4][4];
#pragma unroll
        for (int mt = 0; mt < 4; mt++) {
            int base = tq * 72 + 16 * mt + g;
            au[mt][0] = wa[base];
            au[mt][1] = wa[base + 8];
            au[mt][2] = wa[base + 288];
            au[mt][3] = wa[base + 296];
        }
        int bbase = tq * SKB + cb0 + g;
#pragma unroll
        for (int nt = 0; nt < 4; nt++) {
            uint32_t b0 = bb[bbase + 8 * nt];
            uint32_t b1 = bb[bbase + 4 * SKB + 8 * nt];
#pragma unroll
            for (int mt = 0; mt < 4; mt++)
                mma_f16(acc[mt][nt], au[mt], b0, b1);
        }
        buf ^= 1;
    }

#pragma unroll
    for (int mt = 0; mt < 4; mt++) {
        const int oc = oc0 + 16 * mt + g;
        const float bv0 = bias[oc], bv1 = bias[oc + 8];
#pragma unroll
        for (int nt = 0; nt < 4; nt++) {
            const int pc = p0 + cb0 + 8 * nt + 2 * tq;
            int e0 = b * GBS_ + oc * HW_ + pc;
            int e1 = e0 + 8 * HW_;
            *(__half2*)&t[e0] = __floats2half2_rn(acc[mt][nt][0] + bv0, acc[mt][nt][1] + bv0);
            *(__half2*)&t[e1] = __floats2half2_rn(acc[mt][nt][2] + bv1, acc[mt][nt][3] + bv1);
        }
    }
}

// ---------------- depthwise 3x3: half in, half out ----------------
__global__ __launch_bounds__(256)
void dwconv_v3_kernel(const __half* __restrict__ t, const float* __restrict__ w_dw,
                      const float* __restrict__ b_dw, __half* __restrict__ g)
{
    __shared__ float xs[18][136];
    const int tid = threadIdx.x;
    const int s1_0 = blockIdx.x * 16;
    const int og = blockIdx.y, b = blockIdx.z;
    const int base = b * GBS_ + og * HW_;

    if (tid < 36) {
        int row = tid >> 1, side = tid & 1;
        xs[row][side ? 132 : 3] = 0.f;
    }
    for (int idx = tid; idx < 576; idx += 256) {
        int row = idx >> 5, q = idx & 31;
        int s1g = s1_0 - 1 + row;
        float4 v = make_float4(0.f, 0.f, 0.f, 0.f);
        if (s1g >= 0 && s1g < 128)
            v = h4_to_f4(*(const uint2*)&t[base + s1g * 128 + q * 4]);
        xs[row][4 + q * 4 + 0] = v.x;
        xs[row][4 + q * 4 + 1] = v.y;
        xs[row][4 + q * 4 + 2] = v.z;
        xs[row][4 + q * 4 + 3] = v.w;
    }
    __syncthreads();

    float w[9];
#pragma unroll
    for (int k = 0; k < 9; k++) w[k] = w_dw[og * 9 + k];
    float bb = b_dw[og];

    const int r = tid >> 4, cb = (tid & 15) * 8;
    float o[8];
#pragma unroll
    for (int j = 0; j < 8; j++) {
        float s = bb;
#pragma unroll
        for (int dr = 0; dr < 3; dr++)
#pragma unroll
            for (int dc = 0; dc < 3; dc++)
                s += w[dr * 3 + dc] * xs[r + dr][cb + j + 3 + dc];
        o[j] = s;
    }
    __half2 q0 = __floats2half2_rn(o[0], o[1]);
    __half2 q1 = __floats2half2_rn(o[2], o[3]);
    __half2 q2 = __floats2half2_rn(o[4], o[5]);
    __half2 q3 = __floats2half2_rn(o[6], o[7]);
    uint4 u = make_uint4(*(uint32_t*)&q0, *(uint32_t*)&q1, *(uint32_t*)&q2, *(uint32_t*)&q3);
    *(uint4*)&g[base + (s1_0 + r) * 128 + cb] = u;
}

// ---------------- fp16 tensor-core implicit-GEMM 3x3 conv ----------------
// OUTH: 0 fp32 planar (+RES), 1 half2 pair-interleaved (PERM weights), 2 half planar
template<int C, int S1, int W, int OUTV, int RES, int OUTH>
__global__ __launch_bounds__(256, 2)
void conv3x3_f16(const uint32_t* __restrict__ xh2, const __half* __restrict__ wprep,
                 const float* __restrict__ bias, void* __restrict__ outv,
                 const float* __restrict__ res,
                 int o_oc, int o_s1, int o_s2, int o_b)
{
    constexpr int TR = 256 / W;
    constexpr int NS = C / 16;
    constexpr int RW = W + 8;
    constexpr int SK = (TR + 2) * RW + 8;
    constexpr int ASLAB = 9 * 8 * 72;
    constexpr int BSLAB = 8 * SK;
    constexpr int BCH = W / 4;

    extern __shared__ uint32_t smu[];
    uint32_t* wsm = smu;
    uint32_t* bsm = smu + 2 * ASLAB;

    const int tid = threadIdx.x;
    const int s1_0 = blockIdx.x * TR;
    const int oc0 = blockIdx.y * 64;
    const int b = blockIdx.z;
    const uint32_t* xb = xh2 + b * ((C / 2) * S1 * W);
    const __half* wsrc = wprep + blockIdx.y * (NS * 9216);

    for (int i = tid; i < 2 * 8 * (TR + 2) * 2; i += 256) {
        int side = i & 1; int rest = i >> 1;
        int row = rest % (TR + 2); rest /= (TR + 2);
        int kp = rest & 7; int bufi = rest >> 3;
        bsm[bufi * BSLAB + kp * SK + row * RW + (side ? (W + 4) : 3)] = 0u;
    }

    auto stageA = [&](int slab, int bufi) {
        uint32_t d0 = (uint32_t)__cvta_generic_to_shared(wsm + bufi * ASLAB);
        const __half* src = wsrc + slab * 9216;
        for (int i = tid; i < 1152; i += 256) {
            int j = i & 15; int kp = (i >> 4) & 7; int s = i >> 7;
            cp_async16(d0 + (uint32_t)((s * 576 + kp * 72 + 4 * j) * 4),
                       src + (s * 8 + kp) * 128 + 8 * j, true);
        }
    };
    auto stageB = [&](int slab, int bufi) {
        uint32_t d0 = (uint32_t)__cvta_generic_to_shared(bsm + bufi * BSLAB);
        const uint32_t* src = xb + slab * 8 * (S1 * W);
        for (int i = tid; i < 8 * (TR + 2) * BCH; i += 256) {
            int j = i % BCH; int rest = i / BCH;
            int row = rest % (TR + 2); int kp = rest / (TR + 2);
            int s1g = s1_0 - 1 + row;
            bool v = (s1g >= 0) && (s1g < S1);
            int s1c = v ? s1g : 0;
            cp_async16(d0 + (uint32_t)((kp * SK + row * RW + 4 + 4 * j) * 4),
                       src + kp * (S1 * W) + s1c * W + 4 * j, v);
        }
    };

    stageA(0, 0); stageB(0, 0); cp_commit();

    const int lane = tid & 31, warp = tid >> 5;
    const int g = lane >> 2, tq = lane & 3;
    const int rbase = (warp * 32) / W;
    const int cb0 = (warp * 32) % W;

    float acc[4][4][4];
#pragma unroll
    for (int mt = 0; mt < 4; mt++)
#pragma unroll
        for (int nt = 0; nt < 4; nt++)
#pragma unroll
            for (int q = 0; q < 4; q++) acc[mt][nt][q] = 0.f;

    int buf = 0;
    for (int slab = 0; slab < NS; slab++) {
        cp_wait0();
        __syncthreads();
        if (slab + 1 < NS) { stageA(slab + 1, buf ^ 1); stageB(slab + 1, buf ^ 1); cp_commit(); }

        const uint32_t* wa = wsm + buf * ASLAB;
        const uint32_t* bb = bsm + buf * BSLAB;
#pragma unroll
        for (int dr = 0; dr < 3; dr++) {
#pragma unroll
            for (int dc = 0; dc < 3; dc++) {
                const int s = dr * 3 + dc;
                uint32_t au[4][4];
#pragma unroll
                for (int mt = 0; mt < 4; mt++) {
                    int base = s * 576 + tq * 72 + 16 * mt + g;
                    au[mt][0] = wa[base];
                    au[mt][1] = wa[base + 8];
                    au[mt][2] = wa[base + 288];
                    au[mt][3] = wa[base + 296];
                }
                int bbase = tq * SK + (rbase + dr) * RW + cb0 + g + dc + 3;
#pragma unroll
                for (int nt = 0; nt < 4; nt++) {
                    uint32_t b0 = bb[bbase + 8 * nt];
                    uint32_t b1 = bb[bbase + 4 * SK + 8 * nt];
#pragma unroll
                    for (int mt = 0; mt < 4; mt++)
                        mma_f16(acc[mt][nt], au[mt], b0, b1);
                }
            }
        }
        buf ^= 1;
    }

    const int s1 = s1_0 + rbase;
    if (OUTH == 1) {
        uint32_t* outp = (uint32_t*)outv;
#pragma unroll
        for (int mt = 0; mt < 4; mt++) {
            const int ocb16 = oc0 + 16 * mt;
            const float bve = bias[ocb16 + 2 * g];
            const float bvo = bias[ocb16 + 2 * g + 1];
            const int ocp = (ocb16 >> 1) + g;
#pragma unroll
            for (int nt = 0; nt < 4; nt++) {
                const int px = cb0 + 8 * nt + 2 * tq;
                float v0 = lrelu(acc[mt][nt][0] + bve);
                float v1 = lrelu(acc[mt][nt][1] + bve);
                float v2 = lrelu(acc[mt][nt][2] + bvo);
                float v3 = lrelu(acc[mt][nt][3] + bvo);
                __half2 h0 = __floats2half2_rn(v0, v2);
                __half2 h1 = __floats2half2_rn(v1, v3);
                int e = b * o_b + ocp * o_oc + s1 * o_s1 + px;
                uint2 u = make_uint2(*(uint32_t*)&h0, *(uint32_t*)&h1);
                *(uint2*)&outp[e] = u;
            }
        }
    } else if (OUTH == 2) {
        __half* outh = (__half*)outv;
#pragma unroll
        for (int mt = 0; mt < 4; mt++) {
            const int oc = oc0 + 16 * mt + g;
            const float bv0 = bias[oc], bv1 = bias[oc + 8];
#pragma unroll
            for (int nt = 0; nt < 4; nt++) {
                const int pc = cb0 + 8 * nt + 2 * tq;
                float v0 = lrelu(acc[mt][nt][0] + bv0);
                float v1 = lrelu(acc[mt][nt][1] + bv0);
                float v2 = lrelu(acc[mt][nt][2] + bv1);
                float v3 = lrelu(acc[mt][nt][3] + bv1);
                if (OUTV == 0) {
                    int e0 = b * o_b + oc * o_oc + s1 * o_s1 + pc;
                    int e1 = e0 + 8 * o_oc;
                    *(__half2*)&outh[e0] = __floats2half2_rn(v0, v1);
                    *(__half2*)&outh[e1] = __floats2half2_rn(v2, v3);
                } else {
                    int e = b * o_b + s1 * o_s1 + oc;
                    outh[e + pc * o_s2] = __float2half_rn(v0);
                    outh[e + (pc + 1) * o_s2] = __float2half_rn(v1);
                    outh[e + 8 + pc * o_s2] = __float2half_rn(v2);
                    outh[e + 8 + (pc + 1) * o_s2] = __float2half_rn(v3);
                }
            }
        }
    } else {
        float* out = (float*)outv;
#pragma unroll
        for (int mt = 0; mt < 4; mt++) {
            const int oc = oc0 + 16 * mt + g;
            const float bv0 = bias[oc], bv1 = bias[oc + 8];
#pragma unroll
            for (int nt = 0; nt < 4; nt++) {
                const int pc = cb0 + 8 * nt + 2 * tq;
                float v0 = lrelu(acc[mt][nt][0] + bv0);
                float v1 = lrelu(acc[mt][nt][1] + bv0);
                float v2 = lrelu(acc[mt][nt][2] + bv1);
                float v3 = lrelu(acc[mt][nt][3] + bv1);
                int e0 = b * o_b + oc * o_oc + s1 * o_s1 + pc;
                int e1 = e0 + 8 * o_oc;
                if (RES) {
                    v0 += res[e0]; v1 += res[e0 + 1];
                    v2 += res[e1]; v3 += res[e1 + 1];
                }
                *(float2*)&out[e0] = make_float2(v0, v1);
                *(float2*)&out[e1] = make_float2(v2, v3);
            }
        }
    }
}

// ---------------- fused gate + folded down-conv + residual (fp16 inputs) ----------------
__global__ __launch_bounds__(128)
void down_kernel_v5(const uint32_t* __restrict__ xr, const __half* __restrict__ xhw,
                    const __half* __restrict__ xcw, const __half* __restrict__ xhc,
                    const __half* __restrict__ g, const float* __restrict__ x,
                    const float* __restrict__ wd, const float* __restrict__ b_down,
                    uint32_t* __restrict__ midh2)
{
    __shared__ __align__(16) float ws[4][64][16];
    const int tid = threadIdx.x;
    const int p4 = (blockIdx.x * 128 + tid) * 4;
    const int oc0 = blockIdx.y * 16;
    const int b = blockIdx.z;

    for (int idx = tid; idx < 4096; idx += 128) {
        int s = idx >> 10;
        int rem = idx & 1023;
        int c = rem >> 4, i = rem & 15;
        ws[s][c][i] = wd[s * 4096 + c * 64 + oc0 + i];
    }
    __syncthreads();

    ull acc2[8][4];
#pragma unroll
    for (int i = 0; i < 8; i++)
#pragma unroll
        for (int j = 0; j < 4; j++) acc2[i][j] = 0ull;

    const int hb = b * CHW_ / 16 * 16;   // b * CHW_ (element base for 64-plane half tensors)
    const int gb = b * GBS_;

    for (int c = 0; c < 64; c += 2) {
        // a-term from xr (pair-interleaved)
        uint4 ux = *(const uint4*)&xr[(b * 32 + (c >> 1)) * HW_ + p4];
        float2 a0 = __half22float2(*(__half2*)&ux.x);
        float2 a1 = __half22float2(*(__half2*)&ux.y);
        float2 a2 = __half22float2(*(__half2*)&ux.z);
        float2 a3 = __half22float2(*(__half2*)&ux.w);
        // branches (planar half)
        float4 hw0 = h4_to_f4(*(const uint2*)&xhw[b * CHW_ + c * HW_ + p4]);
        float4 hw1 = h4_to_f4(*(const uint2*)&xhw[b * CHW_ + (c + 1) * HW_ + p4]);
        float4 cw0 = h4_to_f4(*(const uint2*)&xcw[b * CHW_ + c * HW_ + p4]);
        float4 cw1 = h4_to_f4(*(const uint2*)&xcw[b * CHW_ + (c + 1) * HW_ + p4]);
        float4 hc0 = h4_to_f4(*(const uint2*)&xhc[b * CHW_ + c * HW_ + p4]);
        float4 hc1 = h4_to_f4(*(const uint2*)&xhc[b * CHW_ + (c + 1) * HW_ + p4]);
        // gates
        float4 g00 = h4_to_f4(*(const uint2*)&g[gb + c * HW_ + p4]);
        float4 g01 = h4_to_f4(*(const uint2*)&g[gb + (c + 1) * HW_ + p4]);
        float4 g10 = h4_to_f4(*(const uint2*)&g[gb + (64 + c) * HW_ + p4]);
        float4 g11 = h4_to_f4(*(const uint2*)&g[gb + (65 + c) * HW_ + p4]);
        float4 g20 = h4_to_f4(*(const uint2*)&g[gb + (128 + c) * HW_ + p4]);
        float4 g21 = h4_to_f4(*(const uint2*)&g[gb + (129 + c) * HW_ + p4]);

        hw0.x *= g00.x; hw0.y *= g00.y; hw0.z *= g00.z; hw0.w *= g00.w;
        hw1.x *= g01.x; hw1.y *= g01.y; hw1.z *= g01.z; hw1.w *= g01.w;
        cw0.x *= g10.x; cw0.y *= g10.y; cw0.z *= g10.z; cw0.w *= g10.w;
        cw1.x *= g11.x; cw1.y *= g11.y; cw1.z *= g11.z; cw1.w *= g11.w;
        hc0.x *= g20.x; hc0.y *= g20.y; hc0.z *= g20.z; hc0.w *= g20.w;
        hc1.x *= g21.x; hc1.y *= g21.y; hc1.z *= g21.z; hc1.w *= g21.w;

        ull ap0[4]  = { pack2b(a0.x), pack2b(a1.x), pack2b(a2.x), pack2b(a3.x) };
        ull hp0[4]  = { pack2b(hw0.x), pack2b(hw0.y), pack2b(hw0.z), pack2b(hw0.w) };
        ull cp0[4]  = { pack2b(cw0.x), pack2b(cw0.y), pack2b(cw0.z), pack2b(cw0.w) };
        ull hcp0[4] = { pack2b(hc0.x), pack2b(hc0.y), pack2b(hc0.z), pack2b(hc0.w) };
        ull ap1[4]  = { pack2b(a0.y), pack2b(a1.y), pack2b(a2.y), pack2b(a3.y) };
        ull hp1[4]  = { pack2b(hw1.x), pack2b(hw1.y), pack2b(hw1.z), pack2b(hw1.w) };
        ull cp1[4]  = { pack2b(cw1.x), pack2b(cw1.y), pack2b(cw1.z), pack2b(cw1.w) };
        ull hcp1[4] = { pack2b(hc1.x), pack2b(hc1.y), pack2b(hc1.z), pack2b(hc1.w) };

#pragma unroll
        for (int op = 0; op < 8; op++) {
            ull w00 = *(const ull*)&ws[0][c][op * 2];
            ull w10 = *(const ull*)&ws[1][c][op * 2];
            ull w20 = *(const ull*)&ws[2][c][op * 2];
            ull w30 = *(const ull*)&ws[3][c][op * 2];
            ull w01 = *(const ull*)&ws[0][c + 1][op * 2];
            ull w11 = *(const ull*)&ws[1][c + 1][op * 2];
            ull w21 = *(const ull*)&ws[2][c + 1][op * 2];
            ull w31 = *(const ull*)&ws[3][c + 1][op * 2];
#pragma unroll
            for (int j = 0; j < 4; j++) {
                ffma2(acc2[op][j], w00, ap0[j]);
                ffma2(acc2[op][j], w10, hp0[j]);
                ffma2(acc2[op][j], w20, cp0[j]);
                ffma2(acc2[op][j], w30, hcp0[j]);
                ffma2(acc2[op][j], w01, ap1[j]);
                ffma2(acc2[op][j], w11, hp1[j]);
                ffma2(acc2[op][j], w21, cp1[j]);
                ffma2(acc2[op][j], w31, hcp1[j]);
            }
        }
    }
#pragma unroll
    for (int op = 0; op < 8; op++) {
        int oc = oc0 + 2 * op;
        float b0 = b_down[oc], b1 = b_down[oc + 1];
        float4 x0 = *(const float4*)&x[b * CHW_ + oc * HW_ + p4];
        float4 x1 = *(const float4*)&x[b * CHW_ + (oc + 1) * HW_ + p4];
        float2 p0 = unpack2(acc2[op][0]), p1 = unpack2(acc2[op][1]);
        float2 p2 = unpack2(acc2[op][2]), p3 = unpack2(acc2[op][3]);
        __half2 m0 = __floats2half2_rn(p0.x + b0 + x0.x, p0.y + b1 + x1.x);
        __half2 m1 = __floats2half2_rn(p1.x + b0 + x0.y, p1.y + b1 + x1.y);
        __half2 m2 = __floats2half2_rn(p2.x + b0 + x0.z, p2.y + b1 + x1.z);
        __half2 m3 = __floats2half2_rn(p3.x + b0 + x0.w, p3.y + b1 + x1.w);
        uint4 u = make_uint4(*(uint32_t*)&m0, *(uint32_t*)&m1, *(uint32_t*)&m2, *(uint32_t*)&m3);
        *(uint4*)&midh2[(b * 32 + (oc >> 1)) * HW_ + p4] = u;
    }
}

// ---------------- stream/event pool ----------------
struct AsyncCtx {
    cudaStream_t s1, s2, s3;
    cudaEvent_t eRoot, eR4, eCw, eHc, eHw;
    bool ok;
    AsyncCtx() {
        ok = true;
        ok &= (cudaStreamCreateWithFlags(&s1, cudaStreamNonBlocking) == cudaSuccess);
        ok &= (cudaStreamCreateWithFlags(&s2, cudaStreamNonBlocking) == cudaSuccess);
        ok &= (cudaStreamCreateWithFlags(&s3, cudaStreamNonBlocking) == cudaSuccess);
        ok &= (cudaEventCreateWithFlags(&eRoot, cudaEventDisableTiming) == cudaSuccess);
        ok &= (cudaEventCreateWithFlags(&eR4, cudaEventDisableTiming) == cudaSuccess);
        ok &= (cudaEventCreateWithFlags(&eCw, cudaEventDisableTiming) == cudaSuccess);
        ok &= (cudaEventCreateWithFlags(&eHc, cudaEventDisableTiming) == cudaSuccess);
        ok &= (cudaEventCreateWithFlags(&eHw, cudaEventDisableTiming) == cudaSuccess);
    }
};

// ---------------- launch ----------------
extern "C" void kernel_launch(void* const* d_in, const int* in_sizes, int n_in,
                              void* d_out, int out_size)
{
    const float* x      = (const float*)d_in[0];
    const float* w_hwc  = (const float*)d_in[1];
    const float* b_hwc  = (const float*)d_in[2];
    const float* w_dw   = (const float*)d_in[3];
    const float* b_dw   = (const float*)d_in[4];
    const float* w_hw   = (const float*)d_in[5];
    const float* b_hw   = (const float*)d_in[6];
    const float* w_cw   = (const float*)d_in[7];
    const float* b_cw   = (const float*)d_in[8];
    const float* w_hc   = (const float*)d_in[9];
    const float* b_hc   = (const float*)d_in[10];
    const float* w_down = (const float*)d_in[11];
    const float* b_down = (const float*)d_in[12];
    const float* w_l1   = (const float*)d_in[13];
    const float* b_l1   = (const float*)d_in[14];
    const float* w_l2   = (const float*)d_in[15];
    const float* b_l2   = (const float*)d_in[16];
    float* out = (float*)d_out;

    __half *t, *g, *xhw, *xcw, *xhc;
    uint32_t *xt1, *xt2, *xr, *mid, *o1;
    float *wd;
    __half *wrh, *w1h;
    { void* p;
      cudaGetSymbolAddress(&p, d_t);   t   = (__half*)p;
      cudaGetSymbolAddress(&p, d_g);   g   = (__half*)p;
      cudaGetSymbolAddress(&p, d_xt1); xt1 = (uint32_t*)p;
      cudaGetSymbolAddress(&p, d_xt2); xt2 = (uint32_t*)p;
      cudaGetSymbolAddress(&p, d_xr);  xr  = (uint32_t*)p;
      cudaGetSymbolAddress(&p, d_xhw); xhw = (__half*)p;
      cudaGetSymbolAddress(&p, d_xcw); xcw = (__half*)p;
      cudaGetSymbolAddress(&p, d_xhc); xhc = (__half*)p;
      cudaGetSymbolAddress(&p, d_mid); mid = (uint32_t*)p;
      cudaGetSymbolAddress(&p, d_o1);  o1  = (uint32_t*)p;
      cudaGetSymbolAddress(&p, d_wd);  wd  = (float*)p;
      cudaGetSymbolAddress(&p, d_wr);  wrh = (__half*)p;
      cudaGetSymbolAddress(&p, d_w1);  w1h = (__half*)p;
    }

    __half* wf_hw = wrh;
    __half* wf_cw = wrh + 36864;
    __half* wf_hc = wrh + 184320;
    __half* wf_l1 = wrh + 331776;
    __half* wf_l2 = wrh + 368640;

    const int SM128 = (2 * 5184 + 2 * (8 * ((2 + 2) * 136 + 8))) * 4;
    const int SM64  = (2 * 5184 + 2 * (8 * ((4 + 2) * 72 + 8))) * 4;

    cudaFuncSetAttribute((const void*)conv3x3_f16<64, 128, 128, 0, 0, 2>,
                         cudaFuncAttributeMaxDynamicSharedMemorySize, SM128);
    cudaFuncSetAttribute((const void*)conv3x3_f16<128, 64, 128, 0, 0, 2>,
                         cudaFuncAttributeMaxDynamicSharedMemorySize, SM128);
    cudaFuncSetAttribute((const void*)conv3x3_f16<128, 128, 64, 1, 0, 2>,
                         cudaFuncAttributeMaxDynamicSharedMemorySize, SM64);
    cudaFuncSetAttribute((const void*)conv3x3_f16<64, 128, 128, 0, 0, 1>,
                         cudaFuncAttributeMaxDynamicSharedMemorySize, SM128);
    cudaFuncSetAttribute((const void*)conv3x3_f16<64, 128, 128, 0, 1, 0>,
                         cudaFuncAttributeMaxDynamicSharedMemorySize, SM128);

    static AsyncCtx ctx;

    if (ctx.ok) {
        cudaStream_t m = 0;
        cudaEventRecord(ctx.eRoot, m);
        cudaStreamWaitEvent(ctx.s1, ctx.eRoot, 0);
        cudaStreamWaitEvent(ctx.s2, ctx.eRoot, 0);
        cudaStreamWaitEvent(ctx.s3, ctx.eRoot, 0);

        // s1: cw branch
        prep_wf_kernel<<<576, 256, 0, ctx.s1>>>(w_cw, wf_cw, 128, 128, 0);
        t1f_kernel<<<4096, 256, 0, ctx.s1>>>(x, xt1);
        conv3x3_f16<128, 64, 128, 0, 0, 2><<<dim3(32, 2, 8), 256, SM128, ctx.s1>>>(
            xt1, wf_cw, b_cw, xcw, nullptr, 128, HW_, 1, CHW_);
        cudaEventRecord(ctx.eCw, ctx.s1);

        // s2: hc branch
        prep_wf_kernel<<<576, 256, 0, ctx.s2>>>(w_hc, wf_hc, 128, 128, 0);
        t2f_kernel<<<dim3(4, 2, 1024), dim3(32, 8), 0, ctx.s2>>>(x, xt2);
        conv3x3_f16<128, 128, 64, 1, 0, 2><<<dim3(32, 2, 8), 256, SM64, ctx.s2>>>(
            xt2, wf_hc, b_hc, xhc, nullptr, 1, 128, HW_, CHW_);
        cudaEventRecord(ctx.eHc, ctx.s2);

        // s3: hw branch + misc preps
        prep_wf_kernel<<<144, 256, 0, ctx.s3>>>(w_hw, wf_hw, 64, 64, 0);
        prep_wd_kernel<<<64, 256, 0, ctx.s3>>>(w_down, wd);
        prep_wf_kernel<<<144, 256, 0, ctx.s3>>>(w_l1, wf_l1, 64, 64, 1);
        prep_wf_kernel<<<144, 256, 0, ctx.s3>>>(w_l2, wf_l2, 64, 64, 0);

        // main: gate path
        prep_w1f_kernel<<<48, 256, 0, m>>>(w_hwc, w1h);
        pairf_kernel<<<4096, 256, 0, m>>>(x, xr);
        cudaEventRecord(ctx.eR4, m);
        cudaStreamWaitEvent(ctx.s3, ctx.eR4, 0);
        conv3x3_f16<64, 128, 128, 0, 0, 2><<<dim3(64, 1, 8), 256, SM128, ctx.s3>>>(
            xr, wf_hw, b_hw, xhw, nullptr, HW_, 128, 1, CHW_);
        cudaEventRecord(ctx.eHw, ctx.s3);

        gemm1x1_f16<<<dim3(64, 3, 8), 256, 0, m>>>(xr, w1h, b_hwc, t);
        dwconv_v3_kernel<<<dim3(8, 192, 8), 256, 0, m>>>(t, w_dw, b_dw, g);

        // join
        cudaStreamWaitEvent(m, ctx.eCw, 0);
        cudaStreamWaitEvent(m, ctx.eHc, 0);
        cudaStreamWaitEvent(m, ctx.eHw, 0);

        down_kernel_v5<<<dim3(32, 4, 8), 128, 0, m>>>(xr, xhw, xcw, xhc, g, x, wd, b_down, mid);
        conv3x3_f16<64, 128, 128, 0, 0, 1><<<dim3(64, 1, 8), 256, SM128, m>>>(
            mid, wf_l1, b_l1, o1, nullptr, HW_, 128, 1, 32 * HW_);
        conv3x3_f16<64, 128, 128, 0, 1, 0><<<dim3(64, 1, 8), 256, SM128, m>>>(
            o1, wf_l2, b_l2, out, x, HW_, 128, 1, CHW_);
    } else {
        // serial fallback
        prep_wd_kernel<<<64, 256>>>(w_down, wd);
        prep_wf_kernel<<<144, 256>>>(w_hw, wf_hw, 64, 64, 0);
        prep_wf_kernel<<<576, 256>>>(w_cw, wf_cw, 128, 128, 0);
        prep_wf_kernel<<<576, 256>>>(w_hc, wf_hc, 128, 128, 0);
        prep_wf_kernel<<<144, 256>>>(w_l1, wf_l1, 64, 64, 1);
        prep_wf_kernel<<<144, 256>>>(w_l2, wf_l2, 64, 64, 0);
        prep_w1f_kernel<<<48, 256>>>(w_hwc, w1h);
        pairf_kernel<<<4096, 256>>>(x, xr);
        t1f_kernel<<<4096, 256>>>(x, xt1);
        t2f_kernel<<<dim3(4, 2, 1024), dim3(32, 8)>>>(x, xt2);
        gemm1x1_f16<<<dim3(64, 3, 8), 256>>>(xr, w1h, b_hwc, t);
        dwconv_v3_kernel<<<dim3(8, 192, 8), 256>>>(t, w_dw, b_dw, g);
        conv3x3_f16<64, 128, 128, 0, 0, 2><<<dim3(64, 1, 8), 256, SM128>>>(
            xr, wf_hw, b_hw, xhw, nullptr, HW_, 128, 1, CHW_);
        conv3x3_f16<128, 64, 128, 0, 0, 2><<<dim3(32, 2, 8), 256, SM128>>>(
            xt1, wf_cw, b_cw, xcw, nullptr, 128, HW_, 1, CHW_);
        conv3x3_f16<128, 128, 64, 1, 0, 2><<<dim3(32, 2, 8), 256, SM64>>>(
            xt2, wf_hc, b_hc, xhc, nullptr, 1, 128, HW_, CHW_);
        down_kernel_v5<<<dim3(32, 4, 8), 128>>>(xr, xhw, xcw, xhc, g, x, wd, b_down, mid);
        conv3x3_f16<64, 128, 128, 0, 0, 1><<<dim3(64, 1, 8), 256, SM128>>>(
            mid, wf_l1, b_l1, o1, nullptr, HW_, 128, 1, 32 * HW_);
        conv3x3_f16<64, 128, 128, 0, 1, 0><<<dim3(64, 1, 8), 256, SM128>>>(
            o1, wf_l2, b_l2, out, x, HW_, 128, 1, CHW_);
    }
}